// round 6
// baseline (speedup 1.0000x reference)
#include <cuda_runtime.h>
#include <cuda_bf16.h>
#include <math.h>
#include <stdint.h>

// ---------------------------------------------------------------------------
// Problem constants
// ---------------------------------------------------------------------------
constexpr int BB = 2;     // batch
constexpr int SS = 1024;  // seq len
constexpr int DD = 1024;  // model dim
constexpr int HH = 16;    // heads
constexpr int LL = 6;     // layers
constexpr int VV = 256;   // vocab
constexpr int HD = 64;    // head dim
constexpr int DF = 512;   // ffn dim
constexpr float ATT_SCALE = 0.125f;  // 1/sqrt(64)

// ---------------------------------------------------------------------------
// Scratch (static device globals -- no allocations allowed)
// ---------------------------------------------------------------------------
__device__ float g_t1 [BB * SS * DD];                 // pre-LN fp32
__device__ float g_h2 [BB * SS * DD];                 // pre-LN fp32
__device__ float g_qe [(size_t)BB * HH * SS * SS];    // 134 MB
__device__ float g_rate[DD];

// split activation buffers
__device__ __nv_bfloat16 g_xh [BB * SS * DD], g_xl [BB * SS * DD];  // layer in
__device__ __nv_bfloat16 g_qh [BB * SS * DD], g_ql [BB * SS * DD];
__device__ __nv_bfloat16 g_kh [BB * SS * DD], g_kl [BB * SS * DD];
__device__ __nv_bfloat16 g_vth[BB * DD * SS], g_vtl[BB * DD * SS];  // v^T per head
__device__ __nv_bfloat16 g_ath[BB * SS * DD], g_atl[BB * SS * DD];  // attn out
__device__ __nv_bfloat16 g_ffh[BB * SS * DF], g_ffl[BB * SS * DF];
__device__ __nv_bfloat16 g_eh [LL * SS * HD], g_el [LL * SS * HD];

// bf16 split weight buffers ([N, K] transposed, hi/lo)
__device__ __nv_bfloat16 g_wq_h[LL * DD * DD], g_wq_l[LL * DD * DD];
__device__ __nv_bfloat16 g_wk_h[LL * DD * DD], g_wk_l[LL * DD * DD];
__device__ __nv_bfloat16 g_wv_h[LL * DD * DD], g_wv_l[LL * DD * DD];
__device__ __nv_bfloat16 g_wo_h[LL * DD * DD], g_wo_l[LL * DD * DD];
__device__ __nv_bfloat16 g_w1_h[LL * DF * DD], g_w1_l[LL * DF * DD];
__device__ __nv_bfloat16 g_w2_h[LL * DD * DF], g_w2_l[LL * DD * DF];
__device__ __nv_bfloat16 g_wf_h[VV * DD],      g_wf_l[VV * DD];

// ---------------------------------------------------------------------------
// PTX helpers (mma.sync / ldmatrix / cp.async -- standard ISA, sm_80+)
// ---------------------------------------------------------------------------
__device__ __forceinline__ uint32_t smem_u32(const void* p) {
    uint32_t a;
    asm("{ .reg .u64 t; cvta.to.shared.u64 t, %1; cvt.u32.u64 %0, t; }"
        : "=r"(a) : "l"(p));
    return a;
}
__device__ __forceinline__ void cpasync16(uint32_t s, const void* g) {
    asm volatile("cp.async.ca.shared.global [%0], [%1], 16;"
                 :: "r"(s), "l"(g) : "memory");
}
__device__ __forceinline__ void ldm_x4(uint32_t a, uint32_t r[4]) {
    asm volatile("ldmatrix.sync.aligned.m8n8.x4.shared.b16 {%0,%1,%2,%3}, [%4];"
                 : "=r"(r[0]), "=r"(r[1]), "=r"(r[2]), "=r"(r[3]) : "r"(a));
}
__device__ __forceinline__ void mma_bf16(float c[4], const uint32_t a[4],
                                         const uint32_t b[2]) {
    asm volatile("mma.sync.aligned.m16n8k16.row.col.f32.bf16.bf16.f32 "
                 "{%0,%1,%2,%3}, {%4,%5,%6,%7}, {%8,%9}, {%0,%1,%2,%3};"
                 : "+f"(c[0]), "+f"(c[1]), "+f"(c[2]), "+f"(c[3])
                 : "r"(a[0]), "r"(a[1]), "r"(a[2]), "r"(a[3]),
                   "r"(b[0]), "r"(b[1]));
}
__device__ __forceinline__ uint32_t pack_bf2(float a, float b) {
    __nv_bfloat162 t = __floats2bfloat162_rn(a, b);
    return *(uint32_t*)&t;
}
__device__ __forceinline__ float bf_hi(float v) {
    return __bfloat162float(__float2bfloat16(v));
}

// ---------------------------------------------------------------------------
// Unified batched split-bf16 HMMA GEMM (unchanged from R4):
//   C[M,N] = (Ahi+Alo)[M,K] @ (Bhi+Blo)[N,K]^T + bias
// ---------------------------------------------------------------------------
template<int BN, int SKIP, bool KCAP, int OUT, bool RELU>
__global__ __launch_bounds__(256)
void gemm_mma(const __nv_bfloat16* __restrict__ Ahi, const __nv_bfloat16* __restrict__ Alo,
              const __nv_bfloat16* __restrict__ Bhi, const __nv_bfloat16* __restrict__ Blo,
              const float* __restrict__ bias, float* __restrict__ C,
              __nv_bfloat16* __restrict__ Ch, __nv_bfloat16* __restrict__ Cl,
              int K, int lda, int ldb, int ldc, int zdiv,
              long long sA1, long long sA2,
              long long sB1, long long sB2,
              long long sC1, long long sC2)
{
    constexpr int ABY = 10240;            // 128 rows * 80B
    constexpr int BBY = BN * 80;
    constexpr int STG = 2 * ABY + 2 * BBY;
    constexpr int NT  = BN / 16;
    constexpr int BN2 = BN / 2;

    const int m0 = blockIdx.y * 128;
    const int n0 = blockIdx.x * BN;
    if (SKIP == 1 && (m0 + n0 + 127 + BN - 1 < SS - 1)) return;
    if (SKIP == 2 && (n0 >= m0 + 128)) return;

    extern __shared__ char dynsmem[];
    const uint32_t sbase = smem_u32(dynsmem);
    const int tid  = threadIdx.x;
    const int lane = tid & 31;
    const int warp = tid >> 5;
    const int wm = warp & 3;
    const int wn = warp >> 2;

    const int z  = blockIdx.z;
    const int zb = z / zdiv;
    const int zh = z % zdiv;
    Ahi += (size_t)zb * sA1 + (size_t)zh * sA2;
    Alo += (size_t)zb * sA1 + (size_t)zh * sA2;
    Bhi += (size_t)zb * sB1 + (size_t)zh * sB2;
    Blo += (size_t)zb * sB1 + (size_t)zh * sB2;
    if (OUT == 0) C  += (size_t)zb * sC1 + (size_t)zh * sC2;
    else { Ch += (size_t)zb * sC1 + (size_t)zh * sC2;
           Cl += (size_t)zb * sC1 + (size_t)zh * sC2; }

    float acc[2][NT][4];
#pragma unroll
    for (int mt = 0; mt < 2; ++mt)
#pragma unroll
        for (int nt = 0; nt < NT; ++nt)
#pragma unroll
            for (int r = 0; r < 4; ++r) acc[mt][nt][r] = 0.f;

    const int Keff = KCAP ? min(K, m0 + 128) : K;
    const int nch  = Keff >> 5;

    auto load_stage = [&](int c) {
        const int k0c = c << 5;
        const uint32_t sb = sbase + (c & 1) * STG;
#pragma unroll
        for (int i = 0; i < 2; ++i) {
            const int u = tid + i * 256;
            const int row = u >> 2, seg = u & 3;
            const uint32_t so = sb + row * 80 + seg * 16;
            const size_t ga = (size_t)(m0 + row) * lda + k0c + seg * 8;
            cpasync16(so,       Ahi + ga);
            cpasync16(so + ABY, Alo + ga);
        }
        constexpr int BU = (BN * 4) / 256;
#pragma unroll
        for (int i = 0; i < BU; ++i) {
            const int u = tid + i * 256;
            const int row = u >> 2, seg = u & 3;
            const uint32_t so = sb + 2 * ABY + row * 80 + seg * 16;
            const size_t gb = (size_t)(n0 + row) * ldb + k0c + seg * 8;
            cpasync16(so,       Bhi + gb);
            cpasync16(so + BBY, Blo + gb);
        }
        asm volatile("cp.async.commit_group;" ::: "memory");
    };

    load_stage(0);

    const int lr  = lane & 7;
    const int sel = lane >> 3;
    const int a_row_off = lr + ((sel & 1) << 3);
    const int a_k_off   = (sel >> 1) << 3;
    const int b_n_off   = lr + ((sel >> 1) << 3);
    const int b_k_off   = (sel & 1) << 3;

    for (int c = 0; c < nch; ++c) {
        if (c + 1 < nch) {
            load_stage(c + 1);
            asm volatile("cp.async.wait_group 1;" ::: "memory");
        } else {
            asm volatile("cp.async.wait_group 0;" ::: "memory");
        }
        __syncthreads();
        const uint32_t sb = sbase + (c & 1) * STG;

#pragma unroll
        for (int ks = 0; ks < 2; ++ks) {
            const int kk = ks << 4;
            uint32_t ah[2][4], al[2][4], bb[NT][2];
#pragma unroll
            for (int mt = 0; mt < 2; ++mt) {
                const int row = wm * 32 + mt * 16 + a_row_off;
                const uint32_t ad = sb + row * 80 + (kk + a_k_off) * 2;
                ldm_x4(ad, ah[mt]);
                ldm_x4(ad + ABY, al[mt]);
            }
#pragma unroll
            for (int p = 0; p < NT / 2; ++p) {
                const int n = wn * BN2 + p * 16 + b_n_off;
                uint32_t r[4];
                ldm_x4(sb + 2 * ABY + n * 80 + (kk + b_k_off) * 2, r);
                bb[2 * p][0]     = r[0]; bb[2 * p][1]     = r[1];
                bb[2 * p + 1][0] = r[2]; bb[2 * p + 1][1] = r[3];
            }
#pragma unroll
            for (int mt = 0; mt < 2; ++mt)
#pragma unroll
                for (int nt = 0; nt < NT; ++nt)
                    mma_bf16(acc[mt][nt], ah[mt], bb[nt]);
#pragma unroll
            for (int mt = 0; mt < 2; ++mt)
#pragma unroll
                for (int nt = 0; nt < NT; ++nt)
                    mma_bf16(acc[mt][nt], al[mt], bb[nt]);
#pragma unroll
            for (int p = 0; p < NT / 2; ++p) {
                const int n = wn * BN2 + p * 16 + b_n_off;
                uint32_t r[4];
                ldm_x4(sb + 2 * ABY + BBY + n * 80 + (kk + b_k_off) * 2, r);
                bb[2 * p][0]     = r[0]; bb[2 * p][1]     = r[1];
                bb[2 * p + 1][0] = r[2]; bb[2 * p + 1][1] = r[3];
            }
#pragma unroll
            for (int mt = 0; mt < 2; ++mt)
#pragma unroll
                for (int nt = 0; nt < NT; ++nt)
                    mma_bf16(acc[mt][nt], ah[mt], bb[nt]);
        }
        __syncthreads();
    }

    const int rbase = m0 + wm * 32 + (lane >> 2);
    const int cbase = n0 + wn * BN2 + 2 * (lane & 3);
#pragma unroll
    for (int mt = 0; mt < 2; ++mt) {
#pragma unroll
        for (int nt = 0; nt < NT; ++nt) {
            const int col = cbase + nt * 8;
            float b0v = 0.f, b1v = 0.f;
            if (bias) { b0v = bias[col]; b1v = bias[col + 1]; }
            float v0 = acc[mt][nt][0] + b0v;
            float v1 = acc[mt][nt][1] + b1v;
            float v2 = acc[mt][nt][2] + b0v;
            float v3 = acc[mt][nt][3] + b1v;
            if (RELU) {
                v0 = fmaxf(v0, 0.f); v1 = fmaxf(v1, 0.f);
                v2 = fmaxf(v2, 0.f); v3 = fmaxf(v3, 0.f);
            }
            const int r0 = rbase + mt * 16;
            if (OUT == 0) {
                *(float2*)&C[(size_t)r0 * ldc + col]       = make_float2(v0, v1);
                *(float2*)&C[(size_t)(r0 + 8) * ldc + col] = make_float2(v2, v3);
            } else if (OUT == 1) {
                const float h0 = bf_hi(v0), h1 = bf_hi(v1);
                const float h2 = bf_hi(v2), h3 = bf_hi(v3);
                *(uint32_t*)&Ch[(size_t)r0 * ldc + col]       = pack_bf2(h0, h1);
                *(uint32_t*)&Ch[(size_t)(r0 + 8) * ldc + col] = pack_bf2(h2, h3);
                *(uint32_t*)&Cl[(size_t)r0 * ldc + col]       = pack_bf2(v0 - h0, v1 - h1);
                *(uint32_t*)&Cl[(size_t)(r0 + 8) * ldc + col] = pack_bf2(v2 - h2, v3 - h3);
            } else {
                const float vv[4] = {v0, v1, v2, v3};
#pragma unroll
                for (int e = 0; e < 4; ++e) {
                    const int cc = col + (e & 1);
                    const int rr = r0 + (e >> 1) * 8;
                    const __nv_bfloat16 hb = __float2bfloat16(vv[e]);
                    Ch[(size_t)cc * ldc + rr] = hb;
                    Cl[(size_t)cc * ldc + rr] =
                        __float2bfloat16(vv[e] - __bfloat162float(hb));
                }
            }
        }
    }
}

// ---------------------------------------------------------------------------
// Fused flash attention: per (b,h, 128-row q block):
//   loop over causal k blocks: S = split-QK^T HMMA + qe gather + masks,
//   online softmax (per-warp rows), P@V split HMMA -> O, normalize, split out.
// SMEM: Q(hi/lo) + double-buffered {K(hi/lo), V^T(hi/lo), tokens}.
// ---------------------------------------------------------------------------
constexpr int QP = 144;   // Q/K row pitch bytes (64 bf16 + pad)
constexpr int VP = 272;   // V^T row pitch bytes (128 bf16 + pad)
constexpr int FA_QBY  = 128 * QP;              // 18432 per array
constexpr int FA_KBY  = 128 * QP;              // 18432 per array
constexpr int FA_VBY  = 64 * VP;               // 17408 per array
constexpr int FA_STG  = 2 * FA_KBY + 2 * FA_VBY;   // 71680
constexpr int FA_TOK  = 2 * FA_QBY + 2 * FA_STG;   // 180224
constexpr int FA_SMEM = FA_TOK + 2 * 512;          // 181248

__global__ __launch_bounds__(256)
void flash_attn(const __nv_bfloat16* __restrict__ qh, const __nv_bfloat16* __restrict__ ql,
                const __nv_bfloat16* __restrict__ kh, const __nv_bfloat16* __restrict__ kl,
                const __nv_bfloat16* __restrict__ vth, const __nv_bfloat16* __restrict__ vtl,
                const float* __restrict__ qe, const int* __restrict__ x,
                __nv_bfloat16* __restrict__ oh, __nv_bfloat16* __restrict__ ol)
{
    extern __shared__ char dynsmem[];
    const uint32_t sbase = smem_u32(dynsmem);
    const int tid  = threadIdx.x;
    const int lane = tid & 31;
    const int warp = tid >> 5;
    const int ib = (gridDim.x - 1) - blockIdx.x;   // heavy blocks first
    const int I0 = ib * 128;
    const int bh = blockIdx.y;
    const int b  = bh >> 4;
    const int h  = bh & 15;

    const __nv_bfloat16* qgh = qh + ((size_t)(b * SS + I0)) * DD + h * 64;
    const __nv_bfloat16* qgl = ql + ((size_t)(b * SS + I0)) * DD + h * 64;
    const __nv_bfloat16* kgh = kh + ((size_t)(b * SS)) * DD + h * 64;
    const __nv_bfloat16* kgl = kl + ((size_t)(b * SS)) * DD + h * 64;
    const __nv_bfloat16* vgh = vth + ((size_t)b * DD + h * 64) * SS;
    const __nv_bfloat16* vgl = vtl + ((size_t)b * DD + h * 64) * SS;
    const int* xb = x + b * SS;

    // ---- load Q (group 0) ----
#pragma unroll
    for (int i = 0; i < 4; ++i) {
        const int u = tid + i * 256;          // 1024 units: 128 rows x 8 segs
        const int row = u >> 3, seg = u & 7;
        const uint32_t so = sbase + row * QP + seg * 16;
        const size_t ga = (size_t)row * DD + seg * 8;
        cpasync16(so, qgh + ga);
        cpasync16(so + FA_QBY, qgl + ga);
    }
    asm volatile("cp.async.commit_group;" ::: "memory");

    auto load_stage = [&](int jb) {
        const int J0 = jb * 128;
        const uint32_t sb = sbase + 2 * FA_QBY + (jb & 1) * FA_STG;
#pragma unroll
        for (int i = 0; i < 4; ++i) {         // K: 128 rows x 8 segs
            const int u = tid + i * 256;
            const int row = u >> 3, seg = u & 7;
            const uint32_t so = sb + row * QP + seg * 16;
            const size_t ga = (size_t)(J0 + row) * DD + seg * 8;
            cpasync16(so,          kgh + ga);
            cpasync16(so + FA_KBY, kgl + ga);
        }
#pragma unroll
        for (int i = 0; i < 4; ++i) {         // V^T: 64 rows x 16 segs
            const int u = tid + i * 256;
            const int row = u >> 4, seg = u & 15;
            const uint32_t so = sb + 2 * FA_KBY + row * VP + seg * 16;
            const size_t ga = (size_t)row * SS + J0 + seg * 8;
            cpasync16(so,          vgh + ga);
            cpasync16(so + FA_VBY, vgl + ga);
        }
        if (tid < 32)
            cpasync16(sbase + FA_TOK + (jb & 1) * 512 + tid * 16, xb + J0 + tid * 4);
        asm volatile("cp.async.commit_group;" ::: "memory");
    };

    load_stage(0);

    const int lr  = lane & 7;
    const int sel = lane >> 3;
    const int a_row_off = lr + ((sel & 1) << 3);
    const int a_k_off   = (sel >> 1) << 3;
    const int b_n_off   = lr + ((sel >> 1) << 3);
    const int b_k_off   = (sel & 1) << 3;

    const int rl = lane >> 2;
    const int cl = 2 * (lane & 3);
    const int i0 = I0 + warp * 16 + rl;
    const int i1 = i0 + 8;
    const float* qer0 = qe + ((size_t)bh * SS + i0) * SS + (SS - 1 - i0);
    const float* qer1 = qe + ((size_t)bh * SS + i1) * SS + (SS - 1 - i1);

    float m0v = -1e30f, m1v = -1e30f, l0v = 0.f, l1v = 0.f;
    float accO[8][4];
#pragma unroll
    for (int nt = 0; nt < 8; ++nt)
#pragma unroll
        for (int r = 0; r < 4; ++r) accO[nt][r] = 0.f;

    for (int jb = 0; jb <= ib; ++jb) {
        if (jb < ib) {
            load_stage(jb + 1);
            asm volatile("cp.async.wait_group 1;" ::: "memory");
        } else {
            asm volatile("cp.async.wait_group 0;" ::: "memory");
        }
        __syncthreads();
        const uint32_t sb  = sbase + 2 * FA_QBY + (jb & 1) * FA_STG;
        const uint32_t vsb = sb + 2 * FA_KBY;
        const int* tok = (const int*)(dynsmem + FA_TOK + (jb & 1) * 512);
        const int J0 = jb * 128;

        // ---- S = Q @ K^T (3-product split) ----
        float sa[16][4];
#pragma unroll
        for (int nt = 0; nt < 16; ++nt)
#pragma unroll
            for (int r = 0; r < 4; ++r) sa[nt][r] = 0.f;

#pragma unroll
        for (int kk4 = 0; kk4 < 4; ++kk4) {
            const int kkb = kk4 << 4;
            uint32_t aH[4], aL[4], bbf[16][2];
            const uint32_t ad = sbase + (warp * 16 + a_row_off) * QP + (kkb + a_k_off) * 2;
            ldm_x4(ad, aH);
            ldm_x4(ad + FA_QBY, aL);
#pragma unroll
            for (int p = 0; p < 8; ++p) {
                uint32_t r[4];
                ldm_x4(sb + (p * 16 + b_n_off) * QP + (kkb + b_k_off) * 2, r);
                bbf[2 * p][0]     = r[0]; bbf[2 * p][1]     = r[1];
                bbf[2 * p + 1][0] = r[2]; bbf[2 * p + 1][1] = r[3];
            }
#pragma unroll
            for (int nt = 0; nt < 16; ++nt) mma_bf16(sa[nt], aH, bbf[nt]);
#pragma unroll
            for (int nt = 0; nt < 16; ++nt) mma_bf16(sa[nt], aL, bbf[nt]);
#pragma unroll
            for (int p = 0; p < 8; ++p) {
                uint32_t r[4];
                ldm_x4(sb + FA_KBY + (p * 16 + b_n_off) * QP + (kkb + b_k_off) * 2, r);
                bbf[2 * p][0]     = r[0]; bbf[2 * p][1]     = r[1];
                bbf[2 * p + 1][0] = r[2]; bbf[2 * p + 1][1] = r[3];
            }
#pragma unroll
            for (int nt = 0; nt < 16; ++nt) mma_bf16(sa[nt], aH, bbf[nt]);
        }

        // ---- Srel gather + scale + masks ----
        float rm0 = -1e30f, rm1 = -1e30f;
#pragma unroll
        for (int nt = 0; nt < 16; ++nt) {
            const int jj = nt * 8 + cl;
#pragma unroll
            for (int e = 0; e < 2; ++e) {
                const int j = J0 + jj + e;
                const float pen = (tok[jj + e] == 0) ? -1e9f : 0.f;
                float v0 = sa[nt][e];
                v0 = (j <= i0) ? ((v0 + qer0[j]) * ATT_SCALE + pen) : -1e30f;
                sa[nt][e] = v0;
                rm0 = fmaxf(rm0, v0);
                float v1 = sa[nt][2 + e];
                v1 = (j <= i1) ? ((v1 + qer1[j]) * ATT_SCALE + pen) : -1e30f;
                sa[nt][2 + e] = v1;
                rm1 = fmaxf(rm1, v1);
            }
        }
        rm0 = fmaxf(rm0, __shfl_xor_sync(0xffffffffu, rm0, 1));
        rm0 = fmaxf(rm0, __shfl_xor_sync(0xffffffffu, rm0, 2));
        rm1 = fmaxf(rm1, __shfl_xor_sync(0xffffffffu, rm1, 1));
        rm1 = fmaxf(rm1, __shfl_xor_sync(0xffffffffu, rm1, 2));

        const float mn0 = fmaxf(m0v, rm0);
        const float mn1 = fmaxf(m1v, rm1);
        const float al0 = __expf(m0v - mn0);
        const float al1 = __expf(m1v - mn1);
        m0v = mn0; m1v = mn1;

        float rs0 = 0.f, rs1 = 0.f;
#pragma unroll
        for (int nt = 0; nt < 16; ++nt) {
            float p0 = __expf(sa[nt][0] - mn0);
            float p1 = __expf(sa[nt][1] - mn0);
            float p2 = __expf(sa[nt][2] - mn1);
            float p3 = __expf(sa[nt][3] - mn1);
            sa[nt][0] = p0; sa[nt][1] = p1; sa[nt][2] = p2; sa[nt][3] = p3;
            rs0 += p0 + p1; rs1 += p2 + p3;
        }
        rs0 += __shfl_xor_sync(0xffffffffu, rs0, 1);
        rs0 += __shfl_xor_sync(0xffffffffu, rs0, 2);
        rs1 += __shfl_xor_sync(0xffffffffu, rs1, 1);
        rs1 += __shfl_xor_sync(0xffffffffu, rs1, 2);
        l0v = l0v * al0 + rs0;
        l1v = l1v * al1 + rs1;

#pragma unroll
        for (int nt = 0; nt < 8; ++nt) {
            accO[nt][0] *= al0; accO[nt][1] *= al0;
            accO[nt][2] *= al1; accO[nt][3] *= al1;
        }

        // ---- O += P @ V (3-product split; P packed in registers) ----
#pragma unroll
        for (int kt = 0; kt < 8; ++kt) {
            uint32_t aH[4], aL[4], bbf[8][2];
            {
                const float* s0 = sa[2 * kt];
                const float* s1 = sa[2 * kt + 1];
                const float h00 = bf_hi(s0[0]), h01 = bf_hi(s0[1]);
                const float h02 = bf_hi(s0[2]), h03 = bf_hi(s0[3]);
                const float h10 = bf_hi(s1[0]), h11 = bf_hi(s1[1]);
                const float h12 = bf_hi(s1[2]), h13 = bf_hi(s1[3]);
                aH[0] = pack_bf2(h00, h01);           aH[1] = pack_bf2(h02, h03);
                aH[2] = pack_bf2(h10, h11);           aH[3] = pack_bf2(h12, h13);
                aL[0] = pack_bf2(s0[0] - h00, s0[1] - h01);
                aL[1] = pack_bf2(s0[2] - h02, s0[3] - h03);
                aL[2] = pack_bf2(s1[0] - h10, s1[1] - h11);
                aL[3] = pack_bf2(s1[2] - h12, s1[3] - h13);
            }
#pragma unroll
            for (int np = 0; np < 4; ++np) {
                uint32_t r[4];
                ldm_x4(vsb + (np * 16 + b_n_off) * VP + (kt * 16 + b_k_off) * 2, r);
                bbf[2 * np][0]     = r[0]; bbf[2 * np][1]     = r[1];
                bbf[2 * np + 1][0] = r[2]; bbf[2 * np + 1][1] = r[3];
            }
#pragma unroll
            for (int nt = 0; nt < 8; ++nt) mma_bf16(accO[nt], aH, bbf[nt]);
#pragma unroll
            for (int nt = 0; nt < 8; ++nt) mma_bf16(accO[nt], aL, bbf[nt]);
#pragma unroll
            for (int np = 0; np < 4; ++np) {
                uint32_t r[4];
                ldm_x4(vsb + FA_VBY + (np * 16 + b_n_off) * VP + (kt * 16 + b_k_off) * 2, r);
                bbf[2 * np][0]     = r[0]; bbf[2 * np][1]     = r[1];
                bbf[2 * np + 1][0] = r[2]; bbf[2 * np + 1][1] = r[3];
            }
#pragma unroll
            for (int nt = 0; nt < 8; ++nt) mma_bf16(accO[nt], aH, bbf[nt]);
        }
        __syncthreads();
    }

    // ---- normalize + split store ----
    const float inv0 = 1.f / l0v;
    const float inv1 = 1.f / l1v;
    __nv_bfloat16* oh0 = oh + ((size_t)(b * SS + i0)) * DD + h * 64;
    __nv_bfloat16* ol0 = ol + ((size_t)(b * SS + i0)) * DD + h * 64;
    __nv_bfloat16* oh1 = oh + ((size_t)(b * SS + i1)) * DD + h * 64;
    __nv_bfloat16* ol1 = ol + ((size_t)(b * SS + i1)) * DD + h * 64;
#pragma unroll
    for (int nt = 0; nt < 8; ++nt) {
        const int d = nt * 8 + cl;
        const float v0 = accO[nt][0] * inv0, v1 = accO[nt][1] * inv0;
        const float v2 = accO[nt][2] * inv1, v3 = accO[nt][3] * inv1;
        const float h0 = bf_hi(v0), h1 = bf_hi(v1);
        const float h2 = bf_hi(v2), h3 = bf_hi(v3);
        *(uint32_t*)&oh0[d] = pack_bf2(h0, h1);
        *(uint32_t*)&ol0[d] = pack_bf2(v0 - h0, v1 - h1);
        *(uint32_t*)&oh1[d] = pack_bf2(h2, h3);
        *(uint32_t*)&ol1[d] = pack_bf2(v2 - h2, v3 - h3);
    }
}

// ---------------------------------------------------------------------------
// Weight transpose + bf16 hi/lo split: W[l][K][N] -> hi/lo [l][N][K]
// ---------------------------------------------------------------------------
__global__ void conv_w(const float* __restrict__ W, __nv_bfloat16* __restrict__ hi,
                       __nv_bfloat16* __restrict__ lo, int K, int N)
{
    __shared__ float t[32][33];
    const int l = blockIdx.z;
    W  += (size_t)l * K * N;
    hi += (size_t)l * K * N;
    lo += (size_t)l * K * N;
    const int k0 = blockIdx.y * 32, n0 = blockIdx.x * 32;
    const int tx = threadIdx.x, ty = threadIdx.y;
#pragma unroll
    for (int i = ty; i < 32; i += 8)
        t[i][tx] = W[(size_t)(k0 + i) * N + n0 + tx];
    __syncthreads();
#pragma unroll
    for (int i = ty; i < 32; i += 8) {
        const float v = t[tx][i];
        const __nv_bfloat16 h = __float2bfloat16(v);
        const __nv_bfloat16 r = __float2bfloat16(v - __bfloat162float(h));
        hi[(size_t)(n0 + i) * K + k0 + tx] = h;
        lo[(size_t)(n0 + i) * K + k0 + tx] = r;
    }
}

__global__ void split_act(const float* __restrict__ x, __nv_bfloat16* __restrict__ hi,
                          __nv_bfloat16* __restrict__ lo, int n4)
{
    const int i = blockIdx.x * 256 + threadIdx.x;
    if (i >= n4) return;
    const float4 v = ((const float4*)x)[i];
    const float f[4] = {v.x, v.y, v.z, v.w};
    unsigned short hh[4], ll[4];
#pragma unroll
    for (int j = 0; j < 4; j++) {
        const __nv_bfloat16 hb = __float2bfloat16(f[j]);
        const __nv_bfloat16 lb = __float2bfloat16(f[j] - __bfloat162float(hb));
        hh[j] = __bfloat16_as_ushort(hb);
        ll[j] = __bfloat16_as_ushort(lb);
    }
    ((uint2*)hi)[i] = *(const uint2*)hh;
    ((uint2*)lo)[i] = *(const uint2*)ll;
}

__global__ void rate_kernel(float* __restrict__ rate)
{
    const int d = blockIdx.x * 256 + threadIdx.x;
    if (d >= DD) return;
    const double LN1E4 = 9.210340371976184;
    const int par = d & 1;
    const float r1 = (float)exp(-LN1E4 * (double)d   / 1024.0);
    const float r2 = (float)exp( LN1E4 * (double)par / 1024.0);
    rate[d] = r1 * r2;
}

__global__ void embed_split(const int* __restrict__ x,
                            const float* __restrict__ emb,
                            const float* __restrict__ rate,
                            __nv_bfloat16* __restrict__ oh,
                            __nv_bfloat16* __restrict__ ol)
{
    const int bs = blockIdx.x;
    const int s  = bs & (SS - 1);
    const int tok = x[bs];
    const float* e = emb + (size_t)tok * DD;
    for (int d = threadIdx.x; d < DD; d += blockDim.x) {
        const int par = d & 1;
        const float ph = (float)s * rate[d] + 1.5707964f * (float)par;
        const float v = e[d] * 32.0f + sinf(ph);
        const __nv_bfloat16 hb = __float2bfloat16(v);
        oh[(size_t)bs * DD + d] = hb;
        ol[(size_t)bs * DD + d] = __float2bfloat16(v - __bfloat162float(hb));
    }
}

__global__ __launch_bounds__(256)
void ln_split(const float* __restrict__ xin, const float* __restrict__ g,
              const float* __restrict__ be,
              __nv_bfloat16* __restrict__ oh, __nv_bfloat16* __restrict__ ol)
{
    const int row = blockIdx.x;
    const float* p = xin + (size_t)row * DD;
    const int t = threadIdx.x;
    float v[4];
    float s = 0.f, s2 = 0.f;
#pragma unroll
    for (int c = 0; c < 4; c++) {
        v[c] = p[t + c * 256];
        s += v[c];
        s2 += v[c] * v[c];
    }
    __shared__ float sh1[8], sh2[8];
#pragma unroll
    for (int o = 16; o > 0; o >>= 1) {
        s  += __shfl_xor_sync(0xffffffffu, s,  o);
        s2 += __shfl_xor_sync(0xffffffffu, s2, o);
    }
    if ((t & 31) == 0) { sh1[t >> 5] = s; sh2[t >> 5] = s2; }
    __syncthreads();
    s = 0.f; s2 = 0.f;
#pragma unroll
    for (int w = 0; w < 8; w++) { s += sh1[w]; s2 += sh2[w]; }
    const float mu  = s  * (1.f / DD);
    const float var = s2 * (1.f / DD) - mu * mu;
    const float inv = rsqrtf(var + 1e-6f);
#pragma unroll
    for (int c = 0; c < 4; c++) {
        const int d = t + c * 256;
        const float o = (v[c] - mu) * inv * g[d] + be[d];
        const __nv_bfloat16 hb = __float2bfloat16(o);
        oh[(size_t)row * DD + d] = hb;
        ol[(size_t)row * DD + d] = __float2bfloat16(o - __bfloat162float(hb));
    }
}

// ---------------------------------------------------------------------------
// Host side
// ---------------------------------------------------------------------------
using bf16 = __nv_bfloat16;

template<int BN, int SKIP, bool KCAP, int OUT, bool RELU>
static void run_mma(const bf16* ah, const bf16* al, const bf16* bh, const bf16* bl,
                    const float* bias, float* C, bf16* Ch, bf16* Cl,
                    int M, int N, int K, int lda, int ldb, int ldc,
                    int batch, int zdiv,
                    long long sA1, long long sA2,
                    long long sB1, long long sB2,
                    long long sC1, long long sC2)
{
    constexpr int STG = 2 * 10240 + 2 * BN * 80;
    static bool init = false;
    if (!init) {
        cudaFuncSetAttribute(gemm_mma<BN, SKIP, KCAP, OUT, RELU>,
                             cudaFuncAttributeMaxDynamicSharedMemorySize, 2 * STG);
        init = true;
    }
    dim3 grid(N / BN, M / 128, batch);
    gemm_mma<BN, SKIP, KCAP, OUT, RELU><<<grid, 256, 2 * STG>>>(
        ah, al, bh, bl, bias, C, Ch, Cl, K, lda, ldb, ldc,
        zdiv, sA1, sA2, sB1, sB2, sC1, sC2);
}

extern "C" void kernel_launch(void* const* d_in, const int* in_sizes, int n_in,
                              void* d_out, int out_size)
{
    const int*   x   = (const int*)  d_in[0];
    const float* emb = (const float*)d_in[1];
    const float* Wq  = (const float*)d_in[2];
    const float* bq  = (const float*)d_in[3];
    const float* Wk  = (const float*)d_in[4];
    const float* bk  = (const float*)d_in[5];
    const float* Wv  = (const float*)d_in[6];
    const float* bv  = (const float*)d_in[7];
    const float* Wo  = (const float*)d_in[8];
    const float* bo  = (const float*)d_in[9];
    const float* W1  = (const float*)d_in[10];
    const float* b1  = (const float*)d_in[11];
    const float* W2  = (const float*)d_in[12];
    const float* b2  = (const float*)d_in[13];
    const float* g1  = (const float*)d_in[14];
    const float* be1 = (const float*)d_in[15];
    const float* g2  = (const float*)d_in[16];
    const float* be2 = (const float*)d_in[17];
    const float* E   = (const float*)d_in[18];
    const float* Wf  = (const float*)d_in[19];
    const float* bf  = (const float*)d_in[20];
    float* out = (float*)d_out;

    cudaFuncSetAttribute(flash_attn, cudaFuncAttributeMaxDynamicSharedMemorySize,
                         FA_SMEM);

    float *t1, *h2, *qe, *rate;
    cudaGetSymbolAddress((void**)&t1, g_t1);
    cudaGetSymbolAddress((void**)&h2, g_h2);
    cudaGetSymbolAddress((void**)&qe, g_qe);
    cudaGetSymbolAddress((void**)&rate, g_rate);

    bf16 *xh, *xl, *qh, *ql, *kh, *kl, *vth, *vtl, *ath, *atl, *ffh, *ffl, *eh, *el;
    cudaGetSymbolAddress((void**)&xh,  g_xh);  cudaGetSymbolAddress((void**)&xl,  g_xl);
    cudaGetSymbolAddress((void**)&qh,  g_qh);  cudaGetSymbolAddress((void**)&ql,  g_ql);
    cudaGetSymbolAddress((void**)&kh,  g_kh);  cudaGetSymbolAddress((void**)&kl,  g_kl);
    cudaGetSymbolAddress((void**)&vth, g_vth); cudaGetSymbolAddress((void**)&vtl, g_vtl);
    cudaGetSymbolAddress((void**)&ath, g_ath); cudaGetSymbolAddress((void**)&atl, g_atl);
    cudaGetSymbolAddress((void**)&ffh, g_ffh); cudaGetSymbolAddress((void**)&ffl, g_ffl);
    cudaGetSymbolAddress((void**)&eh,  g_eh);  cudaGetSymbolAddress((void**)&el,  g_el);

    bf16 *wqh, *wql, *wkh, *wkl, *wvh, *wvl, *woh, *wol;
    bf16 *w1h, *w1l, *w2h, *w2l, *wfh, *wfl;
    cudaGetSymbolAddress((void**)&wqh, g_wq_h); cudaGetSymbolAddress((void**)&wql, g_wq_l);
    cudaGetSymbolAddress((void**)&wkh, g_wk_h); cudaGetSymbolAddress((void**)&wkl, g_wk_l);
    cudaGetSymbolAddress((void**)&wvh, g_wv_h); cudaGetSymbolAddress((void**)&wvl, g_wv_l);
    cudaGetSymbolAddress((void**)&woh, g_wo_h); cudaGetSymbolAddress((void**)&wol, g_wo_l);
    cudaGetSymbolAddress((void**)&w1h, g_w1_h); cudaGetSymbolAddress((void**)&w1l, g_w1_l);
    cudaGetSymbolAddress((void**)&w2h, g_w2_h); cudaGetSymbolAddress((void**)&w2l, g_w2_l);
    cudaGetSymbolAddress((void**)&wfh, g_wf_h); cudaGetSymbolAddress((void**)&wfl, g_wf_l);

    const int M = BB * SS;  // 2048
    const long long sSD  = (long long)SS * DD;
    const long long sHSS = (long long)HH * SS * SS;
    const long long sSSq = (long long)SS * SS;
    const long long sDS  = (long long)DD * SS;

    // weight + E conversion
    {
        dim3 tb(32, 8);
        conv_w<<<dim3(DD / 32, DD / 32, LL), tb>>>(Wq, wqh, wql, DD, DD);
        conv_w<<<dim3(DD / 32, DD / 32, LL), tb>>>(Wk, wkh, wkl, DD, DD);
        conv_w<<<dim3(DD / 32, DD / 32, LL), tb>>>(Wv, wvh, wvl, DD, DD);
        conv_w<<<dim3(DD / 32, DD / 32, LL), tb>>>(Wo, woh, wol, DD, DD);
        conv_w<<<dim3(DF / 32, DD / 32, LL), tb>>>(W1, w1h, w1l, DD, DF);
        conv_w<<<dim3(DD / 32, DF / 32, LL), tb>>>(W2, w2h, w2l, DF, DD);
        conv_w<<<dim3(VV / 32, DD / 32, 1),  tb>>>(Wf, wfh, wfl, DD, VV);
        split_act<<<(LL * SS * HD / 4 + 255) / 256, 256>>>(E, eh, el, LL * SS * HD / 4);
    }

    rate_kernel<<<4, 256>>>(rate);
    embed_split<<<BB * SS, 256>>>(x, emb, rate, xh, xl);

    for (int l = 0; l < LL; l++) {
        const size_t wdd = (size_t)l * DD * DD;
        const size_t wdf = (size_t)l * DF * DD;
        const bf16* ehl = eh + (size_t)l * SS * HD;
        const bf16* ell = el + (size_t)l * SS * HD;

        // QKV projections; q,k split; v split-transposed per batch
        run_mma<128, 0, false, 1, false>(xh, xl, wqh + wdd, wql + wdd, bq + l * DD,
                                         nullptr, qh, ql, M, DD, DD, DD, DD, DD,
                                         1, 1, 0, 0, 0, 0, 0, 0);
        run_mma<128, 0, false, 1, false>(xh, xl, wkh + wdd, wkl + wdd, bk + l * DD,
                                         nullptr, kh, kl, M, DD, DD, DD, DD, DD,
                                         1, 1, 0, 0, 0, 0, 0, 0);
        run_mma<128, 0, false, 2, false>(xh, xl, wvh + wdd, wvl + wdd, bv + l * DD,
                                         nullptr, vth, vtl, SS, DD, DD, DD, DD, SS,
                                         BB, 1, sSD, 0, 0, 0, sDS, 0);

        // QE = q @ E^T (anti-diagonal tiles only)
        run_mma<128, 1, false, 0, false>(qh, ql, ehl, ell, nullptr, qe, nullptr, nullptr,
                                         SS, SS, HD, DD, HD, SS, BB * HH, HH,
                                         sSD, HD, 0, 0, sHSS, sSSq);

        // fused flash attention: QK + Srel + masks + softmax + PV
        flash_attn<<<dim3(SS / 128, BB * HH), 256, FA_SMEM>>>(
            qh, ql, kh, kl, vth, vtl, qe, x, ath, atl);

        // Wo + LN1
        run_mma<128, 0, false, 0, false>(ath, atl, woh + wdd, wol + wdd, bo + l * DD,
                                         t1, nullptr, nullptr, M, DD, DD, DD, DD, DD,
                                         1, 1, 0, 0, 0, 0, 0, 0);
        ln_split<<<BB * SS, 256>>>(t1, g1 + l * DD, be1 + l * DD, xh, xl);

        // FFN
        run_mma<128, 0, false, 1, true>(xh, xl, w1h + wdf, w1l + wdf, b1 + l * DF,
                                        nullptr, ffh, ffl, M, DF, DD, DD, DD, DF,
                                        1, 1, 0, 0, 0, 0, 0, 0);
        run_mma<128, 0, false, 0, false>(ffh, ffl, w2h + wdf, w2l + wdf, b2 + l * DD,
                                         h2, nullptr, nullptr, M, DD, DF, DF, DF, DD,
                                         1, 1, 0, 0, 0, 0, 0, 0);
        ln_split<<<BB * SS, 256>>>(h2, g2 + l * DD, be2 + l * DD, xh, xl);
    }

    // final projection to vocab
    run_mma<128, 0, false, 0, false>(xh, xl, wfh, wfl, bf, out, nullptr, nullptr,
                                     M, VV, DD, DD, DD, VV, 1, 1, 0, 0, 0, 0, 0, 0);
}

// round 7
// speedup vs baseline: 1.5416x; 1.5416x over previous
#include <cuda_runtime.h>
#include <cuda_bf16.h>
#include <math.h>
#include <stdint.h>

// ---------------------------------------------------------------------------
// Problem constants
// ---------------------------------------------------------------------------
constexpr int BB = 2;     // batch
constexpr int SS = 1024;  // seq len
constexpr int DD = 1024;  // model dim
constexpr int HH = 16;    // heads
constexpr int LL = 6;     // layers
constexpr int VV = 256;   // vocab
constexpr int HD = 64;    // head dim
constexpr int DF = 512;   // ffn dim
constexpr int QKW = 2048; // combined q|k width
constexpr float ATT_SCALE = 0.125f;  // 1/sqrt(64)

// ---------------------------------------------------------------------------
// Scratch (static device globals -- no allocations allowed)
// ---------------------------------------------------------------------------
__device__ float g_t1 [BB * SS * DD];                 // pre-LN fp32
__device__ float g_h2 [BB * SS * DD];                 // pre-LN fp32
__device__ float g_qe [(size_t)BB * HH * SS * SS];    // 134 MB
__device__ float g_lg [(size_t)BB * HH * SS * SS];    // 134 MB
__device__ float g_rate[DD];
__device__ float g_bqk [LL * QKW];

// split activation buffers
__device__ __nv_bfloat16 g_xh [BB * SS * DD], g_xl [BB * SS * DD];  // layer in
__device__ __nv_bfloat16 g_qkh[BB * SS * QKW], g_qkl[BB * SS * QKW]; // q|k
__device__ __nv_bfloat16 g_vth[BB * DD * SS], g_vtl[BB * DD * SS];  // v^T per head
__device__ __nv_bfloat16 g_ath[BB * SS * DD], g_atl[BB * SS * DD];  // attn out
__device__ __nv_bfloat16 g_ffh[BB * SS * DF], g_ffl[BB * SS * DF];
__device__ __nv_bfloat16 g_awh[(size_t)BB * HH * SS * SS];          // 67 MB
__device__ __nv_bfloat16 g_awl[(size_t)BB * HH * SS * SS];          // 67 MB
__device__ __nv_bfloat16 g_eh [LL * SS * HD], g_el [LL * SS * HD];

// bf16 split weight buffers ([N, K] transposed, hi/lo)
__device__ __nv_bfloat16 g_wqk_h[LL * QKW * DD], g_wqk_l[LL * QKW * DD];
__device__ __nv_bfloat16 g_wv_h[LL * DD * DD],  g_wv_l[LL * DD * DD];
__device__ __nv_bfloat16 g_wo_h[LL * DD * DD],  g_wo_l[LL * DD * DD];
__device__ __nv_bfloat16 g_w1_h[LL * DF * DD],  g_w1_l[LL * DF * DD];
__device__ __nv_bfloat16 g_w2_h[LL * DD * DF],  g_w2_l[LL * DD * DF];
__device__ __nv_bfloat16 g_wf_h[VV * DD],       g_wf_l[VV * DD];

// ---------------------------------------------------------------------------
// PTX helpers (mma.sync / ldmatrix / cp.async -- standard ISA, sm_80+)
// ---------------------------------------------------------------------------
__device__ __forceinline__ uint32_t smem_u32(const void* p) {
    uint32_t a;
    asm("{ .reg .u64 t; cvta.to.shared.u64 t, %1; cvt.u32.u64 %0, t; }"
        : "=r"(a) : "l"(p));
    return a;
}
__device__ __forceinline__ void cpasync16(uint32_t s, const void* g) {
    asm volatile("cp.async.ca.shared.global [%0], [%1], 16;"
                 :: "r"(s), "l"(g) : "memory");
}
__device__ __forceinline__ void ldm_x4(uint32_t a, uint32_t r[4]) {
    asm volatile("ldmatrix.sync.aligned.m8n8.x4.shared.b16 {%0,%1,%2,%3}, [%4];"
                 : "=r"(r[0]), "=r"(r[1]), "=r"(r[2]), "=r"(r[3]) : "r"(a));
}
__device__ __forceinline__ void mma_bf16(float c[4], const uint32_t a[4],
                                         const uint32_t b[2]) {
    asm volatile("mma.sync.aligned.m16n8k16.row.col.f32.bf16.bf16.f32 "
                 "{%0,%1,%2,%3}, {%4,%5,%6,%7}, {%8,%9}, {%0,%1,%2,%3};"
                 : "+f"(c[0]), "+f"(c[1]), "+f"(c[2]), "+f"(c[3])
                 : "r"(a[0]), "r"(a[1]), "r"(a[2]), "r"(a[3]),
                   "r"(b[0]), "r"(b[1]));
}
__device__ __forceinline__ uint32_t pack_bf2(float a, float b) {
    __nv_bfloat162 t = __floats2bfloat162_rn(a, b);
    return *(uint32_t*)&t;
}
__device__ __forceinline__ float bf_hi(float v) {
    return __bfloat162float(__float2bfloat16(v));
}

// ---------------------------------------------------------------------------
// Unified batched split-bf16 HMMA GEMM:
//   C[M,N] = (Ahi+Alo)[M,K] @ (Bhi+Blo)[N,K]^T + bias
// BM=128 fixed, BN 128 or 64; 8 warps (4M x 2N), warp tile 32 x BN/2.
// SKIP: 0 none, 1 QE anti-diagonal skip, 2 causal strictly-upper skip.
// KCAP: cap K loop at m0+128 (causal AV).
// OUT:  0 = fp32 C;  1 = split bf16 (Ch,Cl);  2 = split bf16 TRANSPOSED.
// ---------------------------------------------------------------------------
template<int BN, int SKIP, bool KCAP, int OUT, bool RELU>
__global__ __launch_bounds__(256, 2)
void gemm_mma(const __nv_bfloat16* __restrict__ Ahi, const __nv_bfloat16* __restrict__ Alo,
              const __nv_bfloat16* __restrict__ Bhi, const __nv_bfloat16* __restrict__ Blo,
              const float* __restrict__ bias, float* __restrict__ C,
              __nv_bfloat16* __restrict__ Ch, __nv_bfloat16* __restrict__ Cl,
              int K, int lda, int ldb, int ldc, int zdiv,
              long long sA1, long long sA2,
              long long sB1, long long sB2,
              long long sC1, long long sC2)
{
    constexpr int ABY = 10240;            // 128 rows * 80B
    constexpr int BBY = BN * 80;
    constexpr int STG = 2 * ABY + 2 * BBY;
    constexpr int NT  = BN / 16;
    constexpr int BN2 = BN / 2;

    const int m0 = blockIdx.y * 128;
    const int n0 = blockIdx.x * BN;
    if (SKIP == 1 && (m0 + n0 + 127 + BN - 1 < SS - 1)) return;
    if (SKIP == 2 && (n0 >= m0 + 128)) return;

    extern __shared__ char dynsmem[];
    const uint32_t sbase = smem_u32(dynsmem);
    const int tid  = threadIdx.x;
    const int lane = tid & 31;
    const int warp = tid >> 5;
    const int wm = warp & 3;
    const int wn = warp >> 2;

    const int z  = blockIdx.z;
    const int zb = z / zdiv;
    const int zh = z % zdiv;
    Ahi += (size_t)zb * sA1 + (size_t)zh * sA2;
    Alo += (size_t)zb * sA1 + (size_t)zh * sA2;
    Bhi += (size_t)zb * sB1 + (size_t)zh * sB2;
    Blo += (size_t)zb * sB1 + (size_t)zh * sB2;
    if (OUT == 0) C  += (size_t)zb * sC1 + (size_t)zh * sC2;
    else { Ch += (size_t)zb * sC1 + (size_t)zh * sC2;
           Cl += (size_t)zb * sC1 + (size_t)zh * sC2; }

    float acc[2][NT][4];
#pragma unroll
    for (int mt = 0; mt < 2; ++mt)
#pragma unroll
        for (int nt = 0; nt < NT; ++nt)
#pragma unroll
            for (int r = 0; r < 4; ++r) acc[mt][nt][r] = 0.f;

    const int Keff = KCAP ? min(K, m0 + 128) : K;
    const int nch  = Keff >> 5;

    auto load_stage = [&](int c) {
        const int k0c = c << 5;
        const uint32_t sb = sbase + (c & 1) * STG;
#pragma unroll
        for (int i = 0; i < 2; ++i) {
            const int u = tid + i * 256;
            const int row = u >> 2, seg = u & 3;
            const uint32_t so = sb + row * 80 + seg * 16;
            const size_t ga = (size_t)(m0 + row) * lda + k0c + seg * 8;
            cpasync16(so,       Ahi + ga);
            cpasync16(so + ABY, Alo + ga);
        }
        constexpr int BU = (BN * 4) / 256;
#pragma unroll
        for (int i = 0; i < BU; ++i) {
            const int u = tid + i * 256;
            const int row = u >> 2, seg = u & 3;
            const uint32_t so = sb + 2 * ABY + row * 80 + seg * 16;
            const size_t gb = (size_t)(n0 + row) * ldb + k0c + seg * 8;
            cpasync16(so,       Bhi + gb);
            cpasync16(so + BBY, Blo + gb);
        }
        asm volatile("cp.async.commit_group;" ::: "memory");
    };

    load_stage(0);

    const int lr  = lane & 7;
    const int sel = lane >> 3;
    const int a_row_off = lr + ((sel & 1) << 3);
    const int a_k_off   = (sel >> 1) << 3;
    const int b_n_off   = lr + ((sel >> 1) << 3);
    const int b_k_off   = (sel & 1) << 3;

    for (int c = 0; c < nch; ++c) {
        if (c + 1 < nch) {
            load_stage(c + 1);
            asm volatile("cp.async.wait_group 1;" ::: "memory");
        } else {
            asm volatile("cp.async.wait_group 0;" ::: "memory");
        }
        __syncthreads();
        const uint32_t sb = sbase + (c & 1) * STG;

#pragma unroll
        for (int ks = 0; ks < 2; ++ks) {
            const int kk = ks << 4;
            uint32_t ah[2][4], al[2][4], bb[NT][2];
#pragma unroll
            for (int mt = 0; mt < 2; ++mt) {
                const int row = wm * 32 + mt * 16 + a_row_off;
                const uint32_t ad = sb + row * 80 + (kk + a_k_off) * 2;
                ldm_x4(ad, ah[mt]);
                ldm_x4(ad + ABY, al[mt]);
            }
#pragma unroll
            for (int p = 0; p < NT / 2; ++p) {
                const int n = wn * BN2 + p * 16 + b_n_off;
                uint32_t r[4];
                ldm_x4(sb + 2 * ABY + n * 80 + (kk + b_k_off) * 2, r);
                bb[2 * p][0]     = r[0]; bb[2 * p][1]     = r[1];
                bb[2 * p + 1][0] = r[2]; bb[2 * p + 1][1] = r[3];
            }
#pragma unroll
            for (int mt = 0; mt < 2; ++mt)
#pragma unroll
                for (int nt = 0; nt < NT; ++nt)
                    mma_bf16(acc[mt][nt], ah[mt], bb[nt]);
#pragma unroll
            for (int mt = 0; mt < 2; ++mt)
#pragma unroll
                for (int nt = 0; nt < NT; ++nt)
                    mma_bf16(acc[mt][nt], al[mt], bb[nt]);
#pragma unroll
            for (int p = 0; p < NT / 2; ++p) {
                const int n = wn * BN2 + p * 16 + b_n_off;
                uint32_t r[4];
                ldm_x4(sb + 2 * ABY + BBY + n * 80 + (kk + b_k_off) * 2, r);
                bb[2 * p][0]     = r[0]; bb[2 * p][1]     = r[1];
                bb[2 * p + 1][0] = r[2]; bb[2 * p + 1][1] = r[3];
            }
#pragma unroll
            for (int mt = 0; mt < 2; ++mt)
#pragma unroll
                for (int nt = 0; nt < NT; ++nt)
                    mma_bf16(acc[mt][nt], ah[mt], bb[nt]);
        }
        __syncthreads();
    }

    const int rbase = m0 + wm * 32 + (lane >> 2);
    const int cbase = n0 + wn * BN2 + 2 * (lane & 3);
#pragma unroll
    for (int mt = 0; mt < 2; ++mt) {
#pragma unroll
        for (int nt = 0; nt < NT; ++nt) {
            const int col = cbase + nt * 8;
            float b0v = 0.f, b1v = 0.f;
            if (bias) { b0v = bias[col]; b1v = bias[col + 1]; }
            float v0 = acc[mt][nt][0] + b0v;
            float v1 = acc[mt][nt][1] + b1v;
            float v2 = acc[mt][nt][2] + b0v;
            float v3 = acc[mt][nt][3] + b1v;
            if (RELU) {
                v0 = fmaxf(v0, 0.f); v1 = fmaxf(v1, 0.f);
                v2 = fmaxf(v2, 0.f); v3 = fmaxf(v3, 0.f);
            }
            const int r0 = rbase + mt * 16;
            if (OUT == 0) {
                *(float2*)&C[(size_t)r0 * ldc + col]       = make_float2(v0, v1);
                *(float2*)&C[(size_t)(r0 + 8) * ldc + col] = make_float2(v2, v3);
            } else if (OUT == 1) {
                const float h0 = bf_hi(v0), h1 = bf_hi(v1);
                const float h2 = bf_hi(v2), h3 = bf_hi(v3);
                *(uint32_t*)&Ch[(size_t)r0 * ldc + col]       = pack_bf2(h0, h1);
                *(uint32_t*)&Ch[(size_t)(r0 + 8) * ldc + col] = pack_bf2(h2, h3);
                *(uint32_t*)&Cl[(size_t)r0 * ldc + col]       = pack_bf2(v0 - h0, v1 - h1);
                *(uint32_t*)&Cl[(size_t)(r0 + 8) * ldc + col] = pack_bf2(v2 - h2, v3 - h3);
            } else {
                const float vv[4] = {v0, v1, v2, v3};
#pragma unroll
                for (int e = 0; e < 4; ++e) {
                    const int cc = col + (e & 1);
                    const int rr = r0 + (e >> 1) * 8;
                    const __nv_bfloat16 hb = __float2bfloat16(vv[e]);
                    Ch[(size_t)cc * ldc + rr] = hb;
                    Cl[(size_t)cc * ldc + rr] =
                        __float2bfloat16(vv[e] - __bfloat162float(hb));
                }
            }
        }
    }
}

// ---------------------------------------------------------------------------
// Weight transpose + bf16 hi/lo split: W[l][K][N] -> hi/lo at out + l*lstride,
// row-major [N, K].
// ---------------------------------------------------------------------------
__global__ void conv_w(const float* __restrict__ W, __nv_bfloat16* __restrict__ hi,
                       __nv_bfloat16* __restrict__ lo, int K, int N, long long lstride)
{
    __shared__ float t[32][33];
    const int l = blockIdx.z;
    W  += (size_t)l * K * N;
    hi += (size_t)l * lstride;
    lo += (size_t)l * lstride;
    const int k0 = blockIdx.y * 32, n0 = blockIdx.x * 32;
    const int tx = threadIdx.x, ty = threadIdx.y;
#pragma unroll
    for (int i = ty; i < 32; i += 8)
        t[i][tx] = W[(size_t)(k0 + i) * N + n0 + tx];
    __syncthreads();
#pragma unroll
    for (int i = ty; i < 32; i += 8) {
        const float v = t[tx][i];
        const __nv_bfloat16 h = __float2bfloat16(v);
        const __nv_bfloat16 r = __float2bfloat16(v - __bfloat162float(h));
        hi[(size_t)(n0 + i) * K + k0 + tx] = h;
        lo[(size_t)(n0 + i) * K + k0 + tx] = r;
    }
}

// elementwise hi/lo split (for E)
__global__ void split_act(const float* __restrict__ x, __nv_bfloat16* __restrict__ hi,
                          __nv_bfloat16* __restrict__ lo, int n4)
{
    const int i = blockIdx.x * 256 + threadIdx.x;
    if (i >= n4) return;
    const float4 v = ((const float4*)x)[i];
    const float f[4] = {v.x, v.y, v.z, v.w};
    unsigned short hh[4], ll[4];
#pragma unroll
    for (int j = 0; j < 4; j++) {
        const __nv_bfloat16 hb = __float2bfloat16(f[j]);
        const __nv_bfloat16 lb = __float2bfloat16(f[j] - __bfloat162float(hb));
        hh[j] = __bfloat16_as_ushort(hb);
        ll[j] = __bfloat16_as_ushort(lb);
    }
    ((uint2*)hi)[i] = *(const uint2*)hh;
    ((uint2*)lo)[i] = *(const uint2*)ll;
}

// build combined q|k bias [L][2048]
__global__ void concat_bias(const float* __restrict__ bq, const float* __restrict__ bk,
                            float* __restrict__ bqk)
{
    const int i = blockIdx.x * 256 + threadIdx.x;
    if (i >= LL * QKW) return;
    const int l = i >> 11, c = i & (QKW - 1);
    bqk[i] = (c < DD) ? bq[l * DD + c] : bk[l * DD + c - DD];
}

// ---------------------------------------------------------------------------
// Sinusoid rate + embedding (writes split bf16 directly)
// ---------------------------------------------------------------------------
__global__ void rate_kernel(float* __restrict__ rate)
{
    const int d = blockIdx.x * 256 + threadIdx.x;
    if (d >= DD) return;
    const double LN1E4 = 9.210340371976184;
    const int par = d & 1;
    const float r1 = (float)exp(-LN1E4 * (double)d   / 1024.0);
    const float r2 = (float)exp( LN1E4 * (double)par / 1024.0);
    rate[d] = r1 * r2;
}

__global__ void embed_split(const int* __restrict__ x,
                            const float* __restrict__ emb,
                            const float* __restrict__ rate,
                            __nv_bfloat16* __restrict__ oh,
                            __nv_bfloat16* __restrict__ ol)
{
    const int bs = blockIdx.x;
    const int s  = bs & (SS - 1);
    const int tok = x[bs];
    const float* e = emb + (size_t)tok * DD;
    for (int d = threadIdx.x; d < DD; d += blockDim.x) {
        const int par = d & 1;
        const float ph = (float)s * rate[d] + 1.5707964f * (float)par;
        const float v = e[d] * 32.0f + sinf(ph);
        const __nv_bfloat16 hb = __float2bfloat16(v);
        oh[(size_t)bs * DD + d] = hb;
        ol[(size_t)bs * DD + d] = __float2bfloat16(v - __bfloat162float(hb));
    }
}

// ---------------------------------------------------------------------------
// Fused Srel gather + scale + masks + softmax; writes SPLIT bf16 aw.
// Zero-pads each row out to the next 256 boundary (AV reads <=128 boundary).
// ---------------------------------------------------------------------------
__global__ __launch_bounds__(256)
void attn_softmax(const float* __restrict__ lg, const float* __restrict__ qe,
                  const int* __restrict__ x,
                  __nv_bfloat16* __restrict__ awh, __nv_bfloat16* __restrict__ awl)
{
    const int i  = blockIdx.x;
    const int bh = blockIdx.y;
    const int b  = bh >> 4;
    const float* row  = lg + (size_t)bh * SS * SS + (size_t)i * SS;
    const float* qrow = qe + (size_t)bh * SS * SS + (size_t)i * SS;
    __nv_bfloat16* oh = awh + (size_t)bh * SS * SS + (size_t)i * SS;
    __nv_bfloat16* ol = awl + (size_t)bh * SS * SS + (size_t)i * SS;
    const int* xb = x + b * SS;
    const int t = threadIdx.x;
    const int nch = (i >> 8) + 1;

    float vals[4];
    float mx = -1e30f;
    for (int c = 0; c < nch; c++) {
        const int j = c * 256 + t;
        float vv = -1e30f;
        if (j <= i) {
            vv = (row[j] + qrow[SS - 1 - i + j]) * ATT_SCALE;
            if (xb[j] == 0) vv -= 1e9f;
        }
        vals[c] = vv;
        mx = fmaxf(mx, vv);
    }
    __shared__ float sh[8];
#pragma unroll
    for (int o = 16; o > 0; o >>= 1) mx = fmaxf(mx, __shfl_xor_sync(0xffffffffu, mx, o));
    if ((t & 31) == 0) sh[t >> 5] = mx;
    __syncthreads();
    mx = sh[0];
#pragma unroll
    for (int w = 1; w < 8; w++) mx = fmaxf(mx, sh[w]);

    float s = 0.f;
    for (int c = 0; c < nch; c++) { vals[c] = expf(vals[c] - mx); s += vals[c]; }
#pragma unroll
    for (int o = 16; o > 0; o >>= 1) s += __shfl_xor_sync(0xffffffffu, s, o);
    __syncthreads();
    if ((t & 31) == 0) sh[t >> 5] = s;
    __syncthreads();
    s = 0.f;
#pragma unroll
    for (int w = 0; w < 8; w++) s += sh[w];
    const float inv = 1.f / s;
    for (int c = 0; c < nch; c++) {
        const float p = vals[c] * inv;
        const __nv_bfloat16 hb = __float2bfloat16(p);
        oh[c * 256 + t] = hb;
        ol[c * 256 + t] = __float2bfloat16(p - __bfloat162float(hb));
    }
}

// ---------------------------------------------------------------------------
// LayerNorm over last dim (1024); reads fp32, writes SPLIT bf16.
// ---------------------------------------------------------------------------
__global__ __launch_bounds__(256)
void ln_split(const float* __restrict__ xin, const float* __restrict__ g,
              const float* __restrict__ be,
              __nv_bfloat16* __restrict__ oh, __nv_bfloat16* __restrict__ ol)
{
    const int row = blockIdx.x;
    const float* p = xin + (size_t)row * DD;
    const int t = threadIdx.x;
    float v[4];
    float s = 0.f, s2 = 0.f;
#pragma unroll
    for (int c = 0; c < 4; c++) {
        v[c] = p[t + c * 256];
        s += v[c];
        s2 += v[c] * v[c];
    }
    __shared__ float sh1[8], sh2[8];
#pragma unroll
    for (int o = 16; o > 0; o >>= 1) {
        s  += __shfl_xor_sync(0xffffffffu, s,  o);
        s2 += __shfl_xor_sync(0xffffffffu, s2, o);
    }
    if ((t & 31) == 0) { sh1[t >> 5] = s; sh2[t >> 5] = s2; }
    __syncthreads();
    s = 0.f; s2 = 0.f;
#pragma unroll
    for (int w = 0; w < 8; w++) { s += sh1[w]; s2 += sh2[w]; }
    const float mu  = s  * (1.f / DD);
    const float var = s2 * (1.f / DD) - mu * mu;
    const float inv = rsqrtf(var + 1e-6f);
#pragma unroll
    for (int c = 0; c < 4; c++) {
        const int d = t + c * 256;
        const float o = (v[c] - mu) * inv * g[d] + be[d];
        const __nv_bfloat16 hb = __float2bfloat16(o);
        oh[(size_t)row * DD + d] = hb;
        ol[(size_t)row * DD + d] = __float2bfloat16(o - __bfloat162float(hb));
    }
}

// ---------------------------------------------------------------------------
// Host side
// ---------------------------------------------------------------------------
using bf16 = __nv_bfloat16;

template<int BN, int SKIP, bool KCAP, int OUT, bool RELU>
static void run_mma(const bf16* ah, const bf16* al, const bf16* bh, const bf16* bl,
                    const float* bias, float* C, bf16* Ch, bf16* Cl,
                    int M, int N, int K, int lda, int ldb, int ldc,
                    int batch, int zdiv,
                    long long sA1, long long sA2,
                    long long sB1, long long sB2,
                    long long sC1, long long sC2)
{
    constexpr int STG = 2 * 10240 + 2 * BN * 80;
    static bool init = false;
    if (!init) {
        cudaFuncSetAttribute(gemm_mma<BN, SKIP, KCAP, OUT, RELU>,
                             cudaFuncAttributeMaxDynamicSharedMemorySize, 2 * STG);
        init = true;
    }
    dim3 grid(N / BN, M / 128, batch);
    gemm_mma<BN, SKIP, KCAP, OUT, RELU><<<grid, 256, 2 * STG>>>(
        ah, al, bh, bl, bias, C, Ch, Cl, K, lda, ldb, ldc,
        zdiv, sA1, sA2, sB1, sB2, sC1, sC2);
}

extern "C" void kernel_launch(void* const* d_in, const int* in_sizes, int n_in,
                              void* d_out, int out_size)
{
    const int*   x   = (const int*)  d_in[0];
    const float* emb = (const float*)d_in[1];
    const float* Wq  = (const float*)d_in[2];
    const float* bq  = (const float*)d_in[3];
    const float* Wk  = (const float*)d_in[4];
    const float* bk  = (const float*)d_in[5];
    const float* Wv  = (const float*)d_in[6];
    const float* bv  = (const float*)d_in[7];
    const float* Wo  = (const float*)d_in[8];
    const float* bo  = (const float*)d_in[9];
    const float* W1  = (const float*)d_in[10];
    const float* b1  = (const float*)d_in[11];
    const float* W2  = (const float*)d_in[12];
    const float* b2  = (const float*)d_in[13];
    const float* g1  = (const float*)d_in[14];
    const float* be1 = (const float*)d_in[15];
    const float* g2  = (const float*)d_in[16];
    const float* be2 = (const float*)d_in[17];
    const float* E   = (const float*)d_in[18];
    const float* Wf  = (const float*)d_in[19];
    const float* bf  = (const float*)d_in[20];
    float* out = (float*)d_out;

    float *t1, *h2, *qe, *lg, *rate, *bqk;
    cudaGetSymbolAddress((void**)&t1, g_t1);
    cudaGetSymbolAddress((void**)&h2, g_h2);
    cudaGetSymbolAddress((void**)&qe, g_qe);
    cudaGetSymbolAddress((void**)&lg, g_lg);
    cudaGetSymbolAddress((void**)&rate, g_rate);
    cudaGetSymbolAddress((void**)&bqk, g_bqk);

    bf16 *xh, *xl, *qkh, *qkl, *vth, *vtl, *ath, *atl, *ffh, *ffl;
    bf16 *awh, *awl, *eh, *el;
    cudaGetSymbolAddress((void**)&xh,  g_xh);  cudaGetSymbolAddress((void**)&xl,  g_xl);
    cudaGetSymbolAddress((void**)&qkh, g_qkh); cudaGetSymbolAddress((void**)&qkl, g_qkl);
    cudaGetSymbolAddress((void**)&vth, g_vth); cudaGetSymbolAddress((void**)&vtl, g_vtl);
    cudaGetSymbolAddress((void**)&ath, g_ath); cudaGetSymbolAddress((void**)&atl, g_atl);
    cudaGetSymbolAddress((void**)&ffh, g_ffh); cudaGetSymbolAddress((void**)&ffl, g_ffl);
    cudaGetSymbolAddress((void**)&awh, g_awh); cudaGetSymbolAddress((void**)&awl, g_awl);
    cudaGetSymbolAddress((void**)&eh,  g_eh);  cudaGetSymbolAddress((void**)&el,  g_el);

    bf16 *wqkh, *wqkl, *wvh, *wvl, *woh, *wol;
    bf16 *w1h, *w1l, *w2h, *w2l, *wfh, *wfl;
    cudaGetSymbolAddress((void**)&wqkh, g_wqk_h); cudaGetSymbolAddress((void**)&wqkl, g_wqk_l);
    cudaGetSymbolAddress((void**)&wvh, g_wv_h); cudaGetSymbolAddress((void**)&wvl, g_wv_l);
    cudaGetSymbolAddress((void**)&woh, g_wo_h); cudaGetSymbolAddress((void**)&wol, g_wo_l);
    cudaGetSymbolAddress((void**)&w1h, g_w1_h); cudaGetSymbolAddress((void**)&w1l, g_w1_l);
    cudaGetSymbolAddress((void**)&w2h, g_w2_h); cudaGetSymbolAddress((void**)&w2l, g_w2_l);
    cudaGetSymbolAddress((void**)&wfh, g_wf_h); cudaGetSymbolAddress((void**)&wfl, g_wf_l);

    const int M = BB * SS;  // 2048
    const long long sSD  = (long long)SS * DD;
    const long long sSQK = (long long)SS * QKW;
    const long long sHSS = (long long)HH * SS * SS;
    const long long sSSq = (long long)SS * SS;
    const long long sDS  = (long long)DD * SS;
    const long long wQKL = (long long)QKW * DD;     // per-layer qk weight stride

    // weight + E conversion
    {
        dim3 tb(32, 8);
        // Wq -> rows 0..1023 of combined weight; Wk -> rows 1024..2047
        conv_w<<<dim3(DD / 32, DD / 32, LL), tb>>>(Wq, wqkh, wqkl, DD, DD, wQKL);
        conv_w<<<dim3(DD / 32, DD / 32, LL), tb>>>(Wk, wqkh + (size_t)DD * DD,
                                                   wqkl + (size_t)DD * DD, DD, DD, wQKL);
        conv_w<<<dim3(DD / 32, DD / 32, LL), tb>>>(Wv, wvh, wvl, DD, DD, (long long)DD * DD);
        conv_w<<<dim3(DD / 32, DD / 32, LL), tb>>>(Wo, woh, wol, DD, DD, (long long)DD * DD);
        conv_w<<<dim3(DF / 32, DD / 32, LL), tb>>>(W1, w1h, w1l, DD, DF, (long long)DF * DD);
        conv_w<<<dim3(DD / 32, DF / 32, LL), tb>>>(W2, w2h, w2l, DF, DD, (long long)DD * DF);
        conv_w<<<dim3(VV / 32, DD / 32, 1),  tb>>>(Wf, wfh, wfl, DD, VV, (long long)VV * DD);
        split_act<<<(LL * SS * HD / 4 + 255) / 256, 256>>>(E, eh, el, LL * SS * HD / 4);
        concat_bias<<<(LL * QKW + 255) / 256, 256>>>(bq, bk, bqk);
    }

    rate_kernel<<<4, 256>>>(rate);
    embed_split<<<BB * SS, 256>>>(x, emb, rate, xh, xl);

    for (int l = 0; l < LL; l++) {
        const size_t wdd = (size_t)l * DD * DD;
        const size_t wdf = (size_t)l * DF * DD;
        const bf16* ehl = eh + (size_t)l * SS * HD;
        const bf16* ell = el + (size_t)l * SS * HD;

        // combined Q|K projection: N=2048 -> grid 256 CTAs
        run_mma<128, 0, false, 1, false>(xh, xl, wqkh + (size_t)l * wQKL,
                                         wqkl + (size_t)l * wQKL, bqk + l * QKW,
                                         nullptr, qkh, qkl, M, QKW, DD, DD, DD, QKW,
                                         1, 1, 0, 0, 0, 0, 0, 0);
        // V projection (split-transposed per batch)
        run_mma<128, 0, false, 2, false>(xh, xl, wvh + wdd, wvl + wdd, bv + l * DD,
                                         nullptr, vth, vtl, SS, DD, DD, DD, DD, SS,
                                         BB, 1, sSD, 0, 0, 0, sDS, 0);

        // QE = q @ E^T (anti-diagonal tiles only); q rows have stride QKW
        run_mma<128, 1, false, 0, false>(qkh, qkl, ehl, ell, nullptr, qe, nullptr, nullptr,
                                         SS, SS, HD, QKW, HD, SS, BB * HH, HH,
                                         sSQK, HD, 0, 0, sHSS, sSSq);
        // QK^T (causal tiles only); k part lives at column offset DD
        run_mma<128, 2, false, 0, false>(qkh, qkl, qkh + DD, qkl + DD, nullptr, lg,
                                         nullptr, nullptr,
                                         SS, SS, HD, QKW, QKW, SS, BB * HH, HH,
                                         sSQK, HD, sSQK, HD, sHSS, sSSq);

        // fused skew + masks + softmax -> split bf16 aw
        attn_softmax<<<dim3(SS, BB * HH), 256>>>(lg, qe, x, awh, awl);

        // attn = aw @ v (K capped, split output into ath/atl)
        run_mma<64, 0, true, 1, false>(awh, awl, vth, vtl, nullptr,
                                       nullptr, ath, atl, SS, HD, SS, SS, SS, DD,
                                       BB * HH, HH, sHSS, sSSq,
                                       sDS, (long long)HD * SS, sSD, HD);

        // Wo + LN1
        run_mma<128, 0, false, 0, false>(ath, atl, woh + wdd, wol + wdd, bo + l * DD,
                                         t1, nullptr, nullptr, M, DD, DD, DD, DD, DD,
                                         1, 1, 0, 0, 0, 0, 0, 0);
        ln_split<<<BB * SS, 256>>>(t1, g1 + l * DD, be1 + l * DD, xh, xl);

        // FFN (W1 with BN=64 -> 128 CTAs)
        run_mma<64, 0, false, 1, true>(xh, xl, w1h + wdf, w1l + wdf, b1 + l * DF,
                                       nullptr, ffh, ffl, M, DF, DD, DD, DD, DF,
                                       1, 1, 0, 0, 0, 0, 0, 0);
        run_mma<128, 0, false, 0, false>(ffh, ffl, w2h + wdf, w2l + wdf, b2 + l * DD,
                                         h2, nullptr, nullptr, M, DD, DF, DF, DF, DD,
                                         1, 1, 0, 0, 0, 0, 0, 0);
        ln_split<<<BB * SS, 256>>>(h2, g2 + l * DD, be2 + l * DD, xh, xl);
    }

    // final projection to vocab (BN=64 -> 64 CTAs)
    run_mma<64, 0, false, 0, false>(xh, xl, wfh, wfl, bf, out, nullptr, nullptr,
                                    M, VV, DD, DD, DD, VV, 1, 1, 0, 0, 0, 0, 0, 0);
}

// round 8
// speedup vs baseline: 1.5708x; 1.0189x over previous
#include <cuda_runtime.h>
#include <cuda_bf16.h>
#include <math.h>
#include <stdint.h>

// ---------------------------------------------------------------------------
// Problem constants
// ---------------------------------------------------------------------------
constexpr int BB = 2;     // batch
constexpr int SS = 1024;  // seq len
constexpr int DD = 1024;  // model dim
constexpr int HH = 16;    // heads
constexpr int LL = 6;     // layers
constexpr int VV = 256;   // vocab
constexpr int HD = 64;    // head dim
constexpr int DF = 512;   // ffn dim
constexpr int QKW = 2048; // combined q|k width
constexpr float ATT_SCALE = 0.125f;  // 1/sqrt(64)

// ---------------------------------------------------------------------------
// Scratch (static device globals -- no allocations allowed)
// ---------------------------------------------------------------------------
__device__ float g_t1 [BB * SS * DD];                 // pre-LN fp32
__device__ float g_h2 [BB * SS * DD];                 // pre-LN fp32
__device__ float g_qe [(size_t)BB * HH * SS * SS];    // 134 MB
__device__ float g_lg [(size_t)BB * HH * SS * SS];    // 134 MB
__device__ float g_rate[DD];
__device__ float g_bqk [LL * QKW];

// split activation buffers
__device__ __nv_bfloat16 g_xh [BB * SS * DD], g_xl [BB * SS * DD];  // layer in
__device__ __nv_bfloat16 g_qkh[BB * SS * QKW], g_qkl[BB * SS * QKW]; // q|k
__device__ __nv_bfloat16 g_vth[BB * DD * SS], g_vtl[BB * DD * SS];  // v^T per head
__device__ __nv_bfloat16 g_ath[BB * SS * DD], g_atl[BB * SS * DD];  // attn out
__device__ __nv_bfloat16 g_ffh[BB * SS * DF], g_ffl[BB * SS * DF];
__device__ __nv_bfloat16 g_awh[(size_t)BB * HH * SS * SS];          // 67 MB
__device__ __nv_bfloat16 g_awl[(size_t)BB * HH * SS * SS];          // 67 MB
__device__ __nv_bfloat16 g_eh [LL * SS * HD], g_el [LL * SS * HD];

// bf16 split weight buffers ([N, K] transposed, hi/lo)
__device__ __nv_bfloat16 g_wqk_h[LL * QKW * DD], g_wqk_l[LL * QKW * DD];
__device__ __nv_bfloat16 g_wv_h[LL * DD * DD],  g_wv_l[LL * DD * DD];
__device__ __nv_bfloat16 g_wo_h[LL * DD * DD],  g_wo_l[LL * DD * DD];
__device__ __nv_bfloat16 g_w1_h[LL * DF * DD],  g_w1_l[LL * DF * DD];
__device__ __nv_bfloat16 g_w2_h[LL * DD * DF],  g_w2_l[LL * DD * DF];
__device__ __nv_bfloat16 g_wf_h[VV * DD],       g_wf_l[VV * DD];

// ---------------------------------------------------------------------------
// PTX helpers (mma.sync / ldmatrix / cp.async -- standard ISA, sm_80+)
// ---------------------------------------------------------------------------
__device__ __forceinline__ uint32_t smem_u32(const void* p) {
    uint32_t a;
    asm("{ .reg .u64 t; cvta.to.shared.u64 t, %1; cvt.u32.u64 %0, t; }"
        : "=r"(a) : "l"(p));
    return a;
}
__device__ __forceinline__ void cpasync16(uint32_t s, const void* g) {
    asm volatile("cp.async.ca.shared.global [%0], [%1], 16;"
                 :: "r"(s), "l"(g) : "memory");
}
__device__ __forceinline__ void ldm_x4(uint32_t a, uint32_t r[4]) {
    asm volatile("ldmatrix.sync.aligned.m8n8.x4.shared.b16 {%0,%1,%2,%3}, [%4];"
                 : "=r"(r[0]), "=r"(r[1]), "=r"(r[2]), "=r"(r[3]) : "r"(a));
}
__device__ __forceinline__ void mma_bf16(float c[4], const uint32_t a[4],
                                         const uint32_t b[2]) {
    asm volatile("mma.sync.aligned.m16n8k16.row.col.f32.bf16.bf16.f32 "
                 "{%0,%1,%2,%3}, {%4,%5,%6,%7}, {%8,%9}, {%0,%1,%2,%3};"
                 : "+f"(c[0]), "+f"(c[1]), "+f"(c[2]), "+f"(c[3])
                 : "r"(a[0]), "r"(a[1]), "r"(a[2]), "r"(a[3]),
                   "r"(b[0]), "r"(b[1]));
}
__device__ __forceinline__ uint32_t pack_bf2(float a, float b) {
    __nv_bfloat162 t = __floats2bfloat162_rn(a, b);
    return *(uint32_t*)&t;
}
__device__ __forceinline__ float bf_hi(float v) {
    return __bfloat162float(__float2bfloat16(v));
}

// ---------------------------------------------------------------------------
// Unified batched split-bf16 HMMA GEMM:
//   C[M,N] = (Ahi+Alo)[M,K] @ (Bhi+Blo)[N,K]^T + bias
// BM=128 fixed, BN 128 or 64; 8 warps (4M x 2N), warp tile 32 x BN/2.
// SKIP: 0 none, 1 QE anti-diagonal skip, 2 causal strictly-upper skip.
// KCAP: cap K loop at m0+128 (causal AV).
// OUT:  0 = fp32 C;  1 = split bf16 (Ch,Cl);  2 = split bf16 TRANSPOSED
//       (staged through SMEM for coalesced stores).
// ---------------------------------------------------------------------------
template<int BN, int SKIP, bool KCAP, int OUT, bool RELU>
__global__ __launch_bounds__(256, 2)
void gemm_mma(const __nv_bfloat16* __restrict__ Ahi, const __nv_bfloat16* __restrict__ Alo,
              const __nv_bfloat16* __restrict__ Bhi, const __nv_bfloat16* __restrict__ Blo,
              const float* __restrict__ bias, float* __restrict__ C,
              __nv_bfloat16* __restrict__ Ch, __nv_bfloat16* __restrict__ Cl,
              int K, int lda, int ldb, int ldc, int zdiv,
              long long sA1, long long sA2,
              long long sB1, long long sB2,
              long long sC1, long long sC2)
{
    constexpr int ABY = 10240;            // 128 rows * 80B
    constexpr int BBY = BN * 80;
    constexpr int STG = 2 * ABY + 2 * BBY;
    constexpr int NT  = BN / 16;
    constexpr int BN2 = BN / 2;
    constexpr int TP  = 136;              // transpose-stage pitch (bf16 elems)

    const int m0 = blockIdx.y * 128;
    const int n0 = blockIdx.x * BN;
    if (SKIP == 1 && (m0 + n0 + 127 + BN - 1 < SS - 1)) return;
    if (SKIP == 2 && (n0 >= m0 + 128)) return;

    extern __shared__ char dynsmem[];
    const uint32_t sbase = smem_u32(dynsmem);
    const int tid  = threadIdx.x;
    const int lane = tid & 31;
    const int warp = tid >> 5;
    const int wm = warp & 3;
    const int wn = warp >> 2;

    const int z  = blockIdx.z;
    const int zb = z / zdiv;
    const int zh = z % zdiv;
    Ahi += (size_t)zb * sA1 + (size_t)zh * sA2;
    Alo += (size_t)zb * sA1 + (size_t)zh * sA2;
    Bhi += (size_t)zb * sB1 + (size_t)zh * sB2;
    Blo += (size_t)zb * sB1 + (size_t)zh * sB2;
    if (OUT == 0) C  += (size_t)zb * sC1 + (size_t)zh * sC2;
    else { Ch += (size_t)zb * sC1 + (size_t)zh * sC2;
           Cl += (size_t)zb * sC1 + (size_t)zh * sC2; }

    float acc[2][NT][4];
#pragma unroll
    for (int mt = 0; mt < 2; ++mt)
#pragma unroll
        for (int nt = 0; nt < NT; ++nt)
#pragma unroll
            for (int r = 0; r < 4; ++r) acc[mt][nt][r] = 0.f;

    const int Keff = KCAP ? min(K, m0 + 128) : K;
    const int nch  = Keff >> 5;

    auto load_stage = [&](int c) {
        const int k0c = c << 5;
        const uint32_t sb = sbase + (c & 1) * STG;
#pragma unroll
        for (int i = 0; i < 2; ++i) {
            const int u = tid + i * 256;
            const int row = u >> 2, seg = u & 3;
            const uint32_t so = sb + row * 80 + seg * 16;
            const size_t ga = (size_t)(m0 + row) * lda + k0c + seg * 8;
            cpasync16(so,       Ahi + ga);
            cpasync16(so + ABY, Alo + ga);
        }
        constexpr int BU = (BN * 4) / 256;
#pragma unroll
        for (int i = 0; i < BU; ++i) {
            const int u = tid + i * 256;
            const int row = u >> 2, seg = u & 3;
            const uint32_t so = sb + 2 * ABY + row * 80 + seg * 16;
            const size_t gb = (size_t)(n0 + row) * ldb + k0c + seg * 8;
            cpasync16(so,       Bhi + gb);
            cpasync16(so + BBY, Blo + gb);
        }
        asm volatile("cp.async.commit_group;" ::: "memory");
    };

    load_stage(0);

    const int lr  = lane & 7;
    const int sel = lane >> 3;
    const int a_row_off = lr + ((sel & 1) << 3);
    const int a_k_off   = (sel >> 1) << 3;
    const int b_n_off   = lr + ((sel >> 1) << 3);
    const int b_k_off   = (sel & 1) << 3;

    for (int c = 0; c < nch; ++c) {
        if (c + 1 < nch) {
            load_stage(c + 1);
            asm volatile("cp.async.wait_group 1;" ::: "memory");
        } else {
            asm volatile("cp.async.wait_group 0;" ::: "memory");
        }
        __syncthreads();
        const uint32_t sb = sbase + (c & 1) * STG;

#pragma unroll
        for (int ks = 0; ks < 2; ++ks) {
            const int kk = ks << 4;
            uint32_t ah[2][4], al[2][4], bb[NT][2];
#pragma unroll
            for (int mt = 0; mt < 2; ++mt) {
                const int row = wm * 32 + mt * 16 + a_row_off;
                const uint32_t ad = sb + row * 80 + (kk + a_k_off) * 2;
                ldm_x4(ad, ah[mt]);
                ldm_x4(ad + ABY, al[mt]);
            }
#pragma unroll
            for (int p = 0; p < NT / 2; ++p) {
                const int n = wn * BN2 + p * 16 + b_n_off;
                uint32_t r[4];
                ldm_x4(sb + 2 * ABY + n * 80 + (kk + b_k_off) * 2, r);
                bb[2 * p][0]     = r[0]; bb[2 * p][1]     = r[1];
                bb[2 * p + 1][0] = r[2]; bb[2 * p + 1][1] = r[3];
            }
#pragma unroll
            for (int mt = 0; mt < 2; ++mt)
#pragma unroll
                for (int nt = 0; nt < NT; ++nt)
                    mma_bf16(acc[mt][nt], ah[mt], bb[nt]);
#pragma unroll
            for (int mt = 0; mt < 2; ++mt)
#pragma unroll
                for (int nt = 0; nt < NT; ++nt)
                    mma_bf16(acc[mt][nt], al[mt], bb[nt]);
#pragma unroll
            for (int p = 0; p < NT / 2; ++p) {
                const int n = wn * BN2 + p * 16 + b_n_off;
                uint32_t r[4];
                ldm_x4(sb + 2 * ABY + BBY + n * 80 + (kk + b_k_off) * 2, r);
                bb[2 * p][0]     = r[0]; bb[2 * p][1]     = r[1];
                bb[2 * p + 1][0] = r[2]; bb[2 * p + 1][1] = r[3];
            }
#pragma unroll
            for (int mt = 0; mt < 2; ++mt)
#pragma unroll
                for (int nt = 0; nt < NT; ++nt)
                    mma_bf16(acc[mt][nt], ah[mt], bb[nt]);
        }
        __syncthreads();
    }

    const int rbase = m0 + wm * 32 + (lane >> 2);
    const int cbase = n0 + wn * BN2 + 2 * (lane & 3);
    __nv_bfloat16* tsh = (__nv_bfloat16*)dynsmem;            // OUT==2 staging
    __nv_bfloat16* tsl = (__nv_bfloat16*)(dynsmem + (size_t)BN * TP * 2);
#pragma unroll
    for (int mt = 0; mt < 2; ++mt) {
#pragma unroll
        for (int nt = 0; nt < NT; ++nt) {
            const int col = cbase + nt * 8;
            float b0v = 0.f, b1v = 0.f;
            if (bias) { b0v = bias[col]; b1v = bias[col + 1]; }
            float v0 = acc[mt][nt][0] + b0v;
            float v1 = acc[mt][nt][1] + b1v;
            float v2 = acc[mt][nt][2] + b0v;
            float v3 = acc[mt][nt][3] + b1v;
            if (RELU) {
                v0 = fmaxf(v0, 0.f); v1 = fmaxf(v1, 0.f);
                v2 = fmaxf(v2, 0.f); v3 = fmaxf(v3, 0.f);
            }
            const int r0 = rbase + mt * 16;
            if (OUT == 0) {
                *(float2*)&C[(size_t)r0 * ldc + col]       = make_float2(v0, v1);
                *(float2*)&C[(size_t)(r0 + 8) * ldc + col] = make_float2(v2, v3);
            } else if (OUT == 1) {
                const float h0 = bf_hi(v0), h1 = bf_hi(v1);
                const float h2 = bf_hi(v2), h3 = bf_hi(v3);
                *(uint32_t*)&Ch[(size_t)r0 * ldc + col]       = pack_bf2(h0, h1);
                *(uint32_t*)&Ch[(size_t)(r0 + 8) * ldc + col] = pack_bf2(h2, h3);
                *(uint32_t*)&Cl[(size_t)r0 * ldc + col]       = pack_bf2(v0 - h0, v1 - h1);
                *(uint32_t*)&Cl[(size_t)(r0 + 8) * ldc + col] = pack_bf2(v2 - h2, v3 - h3);
            } else {  // OUT == 2: stage transposed into SMEM
                const float vv[4] = {v0, v1, v2, v3};
#pragma unroll
                for (int e = 0; e < 4; ++e) {
                    const int cc = col - n0 + (e & 1);
                    const int rr = r0 - m0 + (e >> 1) * 8;
                    const __nv_bfloat16 hb = __float2bfloat16(vv[e]);
                    tsh[cc * TP + rr] = hb;
                    tsl[cc * TP + rr] =
                        __float2bfloat16(vv[e] - __bfloat162float(hb));
                }
            }
        }
    }
    if (OUT == 2) {
        __syncthreads();
        // cooperative coalesced store: BN rows of C^T, each 128 bf16 = 16 uint4
#pragma unroll
        for (int p = 0; p < BN / 16; ++p) {
            const int idx = tid + p * 256;
            const int row = idx >> 4, seg = idx & 15;
            const uint4 vh = *(const uint4*)&tsh[row * TP + seg * 8];
            const uint4 vl = *(const uint4*)&tsl[row * TP + seg * 8];
            *(uint4*)&Ch[(size_t)(n0 + row) * ldc + m0 + seg * 8] = vh;
            *(uint4*)&Cl[(size_t)(n0 + row) * ldc + m0 + seg * 8] = vl;
        }
    }
}

// ---------------------------------------------------------------------------
// Weight transpose + bf16 hi/lo split: W[l][K][N] -> hi/lo at out + l*lstride,
// row-major [N, K]. 64x64 tiles, float2 loads, packed uint32 bf16-pair stores.
// ---------------------------------------------------------------------------
__global__ __launch_bounds__(256)
void conv_w(const float* __restrict__ W, __nv_bfloat16* __restrict__ hi,
            __nv_bfloat16* __restrict__ lo, int K, int N, long long lstride)
{
    __shared__ float t[64][65];   // [n][k]
    const int l = blockIdx.z;
    W  += (size_t)l * K * N;
    hi += (size_t)l * lstride;
    lo += (size_t)l * lstride;
    const int k0 = blockIdx.y * 64, n0 = blockIdx.x * 64;
    const int tid = threadIdx.x;
    const int tc = tid & 31;      // 2 floats per row
    const int tr = tid >> 5;      // row group
#pragma unroll
    for (int i = 0; i < 8; ++i) {
        const int kk = tr + i * 8;
        const float2 v = *(const float2*)&W[(size_t)(k0 + kk) * N + n0 + tc * 2];
        t[tc * 2][kk]     = v.x;
        t[tc * 2 + 1][kk] = v.y;
    }
    __syncthreads();
    const int kp = (tid & 31) * 2;
    const int nb = tid >> 5;
#pragma unroll
    for (int i = 0; i < 8; ++i) {
        const int n = nb + i * 8;
        const float a = t[n][kp], b = t[n][kp + 1];
        const float ha = bf_hi(a), hb = bf_hi(b);
        *(uint32_t*)&hi[(size_t)(n0 + n) * K + k0 + kp] = pack_bf2(ha, hb);
        *(uint32_t*)&lo[(size_t)(n0 + n) * K + k0 + kp] = pack_bf2(a - ha, b - hb);
    }
}

// elementwise hi/lo split (for E)
__global__ void split_act(const float* __restrict__ x, __nv_bfloat16* __restrict__ hi,
                          __nv_bfloat16* __restrict__ lo, int n4)
{
    const int i = blockIdx.x * 256 + threadIdx.x;
    if (i >= n4) return;
    const float4 v = ((const float4*)x)[i];
    const float f[4] = {v.x, v.y, v.z, v.w};
    unsigned short hh[4], ll[4];
#pragma unroll
    for (int j = 0; j < 4; j++) {
        const __nv_bfloat16 hb = __float2bfloat16(f[j]);
        const __nv_bfloat16 lb = __float2bfloat16(f[j] - __bfloat162float(hb));
        hh[j] = __bfloat16_as_ushort(hb);
        ll[j] = __bfloat16_as_ushort(lb);
    }
    ((uint2*)hi)[i] = *(const uint2*)hh;
    ((uint2*)lo)[i] = *(const uint2*)ll;
}

// build combined q|k bias [L][2048]
__global__ void concat_bias(const float* __restrict__ bq, const float* __restrict__ bk,
                            float* __restrict__ bqk)
{
    const int i = blockIdx.x * 256 + threadIdx.x;
    if (i >= LL * QKW) return;
    const int l = i >> 11, c = i & (QKW - 1);
    bqk[i] = (c < DD) ? bq[l * DD + c] : bk[l * DD + c - DD];
}

// ---------------------------------------------------------------------------
// Sinusoid rate + embedding (writes split bf16 directly)
// ---------------------------------------------------------------------------
__global__ void rate_kernel(float* __restrict__ rate)
{
    const int d = blockIdx.x * 256 + threadIdx.x;
    if (d >= DD) return;
    const double LN1E4 = 9.210340371976184;
    const int par = d & 1;
    const float r1 = (float)exp(-LN1E4 * (double)d   / 1024.0);
    const float r2 = (float)exp( LN1E4 * (double)par / 1024.0);
    rate[d] = r1 * r2;
}

__global__ void embed_split(const int* __restrict__ x,
                            const float* __restrict__ emb,
                            const float* __restrict__ rate,
                            __nv_bfloat16* __restrict__ oh,
                            __nv_bfloat16* __restrict__ ol)
{
    const int bs = blockIdx.x;
    const int s  = bs & (SS - 1);
    const int tok = x[bs];
    const float* e = emb + (size_t)tok * DD;
    for (int d = threadIdx.x; d < DD; d += blockDim.x) {
        const int par = d & 1;
        const float ph = (float)s * rate[d] + 1.5707964f * (float)par;
        const float v = e[d] * 32.0f + sinf(ph);
        const __nv_bfloat16 hb = __float2bfloat16(v);
        oh[(size_t)bs * DD + d] = hb;
        ol[(size_t)bs * DD + d] = __float2bfloat16(v - __bfloat162float(hb));
    }
}

// ---------------------------------------------------------------------------
// Fused Srel gather + scale + masks + softmax; writes SPLIT bf16 aw.
// Zero-pads each row out to the next 256 boundary (AV reads <=128 boundary).
// ---------------------------------------------------------------------------
__global__ __launch_bounds__(256)
void attn_softmax(const float* __restrict__ lg, const float* __restrict__ qe,
                  const int* __restrict__ x,
                  __nv_bfloat16* __restrict__ awh, __nv_bfloat16* __restrict__ awl)
{
    const int i  = blockIdx.x;
    const int bh = blockIdx.y;
    const int b  = bh >> 4;
    const float* row  = lg + (size_t)bh * SS * SS + (size_t)i * SS;
    const float* qrow = qe + (size_t)bh * SS * SS + (size_t)i * SS;
    __nv_bfloat16* oh = awh + (size_t)bh * SS * SS + (size_t)i * SS;
    __nv_bfloat16* ol = awl + (size_t)bh * SS * SS + (size_t)i * SS;
    const int* xb = x + b * SS;
    const int t = threadIdx.x;
    const int nch = (i >> 8) + 1;

    float vals[4];
    float mx = -1e30f;
    for (int c = 0; c < nch; c++) {
        const int j = c * 256 + t;
        float vv = -1e30f;
        if (j <= i) {
            vv = (row[j] + qrow[SS - 1 - i + j]) * ATT_SCALE;
            if (xb[j] == 0) vv -= 1e9f;
        }
        vals[c] = vv;
        mx = fmaxf(mx, vv);
    }
    __shared__ float sh[8];
#pragma unroll
    for (int o = 16; o > 0; o >>= 1) mx = fmaxf(mx, __shfl_xor_sync(0xffffffffu, mx, o));
    if ((t & 31) == 0) sh[t >> 5] = mx;
    __syncthreads();
    mx = sh[0];
#pragma unroll
    for (int w = 1; w < 8; w++) mx = fmaxf(mx, sh[w]);

    float s = 0.f;
    for (int c = 0; c < nch; c++) { vals[c] = __expf(vals[c] - mx); s += vals[c]; }
#pragma unroll
    for (int o = 16; o > 0; o >>= 1) s += __shfl_xor_sync(0xffffffffu, s, o);
    __syncthreads();
    if ((t & 31) == 0) sh[t >> 5] = s;
    __syncthreads();
    s = 0.f;
#pragma unroll
    for (int w = 0; w < 8; w++) s += sh[w];
    const float inv = 1.f / s;
    for (int c = 0; c < nch; c++) {
        const float p = vals[c] * inv;
        const __nv_bfloat16 hb = __float2bfloat16(p);
        oh[c * 256 + t] = hb;
        ol[c * 256 + t] = __float2bfloat16(p - __bfloat162float(hb));
    }
}

// ---------------------------------------------------------------------------
// LayerNorm over last dim (1024); reads fp32, writes SPLIT bf16.
// ---------------------------------------------------------------------------
__global__ __launch_bounds__(256)
void ln_split(const float* __restrict__ xin, const float* __restrict__ g,
              const float* __restrict__ be,
              __nv_bfloat16* __restrict__ oh, __nv_bfloat16* __restrict__ ol)
{
    const int row = blockIdx.x;
    const float* p = xin + (size_t)row * DD;
    const int t = threadIdx.x;
    float v[4];
    float s = 0.f, s2 = 0.f;
#pragma unroll
    for (int c = 0; c < 4; c++) {
        v[c] = p[t + c * 256];
        s += v[c];
        s2 += v[c] * v[c];
    }
    __shared__ float sh1[8], sh2[8];
#pragma unroll
    for (int o = 16; o > 0; o >>= 1) {
        s  += __shfl_xor_sync(0xffffffffu, s,  o);
        s2 += __shfl_xor_sync(0xffffffffu, s2, o);
    }
    if ((t & 31) == 0) { sh1[t >> 5] = s; sh2[t >> 5] = s2; }
    __syncthreads();
    s = 0.f; s2 = 0.f;
#pragma unroll
    for (int w = 0; w < 8; w++) { s += sh1[w]; s2 += sh2[w]; }
    const float mu  = s  * (1.f / DD);
    const float var = s2 * (1.f / DD) - mu * mu;
    const float inv = rsqrtf(var + 1e-6f);
#pragma unroll
    for (int c = 0; c < 4; c++) {
        const int d = t + c * 256;
        const float o = (v[c] - mu) * inv * g[d] + be[d];
        const __nv_bfloat16 hb = __float2bfloat16(o);
        oh[(size_t)row * DD + d] = hb;
        ol[(size_t)row * DD + d] = __float2bfloat16(o - __bfloat162float(hb));
    }
}

// ---------------------------------------------------------------------------
// Host side
// ---------------------------------------------------------------------------
using bf16 = __nv_bfloat16;

template<int BN, int SKIP, bool KCAP, int OUT, bool RELU>
static void run_mma(const bf16* ah, const bf16* al, const bf16* bh, const bf16* bl,
                    const float* bias, float* C, bf16* Ch, bf16* Cl,
                    int M, int N, int K, int lda, int ldb, int ldc,
                    int batch, int zdiv,
                    long long sA1, long long sA2,
                    long long sB1, long long sB2,
                    long long sC1, long long sC2)
{
    constexpr int STG = 2 * 10240 + 2 * BN * 80;
    static bool init = false;
    if (!init) {
        cudaFuncSetAttribute(gemm_mma<BN, SKIP, KCAP, OUT, RELU>,
                             cudaFuncAttributeMaxDynamicSharedMemorySize, 2 * STG);
        init = true;
    }
    dim3 grid(N / BN, M / 128, batch);
    gemm_mma<BN, SKIP, KCAP, OUT, RELU><<<grid, 256, 2 * STG>>>(
        ah, al, bh, bl, bias, C, Ch, Cl, K, lda, ldb, ldc,
        zdiv, sA1, sA2, sB1, sB2, sC1, sC2);
}

extern "C" void kernel_launch(void* const* d_in, const int* in_sizes, int n_in,
                              void* d_out, int out_size)
{
    const int*   x   = (const int*)  d_in[0];
    const float* emb = (const float*)d_in[1];
    const float* Wq  = (const float*)d_in[2];
    const float* bq  = (const float*)d_in[3];
    const float* Wk  = (const float*)d_in[4];
    const float* bk  = (const float*)d_in[5];
    const float* Wv  = (const float*)d_in[6];
    const float* bv  = (const float*)d_in[7];
    const float* Wo  = (const float*)d_in[8];
    const float* bo  = (const float*)d_in[9];
    const float* W1  = (const float*)d_in[10];
    const float* b1  = (const float*)d_in[11];
    const float* W2  = (const float*)d_in[12];
    const float* b2  = (const float*)d_in[13];
    const float* g1  = (const float*)d_in[14];
    const float* be1 = (const float*)d_in[15];
    const float* g2  = (const float*)d_in[16];
    const float* be2 = (const float*)d_in[17];
    const float* E   = (const float*)d_in[18];
    const float* Wf  = (const float*)d_in[19];
    const float* bf  = (const float*)d_in[20];
    float* out = (float*)d_out;

    float *t1, *h2, *qe, *lg, *rate, *bqk;
    cudaGetSymbolAddress((void**)&t1, g_t1);
    cudaGetSymbolAddress((void**)&h2, g_h2);
    cudaGetSymbolAddress((void**)&qe, g_qe);
    cudaGetSymbolAddress((void**)&lg, g_lg);
    cudaGetSymbolAddress((void**)&rate, g_rate);
    cudaGetSymbolAddress((void**)&bqk, g_bqk);

    bf16 *xh, *xl, *qkh, *qkl, *vth, *vtl, *ath, *atl, *ffh, *ffl;
    bf16 *awh, *awl, *eh, *el;
    cudaGetSymbolAddress((void**)&xh,  g_xh);  cudaGetSymbolAddress((void**)&xl,  g_xl);
    cudaGetSymbolAddress((void**)&qkh, g_qkh); cudaGetSymbolAddress((void**)&qkl, g_qkl);
    cudaGetSymbolAddress((void**)&vth, g_vth); cudaGetSymbolAddress((void**)&vtl, g_vtl);
    cudaGetSymbolAddress((void**)&ath, g_ath); cudaGetSymbolAddress((void**)&atl, g_atl);
    cudaGetSymbolAddress((void**)&ffh, g_ffh); cudaGetSymbolAddress((void**)&ffl, g_ffl);
    cudaGetSymbolAddress((void**)&awh, g_awh); cudaGetSymbolAddress((void**)&awl, g_awl);
    cudaGetSymbolAddress((void**)&eh,  g_eh);  cudaGetSymbolAddress((void**)&el,  g_el);

    bf16 *wqkh, *wqkl, *wvh, *wvl, *woh, *wol;
    bf16 *w1h, *w1l, *w2h, *w2l, *wfh, *wfl;
    cudaGetSymbolAddress((void**)&wqkh, g_wqk_h); cudaGetSymbolAddress((void**)&wqkl, g_wqk_l);
    cudaGetSymbolAddress((void**)&wvh, g_wv_h); cudaGetSymbolAddress((void**)&wvl, g_wv_l);
    cudaGetSymbolAddress((void**)&woh, g_wo_h); cudaGetSymbolAddress((void**)&wol, g_wo_l);
    cudaGetSymbolAddress((void**)&w1h, g_w1_h); cudaGetSymbolAddress((void**)&w1l, g_w1_l);
    cudaGetSymbolAddress((void**)&w2h, g_w2_h); cudaGetSymbolAddress((void**)&w2l, g_w2_l);
    cudaGetSymbolAddress((void**)&wfh, g_wf_h); cudaGetSymbolAddress((void**)&wfl, g_wf_l);

    const int M = BB * SS;  // 2048
    const long long sSD  = (long long)SS * DD;
    const long long sSQK = (long long)SS * QKW;
    const long long sHSS = (long long)HH * SS * SS;
    const long long sSSq = (long long)SS * SS;
    const long long sDS  = (long long)DD * SS;
    const long long wQKL = (long long)QKW * DD;     // per-layer qk weight stride

    // weight + E conversion
    {
        // Wq -> rows 0..1023 of combined weight; Wk -> rows 1024..2047
        conv_w<<<dim3(DD / 64, DD / 64, LL), 256>>>(Wq, wqkh, wqkl, DD, DD, wQKL);
        conv_w<<<dim3(DD / 64, DD / 64, LL), 256>>>(Wk, wqkh + (size_t)DD * DD,
                                                    wqkl + (size_t)DD * DD, DD, DD, wQKL);
        conv_w<<<dim3(DD / 64, DD / 64, LL), 256>>>(Wv, wvh, wvl, DD, DD, (long long)DD * DD);
        conv_w<<<dim3(DD / 64, DD / 64, LL), 256>>>(Wo, woh, wol, DD, DD, (long long)DD * DD);
        conv_w<<<dim3(DF / 64, DD / 64, LL), 256>>>(W1, w1h, w1l, DD, DF, (long long)DF * DD);
        conv_w<<<dim3(DD / 64, DF / 64, LL), 256>>>(W2, w2h, w2l, DF, DD, (long long)DD * DF);
        conv_w<<<dim3(VV / 64, DD / 64, 1),  256>>>(Wf, wfh, wfl, DD, VV, (long long)VV * DD);
        split_act<<<(LL * SS * HD / 4 + 255) / 256, 256>>>(E, eh, el, LL * SS * HD / 4);
        concat_bias<<<(LL * QKW + 255) / 256, 256>>>(bq, bk, bqk);
    }

    rate_kernel<<<4, 256>>>(rate);
    embed_split<<<BB * SS, 256>>>(x, emb, rate, xh, xl);

    for (int l = 0; l < LL; l++) {
        const size_t wdd = (size_t)l * DD * DD;
        const size_t wdf = (size_t)l * DF * DD;
        const bf16* ehl = eh + (size_t)l * SS * HD;
        const bf16* ell = el + (size_t)l * SS * HD;

        // combined Q|K projection: N=2048 -> grid 256 CTAs
        run_mma<128, 0, false, 1, false>(xh, xl, wqkh + (size_t)l * wQKL,
                                         wqkl + (size_t)l * wQKL, bqk + l * QKW,
                                         nullptr, qkh, qkl, M, QKW, DD, DD, DD, QKW,
                                         1, 1, 0, 0, 0, 0, 0, 0);
        // V projection (split-transposed per batch, smem-staged stores)
        run_mma<128, 0, false, 2, false>(xh, xl, wvh + wdd, wvl + wdd, bv + l * DD,
                                         nullptr, vth, vtl, SS, DD, DD, DD, DD, SS,
                                         BB, 1, sSD, 0, 0, 0, sDS, 0);

        // QE = q @ E^T (anti-diagonal tiles only); q rows have stride QKW
        run_mma<128, 1, false, 0, false>(qkh, qkl, ehl, ell, nullptr, qe, nullptr, nullptr,
                                         SS, SS, HD, QKW, HD, SS, BB * HH, HH,
                                         sSQK, HD, 0, 0, sHSS, sSSq);
        // QK^T (causal tiles only); k part lives at column offset DD
        run_mma<128, 2, false, 0, false>(qkh, qkl, qkh + DD, qkl + DD, nullptr, lg,
                                         nullptr, nullptr,
                                         SS, SS, HD, QKW, QKW, SS, BB * HH, HH,
                                         sSQK, HD, sSQK, HD, sHSS, sSSq);

        // fused skew + masks + softmax -> split bf16 aw
        attn_softmax<<<dim3(SS, BB * HH), 256>>>(lg, qe, x, awh, awl);

        // attn = aw @ v (K capped, split output into ath/atl)
        run_mma<64, 0, true, 1, false>(awh, awl, vth, vtl, nullptr,
                                       nullptr, ath, atl, SS, HD, SS, SS, SS, DD,
                                       BB * HH, HH, sHSS, sSSq,
                                       sDS, (long long)HD * SS, sSD, HD);

        // Wo + LN1
        run_mma<128, 0, false, 0, false>(ath, atl, woh + wdd, wol + wdd, bo + l * DD,
                                         t1, nullptr, nullptr, M, DD, DD, DD, DD, DD,
                                         1, 1, 0, 0, 0, 0, 0, 0);
        ln_split<<<BB * SS, 256>>>(t1, g1 + l * DD, be1 + l * DD, xh, xl);

        // FFN (W1 with BN=64 -> 128 CTAs)
        run_mma<64, 0, false, 1, true>(xh, xl, w1h + wdf, w1l + wdf, b1 + l * DF,
                                       nullptr, ffh, ffl, M, DF, DD, DD, DD, DF,
                                       1, 1, 0, 0, 0, 0, 0, 0);
        run_mma<128, 0, false, 0, false>(ffh, ffl, w2h + wdf, w2l + wdf, b2 + l * DD,
                                         h2, nullptr, nullptr, M, DD, DF, DF, DF, DD,
                                         1, 1, 0, 0, 0, 0, 0, 0);
        ln_split<<<BB * SS, 256>>>(h2, g2 + l * DD, be2 + l * DD, xh, xl);
    }

    // final projection to vocab (BN=64 -> 64 CTAs)
    run_mma<64, 0, false, 0, false>(xh, xl, wfh, wfl, bf, out, nullptr, nullptr,
                                    M, VV, DD, DD, DD, VV, 1, 1, 0, 0, 0, 0, 0, 0);
}

// round 10
// speedup vs baseline: 1.6337x; 1.0401x over previous
#include <cuda_runtime.h>
#include <cuda_bf16.h>
#include <math.h>
#include <stdint.h>

// ---------------------------------------------------------------------------
// Problem constants
// ---------------------------------------------------------------------------
constexpr int BB = 2;     // batch
constexpr int SS = 1024;  // seq len
constexpr int DD = 1024;  // model dim
constexpr int HH = 16;    // heads
constexpr int LL = 6;     // layers
constexpr int VV = 256;   // vocab
constexpr int HD = 64;    // head dim
constexpr int DF = 512;   // ffn dim
constexpr int QKW = 2048; // combined q|k width
constexpr float ATT_SCALE = 0.125f;  // 1/sqrt(64)

// ---------------------------------------------------------------------------
// Scratch (static device globals -- no allocations allowed)
// ---------------------------------------------------------------------------
__device__ float g_t1 [BB * SS * DD];                 // pre-LN fp32
__device__ float g_h2 [BB * SS * DD];                 // pre-LN fp32
__device__ float g_qe [(size_t)BB * HH * SS * SS];    // 134 MB
__device__ float g_lg [(size_t)BB * HH * SS * SS];    // 134 MB
__device__ float g_rate[DD];
__device__ float g_bqk [LL * QKW];

// split activation buffers
__device__ __nv_bfloat16 g_xh [BB * SS * DD], g_xl [BB * SS * DD];  // layer in
__device__ __nv_bfloat16 g_qkh[BB * SS * QKW], g_qkl[BB * SS * QKW]; // q|k
__device__ __nv_bfloat16 g_vth[BB * DD * SS], g_vtl[BB * DD * SS];  // v^T per head
__device__ __nv_bfloat16 g_ath[BB * SS * DD], g_atl[BB * SS * DD];  // attn out
__device__ __nv_bfloat16 g_ffh[BB * SS * DF], g_ffl[BB * SS * DF];
__device__ __nv_bfloat16 g_awh[(size_t)BB * HH * SS * SS];          // 67 MB
__device__ __nv_bfloat16 g_awl[(size_t)BB * HH * SS * SS];          // 67 MB
__device__ __nv_bfloat16 g_eh [LL * SS * HD], g_el [LL * SS * HD];

// bf16 split weight buffers ([N, K] transposed, hi/lo)
__device__ __nv_bfloat16 g_wqk_h[LL * QKW * DD], g_wqk_l[LL * QKW * DD];
__device__ __nv_bfloat16 g_wv_h[LL * DD * DD],  g_wv_l[LL * DD * DD];
__device__ __nv_bfloat16 g_wo_h[LL * DD * DD],  g_wo_l[LL * DD * DD];
__device__ __nv_bfloat16 g_w1_h[LL * DF * DD],  g_w1_l[LL * DF * DD];
__device__ __nv_bfloat16 g_w2_h[LL * DD * DF],  g_w2_l[LL * DD * DF];
__device__ __nv_bfloat16 g_wf_h[VV * DD],       g_wf_l[VV * DD];

// ---------------------------------------------------------------------------
// PTX helpers (mma.sync / ldmatrix / cp.async -- standard ISA, sm_80+)
// ---------------------------------------------------------------------------
__device__ __forceinline__ uint32_t smem_u32(const void* p) {
    uint32_t a;
    asm("{ .reg .u64 t; cvta.to.shared.u64 t, %1; cvt.u32.u64 %0, t; }"
        : "=r"(a) : "l"(p));
    return a;
}
__device__ __forceinline__ void cpasync16(uint32_t s, const void* g) {
    asm volatile("cp.async.ca.shared.global [%0], [%1], 16;"
                 :: "r"(s), "l"(g) : "memory");
}
__device__ __forceinline__ void ldm_x4(uint32_t a, uint32_t r[4]) {
    asm volatile("ldmatrix.sync.aligned.m8n8.x4.shared.b16 {%0,%1,%2,%3}, [%4];"
                 : "=r"(r[0]), "=r"(r[1]), "=r"(r[2]), "=r"(r[3]) : "r"(a));
}
__device__ __forceinline__ void mma_bf16(float c[4], const uint32_t a[4],
                                         const uint32_t b[2]) {
    asm volatile("mma.sync.aligned.m16n8k16.row.col.f32.bf16.bf16.f32 "
                 "{%0,%1,%2,%3}, {%4,%5,%6,%7}, {%8,%9}, {%0,%1,%2,%3};"
                 : "+f"(c[0]), "+f"(c[1]), "+f"(c[2]), "+f"(c[3])
                 : "r"(a[0]), "r"(a[1]), "r"(a[2]), "r"(a[3]),
                   "r"(b[0]), "r"(b[1]));
}
__device__ __forceinline__ uint32_t pack_bf2(float a, float b) {
    __nv_bfloat162 t = __floats2bfloat162_rn(a, b);
    return *(uint32_t*)&t;
}
__device__ __forceinline__ float bf_hi(float v) {
    return __bfloat162float(__float2bfloat16(v));
}

// ---------------------------------------------------------------------------
// Unified batched split-bf16 HMMA GEMM (unchanged from R7)
// ---------------------------------------------------------------------------
template<int BN, int SKIP, bool KCAP, int OUT, bool RELU>
__global__ __launch_bounds__(256, 2)
void gemm_mma(const __nv_bfloat16* __restrict__ Ahi, const __nv_bfloat16* __restrict__ Alo,
              const __nv_bfloat16* __restrict__ Bhi, const __nv_bfloat16* __restrict__ Blo,
              const float* __restrict__ bias, float* __restrict__ C,
              __nv_bfloat16* __restrict__ Ch, __nv_bfloat16* __restrict__ Cl,
              int K, int lda, int ldb, int ldc, int zdiv,
              long long sA1, long long sA2,
              long long sB1, long long sB2,
              long long sC1, long long sC2)
{
    constexpr int ABY = 10240;            // 128 rows * 80B
    constexpr int BBY = BN * 80;
    constexpr int STG = 2 * ABY + 2 * BBY;
    constexpr int NT  = BN / 16;
    constexpr int BN2 = BN / 2;
    constexpr int TP  = 136;              // transpose-stage pitch (bf16 elems)

    const int m0 = blockIdx.y * 128;
    const int n0 = blockIdx.x * BN;
    if (SKIP == 1 && (m0 + n0 + 127 + BN - 1 < SS - 1)) return;
    if (SKIP == 2 && (n0 >= m0 + 128)) return;

    extern __shared__ char dynsmem[];
    const uint32_t sbase = smem_u32(dynsmem);
    const int tid  = threadIdx.x;
    const int lane = tid & 31;
    const int warp = tid >> 5;
    const int wm = warp & 3;
    const int wn = warp >> 2;

    const int z  = blockIdx.z;
    const int zb = z / zdiv;
    const int zh = z % zdiv;
    Ahi += (size_t)zb * sA1 + (size_t)zh * sA2;
    Alo += (size_t)zb * sA1 + (size_t)zh * sA2;
    Bhi += (size_t)zb * sB1 + (size_t)zh * sB2;
    Blo += (size_t)zb * sB1 + (size_t)zh * sB2;
    if (OUT == 0) C  += (size_t)zb * sC1 + (size_t)zh * sC2;
    else { Ch += (size_t)zb * sC1 + (size_t)zh * sC2;
           Cl += (size_t)zb * sC1 + (size_t)zh * sC2; }

    float acc[2][NT][4];
#pragma unroll
    for (int mt = 0; mt < 2; ++mt)
#pragma unroll
        for (int nt = 0; nt < NT; ++nt)
#pragma unroll
            for (int r = 0; r < 4; ++r) acc[mt][nt][r] = 0.f;

    const int Keff = KCAP ? min(K, m0 + 128) : K;
    const int nch  = Keff >> 5;

    auto load_stage = [&](int c) {
        const int k0c = c << 5;
        const uint32_t sb = sbase + (c & 1) * STG;
#pragma unroll
        for (int i = 0; i < 2; ++i) {
            const int u = tid + i * 256;
            const int row = u >> 2, seg = u & 3;
            const uint32_t so = sb + row * 80 + seg * 16;
            const size_t ga = (size_t)(m0 + row) * lda + k0c + seg * 8;
            cpasync16(so,       Ahi + ga);
            cpasync16(so + ABY, Alo + ga);
        }
        constexpr int BU = (BN * 4) / 256;
#pragma unroll
        for (int i = 0; i < BU; ++i) {
            const int u = tid + i * 256;
            const int row = u >> 2, seg = u & 3;
            const uint32_t so = sb + 2 * ABY + row * 80 + seg * 16;
            const size_t gb = (size_t)(n0 + row) * ldb + k0c + seg * 8;
            cpasync16(so,       Bhi + gb);
            cpasync16(so + BBY, Blo + gb);
        }
        asm volatile("cp.async.commit_group;" ::: "memory");
    };

    load_stage(0);

    const int lr  = lane & 7;
    const int sel = lane >> 3;
    const int a_row_off = lr + ((sel & 1) << 3);
    const int a_k_off   = (sel >> 1) << 3;
    const int b_n_off   = lr + ((sel >> 1) << 3);
    const int b_k_off   = (sel & 1) << 3;

    for (int c = 0; c < nch; ++c) {
        if (c + 1 < nch) {
            load_stage(c + 1);
            asm volatile("cp.async.wait_group 1;" ::: "memory");
        } else {
            asm volatile("cp.async.wait_group 0;" ::: "memory");
        }
        __syncthreads();
        const uint32_t sb = sbase + (c & 1) * STG;

#pragma unroll
        for (int ks = 0; ks < 2; ++ks) {
            const int kk = ks << 4;
            uint32_t ah[2][4], al[2][4], bb[NT][2];
#pragma unroll
            for (int mt = 0; mt < 2; ++mt) {
                const int row = wm * 32 + mt * 16 + a_row_off;
                const uint32_t ad = sb + row * 80 + (kk + a_k_off) * 2;
                ldm_x4(ad, ah[mt]);
                ldm_x4(ad + ABY, al[mt]);
            }
#pragma unroll
            for (int p = 0; p < NT / 2; ++p) {
                const int n = wn * BN2 + p * 16 + b_n_off;
                uint32_t r[4];
                ldm_x4(sb + 2 * ABY + n * 80 + (kk + b_k_off) * 2, r);
                bb[2 * p][0]     = r[0]; bb[2 * p][1]     = r[1];
                bb[2 * p + 1][0] = r[2]; bb[2 * p + 1][1] = r[3];
            }
#pragma unroll
            for (int mt = 0; mt < 2; ++mt)
#pragma unroll
                for (int nt = 0; nt < NT; ++nt)
                    mma_bf16(acc[mt][nt], ah[mt], bb[nt]);
#pragma unroll
            for (int mt = 0; mt < 2; ++mt)
#pragma unroll
                for (int nt = 0; nt < NT; ++nt)
                    mma_bf16(acc[mt][nt], al[mt], bb[nt]);
#pragma unroll
            for (int p = 0; p < NT / 2; ++p) {
                const int n = wn * BN2 + p * 16 + b_n_off;
                uint32_t r[4];
                ldm_x4(sb + 2 * ABY + BBY + n * 80 + (kk + b_k_off) * 2, r);
                bb[2 * p][0]     = r[0]; bb[2 * p][1]     = r[1];
                bb[2 * p + 1][0] = r[2]; bb[2 * p + 1][1] = r[3];
            }
#pragma unroll
            for (int mt = 0; mt < 2; ++mt)
#pragma unroll
                for (int nt = 0; nt < NT; ++nt)
                    mma_bf16(acc[mt][nt], ah[mt], bb[nt]);
        }
        __syncthreads();
    }

    const int rbase = m0 + wm * 32 + (lane >> 2);
    const int cbase = n0 + wn * BN2 + 2 * (lane & 3);
    __nv_bfloat16* tsh = (__nv_bfloat16*)dynsmem;            // OUT==2 staging
    __nv_bfloat16* tsl = (__nv_bfloat16*)(dynsmem + (size_t)BN * TP * 2);
#pragma unroll
    for (int mt = 0; mt < 2; ++mt) {
#pragma unroll
        for (int nt = 0; nt < NT; ++nt) {
            const int col = cbase + nt * 8;
            float b0v = 0.f, b1v = 0.f;
            if (bias) { b0v = bias[col]; b1v = bias[col + 1]; }
            float v0 = acc[mt][nt][0] + b0v;
            float v1 = acc[mt][nt][1] + b1v;
            float v2 = acc[mt][nt][2] + b0v;
            float v3 = acc[mt][nt][3] + b1v;
            if (RELU) {
                v0 = fmaxf(v0, 0.f); v1 = fmaxf(v1, 0.f);
                v2 = fmaxf(v2, 0.f); v3 = fmaxf(v3, 0.f);
            }
            const int r0 = rbase + mt * 16;
            if (OUT == 0) {
                *(float2*)&C[(size_t)r0 * ldc + col]       = make_float2(v0, v1);
                *(float2*)&C[(size_t)(r0 + 8) * ldc + col] = make_float2(v2, v3);
            } else if (OUT == 1) {
                const float h0 = bf_hi(v0), h1 = bf_hi(v1);
                const float h2 = bf_hi(v2), h3 = bf_hi(v3);
                *(uint32_t*)&Ch[(size_t)r0 * ldc + col]       = pack_bf2(h0, h1);
                *(uint32_t*)&Ch[(size_t)(r0 + 8) * ldc + col] = pack_bf2(h2, h3);
                *(uint32_t*)&Cl[(size_t)r0 * ldc + col]       = pack_bf2(v0 - h0, v1 - h1);
                *(uint32_t*)&Cl[(size_t)(r0 + 8) * ldc + col] = pack_bf2(v2 - h2, v3 - h3);
            } else {  // OUT == 2: stage transposed into SMEM
                const float vv[4] = {v0, v1, v2, v3};
#pragma unroll
                for (int e = 0; e < 4; ++e) {
                    const int cc = col - n0 + (e & 1);
                    const int rr = r0 - m0 + (e >> 1) * 8;
                    const __nv_bfloat16 hb = __float2bfloat16(vv[e]);
                    tsh[cc * TP + rr] = hb;
                    tsl[cc * TP + rr] =
                        __float2bfloat16(vv[e] - __bfloat162float(hb));
                }
            }
        }
    }
    if (OUT == 2) {
        __syncthreads();
#pragma unroll
        for (int p = 0; p < BN / 16; ++p) {
            const int idx = tid + p * 256;
            const int row = idx >> 4, seg = idx & 15;
            const uint4 vh = *(const uint4*)&tsh[row * TP + seg * 8];
            const uint4 vl = *(const uint4*)&tsl[row * TP + seg * 8];
            *(uint4*)&Ch[(size_t)(n0 + row) * ldc + m0 + seg * 8] = vh;
            *(uint4*)&Cl[(size_t)(n0 + row) * ldc + m0 + seg * 8] = vl;
        }
    }
}

// ---------------------------------------------------------------------------
// Weight transpose + bf16 hi/lo split (64x64 tiles, packed stores)
// ---------------------------------------------------------------------------
__global__ __launch_bounds__(256)
void conv_w(const float* __restrict__ W, __nv_bfloat16* __restrict__ hi,
            __nv_bfloat16* __restrict__ lo, int K, int N, long long lstride)
{
    __shared__ float t[64][65];   // [n][k]
    const int l = blockIdx.z;
    W  += (size_t)l * K * N;
    hi += (size_t)l * lstride;
    lo += (size_t)l * lstride;
    const int k0 = blockIdx.y * 64, n0 = blockIdx.x * 64;
    const int tid = threadIdx.x;
    const int tc = tid & 31;
    const int tr = tid >> 5;
#pragma unroll
    for (int i = 0; i < 8; ++i) {
        const int kk = tr + i * 8;
        const float2 v = *(const float2*)&W[(size_t)(k0 + kk) * N + n0 + tc * 2];
        t[tc * 2][kk]     = v.x;
        t[tc * 2 + 1][kk] = v.y;
    }
    __syncthreads();
    const int kp = (tid & 31) * 2;
    const int nb = tid >> 5;
#pragma unroll
    for (int i = 0; i < 8; ++i) {
        const int n = nb + i * 8;
        const float a = t[n][kp], b = t[n][kp + 1];
        const float ha = bf_hi(a), hb = bf_hi(b);
        *(uint32_t*)&hi[(size_t)(n0 + n) * K + k0 + kp] = pack_bf2(ha, hb);
        *(uint32_t*)&lo[(size_t)(n0 + n) * K + k0 + kp] = pack_bf2(a - ha, b - hb);
    }
}

// elementwise hi/lo split (for E)
__global__ void split_act(const float* __restrict__ x, __nv_bfloat16* __restrict__ hi,
                          __nv_bfloat16* __restrict__ lo, int n4)
{
    const int i = blockIdx.x * 256 + threadIdx.x;
    if (i >= n4) return;
    const float4 v = ((const float4*)x)[i];
    const float f[4] = {v.x, v.y, v.z, v.w};
    unsigned short hh[4], ll[4];
#pragma unroll
    for (int j = 0; j < 4; j++) {
        const __nv_bfloat16 hb = __float2bfloat16(f[j]);
        const __nv_bfloat16 lb = __float2bfloat16(f[j] - __bfloat162float(hb));
        hh[j] = __bfloat16_as_ushort(hb);
        ll[j] = __bfloat16_as_ushort(lb);
    }
    ((uint2*)hi)[i] = *(const uint2*)hh;
    ((uint2*)lo)[i] = *(const uint2*)ll;
}

// build combined q|k bias [L][2048]
__global__ void concat_bias(const float* __restrict__ bq, const float* __restrict__ bk,
                            float* __restrict__ bqk)
{
    const int i = blockIdx.x * 256 + threadIdx.x;
    if (i >= LL * QKW) return;
    const int l = i >> 11, c = i & (QKW - 1);
    bqk[i] = (c < DD) ? bq[l * DD + c] : bk[l * DD + c - DD];
}

// ---------------------------------------------------------------------------
// Sinusoid rate + embedding (writes split bf16 directly)
// ---------------------------------------------------------------------------
__global__ void rate_kernel(float* __restrict__ rate)
{
    const int d = blockIdx.x * 256 + threadIdx.x;
    if (d >= DD) return;
    const double LN1E4 = 9.210340371976184;
    const int par = d & 1;
    const float r1 = (float)exp(-LN1E4 * (double)d   / 1024.0);
    const float r2 = (float)exp( LN1E4 * (double)par / 1024.0);
    rate[d] = r1 * r2;
}

__global__ void embed_split(const int* __restrict__ x,
                            const float* __restrict__ emb,
                            const float* __restrict__ rate,
                            __nv_bfloat16* __restrict__ oh,
                            __nv_bfloat16* __restrict__ ol)
{
    const int bs = blockIdx.x;
    const int s  = bs & (SS - 1);
    const int tok = x[bs];
    const float* e = emb + (size_t)tok * DD;
    for (int d = threadIdx.x; d < DD; d += blockDim.x) {
        const int par = d & 1;
        const float ph = (float)s * rate[d] + 1.5707964f * (float)par;
        const float v = e[d] * 32.0f + sinf(ph);
        const __nv_bfloat16 hb = __float2bfloat16(v);
        oh[(size_t)bs * DD + d] = hb;
        ol[(size_t)bs * DD + d] = __float2bfloat16(v - __bfloat162float(hb));
    }
}

// ---------------------------------------------------------------------------
// Fused Srel gather + scale + masks + softmax; writes SPLIT bf16 aw.
// ---------------------------------------------------------------------------
__global__ __launch_bounds__(256)
void attn_softmax(const float* __restrict__ lg, const float* __restrict__ qe,
                  const int* __restrict__ x,
                  __nv_bfloat16* __restrict__ awh, __nv_bfloat16* __restrict__ awl)
{
    const int i  = blockIdx.x;
    const int bh = blockIdx.y;
    const int b  = bh >> 4;
    const float* row  = lg + (size_t)bh * SS * SS + (size_t)i * SS;
    const float* qrow = qe + (size_t)bh * SS * SS + (size_t)i * SS;
    __nv_bfloat16* oh = awh + (size_t)bh * SS * SS + (size_t)i * SS;
    __nv_bfloat16* ol = awl + (size_t)bh * SS * SS + (size_t)i * SS;
    const int* xb = x + b * SS;
    const int t = threadIdx.x;
    const int nch = (i >> 8) + 1;

    float vals[4];
    float mx = -1e30f;
    for (int c = 0; c < nch; c++) {
        const int j = c * 256 + t;
        float vv = -1e30f;
        if (j <= i) {
            vv = (row[j] + qrow[SS - 1 - i + j]) * ATT_SCALE;
            if (xb[j] == 0) vv -= 1e9f;
        }
        vals[c] = vv;
        mx = fmaxf(mx, vv);
    }
    __shared__ float sh[8];
#pragma unroll
    for (int o = 16; o > 0; o >>= 1) mx = fmaxf(mx, __shfl_xor_sync(0xffffffffu, mx, o));
    if ((t & 31) == 0) sh[t >> 5] = mx;
    __syncthreads();
    mx = sh[0];
#pragma unroll
    for (int w = 1; w < 8; w++) mx = fmaxf(mx, sh[w]);

    float s = 0.f;
    for (int c = 0; c < nch; c++) { vals[c] = __expf(vals[c] - mx); s += vals[c]; }
#pragma unroll
    for (int o = 16; o > 0; o >>= 1) s += __shfl_xor_sync(0xffffffffu, s, o);
    __syncthreads();
    if ((t & 31) == 0) sh[t >> 5] = s;
    __syncthreads();
    s = 0.f;
#pragma unroll
    for (int w = 0; w < 8; w++) s += sh[w];
    const float inv = 1.f / s;
    for (int c = 0; c < nch; c++) {
        const float p = vals[c] * inv;
        const __nv_bfloat16 hb = __float2bfloat16(p);
        oh[c * 256 + t] = hb;
        ol[c * 256 + t] = __float2bfloat16(p - __bfloat162float(hb));
    }
}

// ---------------------------------------------------------------------------
// LayerNorm over last dim (1024); reads fp32, writes SPLIT bf16.
// ---------------------------------------------------------------------------
__global__ __launch_bounds__(256)
void ln_split(const float* __restrict__ xin, const float* __restrict__ g,
              const float* __restrict__ be,
              __nv_bfloat16* __restrict__ oh, __nv_bfloat16* __restrict__ ol)
{
    const int row = blockIdx.x;
    const float* p = xin + (size_t)row * DD;
    const int t = threadIdx.x;
    float v[4];
    float s = 0.f, s2 = 0.f;
#pragma unroll
    for (int c = 0; c < 4; c++) {
        v[c] = p[t + c * 256];
        s += v[c];
        s2 += v[c] * v[c];
    }
    __shared__ float sh1[8], sh2[8];
#pragma unroll
    for (int o = 16; o > 0; o >>= 1) {
        s  += __shfl_xor_sync(0xffffffffu, s,  o);
        s2 += __shfl_xor_sync(0xffffffffu, s2, o);
    }
    if ((t & 31) == 0) { sh1[t >> 5] = s; sh2[t >> 5] = s2; }
    __syncthreads();
    s = 0.f; s2 = 0.f;
#pragma unroll
    for (int w = 0; w < 8; w++) { s += sh1[w]; s2 += sh2[w]; }
    const float mu  = s  * (1.f / DD);
    const float var = s2 * (1.f / DD) - mu * mu;
    const float inv = rsqrtf(var + 1e-6f);
#pragma unroll
    for (int c = 0; c < 4; c++) {
        const int d = t + c * 256;
        const float o = (v[c] - mu) * inv * g[d] + be[d];
        const __nv_bfloat16 hb = __float2bfloat16(o);
        oh[(size_t)row * DD + d] = hb;
        ol[(size_t)row * DD + d] = __float2bfloat16(o - __bfloat162float(hb));
    }
}

// ---------------------------------------------------------------------------
// Host side
// ---------------------------------------------------------------------------
using bf16 = __nv_bfloat16;

template<int BN, int SKIP, bool KCAP, int OUT, bool RELU>
static void run_mma_s(cudaStream_t st,
                      const bf16* ah, const bf16* al, const bf16* bh, const bf16* bl,
                      const float* bias, float* C, bf16* Ch, bf16* Cl,
                      int M, int N, int K, int lda, int ldb, int ldc,
                      int batch, int zdiv,
                      long long sA1, long long sA2,
                      long long sB1, long long sB2,
                      long long sC1, long long sC2)
{
    constexpr int STG = 2 * 10240 + 2 * BN * 80;
    static bool init = false;
    if (!init) {
        cudaFuncSetAttribute(gemm_mma<BN, SKIP, KCAP, OUT, RELU>,
                             cudaFuncAttributeMaxDynamicSharedMemorySize, 2 * STG);
        init = true;
    }
    dim3 grid(N / BN, M / 128, batch);
    gemm_mma<BN, SKIP, KCAP, OUT, RELU><<<grid, 256, 2 * STG, st>>>(
        ah, al, bh, bl, bias, C, Ch, Cl, K, lda, ldb, ldc,
        zdiv, sA1, sA2, sB1, sB2, sC1, sC2);
}

extern "C" void kernel_launch(void* const* d_in, const int* in_sizes, int n_in,
                              void* d_out, int out_size)
{
    const int*   x   = (const int*)  d_in[0];
    const float* emb = (const float*)d_in[1];
    const float* Wq  = (const float*)d_in[2];
    const float* bq  = (const float*)d_in[3];
    const float* Wk  = (const float*)d_in[4];
    const float* bk  = (const float*)d_in[5];
    const float* Wv  = (const float*)d_in[6];
    const float* bv  = (const float*)d_in[7];
    const float* Wo  = (const float*)d_in[8];
    const float* bo  = (const float*)d_in[9];
    const float* W1  = (const float*)d_in[10];
    const float* b1  = (const float*)d_in[11];
    const float* W2  = (const float*)d_in[12];
    const float* b2  = (const float*)d_in[13];
    const float* g1  = (const float*)d_in[14];
    const float* be1 = (const float*)d_in[15];
    const float* g2  = (const float*)d_in[16];
    const float* be2 = (const float*)d_in[17];
    const float* E   = (const float*)d_in[18];
    const float* Wf  = (const float*)d_in[19];
    const float* bf  = (const float*)d_in[20];
    float* out = (float*)d_out;

    // side stream + events (created once; host objects only)
    static cudaStream_t s1 = nullptr;
    static cudaEvent_t evFork = nullptr, evJoin = nullptr, evQE = nullptr, evV = nullptr;
    if (!s1) {
        cudaStreamCreateWithFlags(&s1, cudaStreamNonBlocking);
        cudaEventCreateWithFlags(&evFork, cudaEventDisableTiming);
        cudaEventCreateWithFlags(&evJoin, cudaEventDisableTiming);
        cudaEventCreateWithFlags(&evQE,   cudaEventDisableTiming);
        cudaEventCreateWithFlags(&evV,    cudaEventDisableTiming);
    }
    cudaStream_t s0 = 0;  // capture/default stream

    float *t1, *h2, *qe, *lg, *rate, *bqk;
    cudaGetSymbolAddress((void**)&t1, g_t1);
    cudaGetSymbolAddress((void**)&h2, g_h2);
    cudaGetSymbolAddress((void**)&qe, g_qe);
    cudaGetSymbolAddress((void**)&lg, g_lg);
    cudaGetSymbolAddress((void**)&rate, g_rate);
    cudaGetSymbolAddress((void**)&bqk, g_bqk);

    bf16 *xh, *xl, *qkh, *qkl, *vth, *vtl, *ath, *atl, *ffh, *ffl;
    bf16 *awh, *awl, *eh, *el;
    cudaGetSymbolAddress((void**)&xh,  g_xh);  cudaGetSymbolAddress((void**)&xl,  g_xl);
    cudaGetSymbolAddress((void**)&qkh, g_qkh); cudaGetSymbolAddress((void**)&qkl, g_qkl);
    cudaGetSymbolAddress((void**)&vth, g_vth); cudaGetSymbolAddress((void**)&vtl, g_vtl);
    cudaGetSymbolAddress((void**)&ath, g_ath); cudaGetSymbolAddress((void**)&atl, g_atl);
    cudaGetSymbolAddress((void**)&ffh, g_ffh); cudaGetSymbolAddress((void**)&ffl, g_ffl);
    cudaGetSymbolAddress((void**)&awh, g_awh); cudaGetSymbolAddress((void**)&awl, g_awl);
    cudaGetSymbolAddress((void**)&eh,  g_eh);  cudaGetSymbolAddress((void**)&el,  g_el);

    bf16 *wqkh, *wqkl, *wvh, *wvl, *woh, *wol;
    bf16 *w1h, *w1l, *w2h, *w2l, *wfh, *wfl;
    cudaGetSymbolAddress((void**)&wqkh, g_wqk_h); cudaGetSymbolAddress((void**)&wqkl, g_wqk_l);
    cudaGetSymbolAddress((void**)&wvh, g_wv_h); cudaGetSymbolAddress((void**)&wvl, g_wv_l);
    cudaGetSymbolAddress((void**)&woh, g_wo_h); cudaGetSymbolAddress((void**)&wol, g_wo_l);
    cudaGetSymbolAddress((void**)&w1h, g_w1_h); cudaGetSymbolAddress((void**)&w1l, g_w1_l);
    cudaGetSymbolAddress((void**)&w2h, g_w2_h); cudaGetSymbolAddress((void**)&w2l, g_w2_l);
    cudaGetSymbolAddress((void**)&wfh, g_wf_h); cudaGetSymbolAddress((void**)&wfl, g_wf_l);

    const int M = BB * SS;  // 2048
    const long long sSD  = (long long)SS * DD;
    const long long sSQK = (long long)SS * QKW;
    const long long sHSS = (long long)HH * SS * SS;
    const long long sSSq = (long long)SS * SS;
    const long long sDS  = (long long)DD * SS;
    const long long wQKL = (long long)QKW * DD;

    // ---- setup: conversions on s0 || {rest of conversions, rate, embed} on s1
    cudaEventRecord(evFork, s0);
    cudaStreamWaitEvent(s1, evFork, 0);

    conv_w<<<dim3(DD / 64, DD / 64, LL), 256, 0, s0>>>(Wq, wqkh, wqkl, DD, DD, wQKL);
    conv_w<<<dim3(DD / 64, DD / 64, LL), 256, 0, s0>>>(Wk, wqkh + (size_t)DD * DD,
                                                       wqkl + (size_t)DD * DD, DD, DD, wQKL);
    conv_w<<<dim3(DD / 64, DD / 64, LL), 256, 0, s0>>>(Wv, wvh, wvl, DD, DD, (long long)DD * DD);

    conv_w<<<dim3(DD / 64, DD / 64, LL), 256, 0, s1>>>(Wo, woh, wol, DD, DD, (long long)DD * DD);
    conv_w<<<dim3(DF / 64, DD / 64, LL), 256, 0, s1>>>(W1, w1h, w1l, DD, DF, (long long)DF * DD);
    conv_w<<<dim3(DD / 64, DF / 64, LL), 256, 0, s1>>>(W2, w2h, w2l, DF, DD, (long long)DD * DF);
    conv_w<<<dim3(VV / 64, DD / 64, 1),  256, 0, s1>>>(Wf, wfh, wfl, DD, VV, (long long)VV * DD);
    split_act<<<(LL * SS * HD / 4 + 255) / 256, 256, 0, s1>>>(E, eh, el, LL * SS * HD / 4);
    concat_bias<<<(LL * QKW + 255) / 256, 256, 0, s1>>>(bq, bk, bqk);
    rate_kernel<<<4, 256, 0, s1>>>(rate);
    embed_split<<<BB * SS, 256, 0, s1>>>(x, emb, rate, xh, xl);

    cudaEventRecord(evJoin, s1);
    cudaStreamWaitEvent(s0, evJoin, 0);

    for (int l = 0; l < LL; l++) {
        const size_t wdd = (size_t)l * DD * DD;
        const size_t wdf = (size_t)l * DF * DD;
        const bf16* ehl = eh + (size_t)l * SS * HD;
        const bf16* ell = el + (size_t)l * SS * HD;

        // combined Q|K projection on s0
        run_mma_s<128, 0, false, 1, false>(s0, xh, xl, wqkh + (size_t)l * wQKL,
                                           wqkl + (size_t)l * wQKL, bqk + l * QKW,
                                           nullptr, qkh, qkl, M, QKW, DD, DD, DD, QKW,
                                           1, 1, 0, 0, 0, 0, 0, 0);

        // fork: s1 does QE then V-proj, s0 does QK^T
        cudaEventRecord(evFork, s0);
        cudaStreamWaitEvent(s1, evFork, 0);

        run_mma_s<128, 1, false, 0, false>(s1, qkh, qkl, ehl, ell, nullptr, qe,
                                           nullptr, nullptr,
                                           SS, SS, HD, QKW, HD, SS, BB * HH, HH,
                                           sSQK, HD, 0, 0, sHSS, sSSq);
        cudaEventRecord(evQE, s1);
        run_mma_s<128, 0, false, 2, false>(s1, xh, xl, wvh + wdd, wvl + wdd, bv + l * DD,
                                           nullptr, vth, vtl, SS, DD, DD, DD, DD, SS,
                                           BB, 1, sSD, 0, 0, 0, sDS, 0);
        cudaEventRecord(evV, s1);

        run_mma_s<128, 2, false, 0, false>(s0, qkh, qkl, qkh + DD, qkl + DD, nullptr, lg,
                                           nullptr, nullptr,
                                           SS, SS, HD, QKW, QKW, SS, BB * HH, HH,
                                           sSQK, HD, sSQK, HD, sHSS, sSSq);

        cudaStreamWaitEvent(s0, evQE, 0);
        attn_softmax<<<dim3(SS, BB * HH), 256, 0, s0>>>(lg, qe, x, awh, awl);

        cudaStreamWaitEvent(s0, evV, 0);
        run_mma_s<64, 0, true, 1, false>(s0, awh, awl, vth, vtl, nullptr,
                                         nullptr, ath, atl, SS, HD, SS, SS, SS, DD,
                                         BB * HH, HH, sHSS, sSSq,
                                         sDS, (long long)HD * SS, sSD, HD);

        // Wo + LN1
        run_mma_s<128, 0, false, 0, false>(s0, ath, atl, woh + wdd, wol + wdd, bo + l * DD,
                                           t1, nullptr, nullptr, M, DD, DD, DD, DD, DD,
                                           1, 1, 0, 0, 0, 0, 0, 0);
        ln_split<<<BB * SS, 256, 0, s0>>>(t1, g1 + l * DD, be1 + l * DD, xh, xl);

        // FFN
        run_mma_s<64, 0, false, 1, true>(s0, xh, xl, w1h + wdf, w1l + wdf, b1 + l * DF,
                                         nullptr, ffh, ffl, M, DF, DD, DD, DD, DF,
                                         1, 1, 0, 0, 0, 0, 0, 0);
        run_mma_s<128, 0, false, 0, false>(s0, ffh, ffl, w2h + wdf, w2l + wdf, b2 + l * DD,
                                           h2, nullptr, nullptr, M, DD, DF, DF, DF, DD,
                                           1, 1, 0, 0, 0, 0, 0, 0);
        ln_split<<<BB * SS, 256, 0, s0>>>(h2, g2 + l * DD, be2 + l * DD, xh, xl);
    }

    // final projection to vocab
    run_mma_s<64, 0, false, 0, false>(s0, xh, xl, wfh, wfl, bf, out, nullptr, nullptr,
                                      M, VV, DD, DD, DD, VV, 1, 1, 0, 0, 0, 0, 0, 0);
}

// round 11
// speedup vs baseline: 1.6706x; 1.0226x over previous
#include <cuda_runtime.h>
#include <cuda_bf16.h>
#include <math.h>
#include <stdint.h>

// ---------------------------------------------------------------------------
// Problem constants
// ---------------------------------------------------------------------------
constexpr int BB = 2;     // batch
constexpr int SS = 1024;  // seq len
constexpr int DD = 1024;  // model dim
constexpr int HH = 16;    // heads
constexpr int LL = 6;     // layers
constexpr int VV = 256;   // vocab
constexpr int HD = 64;    // head dim
constexpr int DF = 512;   // ffn dim
constexpr int QKW = 2048; // combined q|k width
constexpr float ATT_SCALE = 0.125f;  // 1/sqrt(64)

// ---------------------------------------------------------------------------
// Scratch (static device globals -- no allocations allowed)
// ---------------------------------------------------------------------------
__device__ float g_t1 [BB * SS * DD];                 // pre-LN fp32
__device__ float g_h2 [BB * SS * DD];                 // pre-LN fp32
__device__ float g_qe [(size_t)BB * HH * SS * SS];    // 134 MB
__device__ float g_lg [(size_t)BB * HH * SS * SS];    // 134 MB
__device__ float g_rate[DD];
__device__ float g_bqk [LL * QKW];
__device__ float g_ps [(size_t)BB * HH * SS * 16];    // per-(row,tile,half) sumexp
__device__ float g_rs [BB * HH * SS];                 // 1/rowsum

// split activation buffers
__device__ __nv_bfloat16 g_xh [BB * SS * DD], g_xl [BB * SS * DD];  // layer in
__device__ __nv_bfloat16 g_qkh[BB * SS * QKW], g_qkl[BB * SS * QKW]; // q|k
__device__ __nv_bfloat16 g_vth[BB * DD * SS], g_vtl[BB * DD * SS];  // v^T per head
__device__ __nv_bfloat16 g_ath[BB * SS * DD], g_atl[BB * SS * DD];  // attn out
__device__ __nv_bfloat16 g_ffh[BB * SS * DF], g_ffl[BB * SS * DF];
__device__ __nv_bfloat16 g_eh [LL * SS * HD], g_el [LL * SS * HD];

// bf16 split weight buffers ([N, K] transposed, hi/lo)
__device__ __nv_bfloat16 g_wqk_h[LL * QKW * DD], g_wqk_l[LL * QKW * DD];
__device__ __nv_bfloat16 g_wv_h[LL * DD * DD],  g_wv_l[LL * DD * DD];
__device__ __nv_bfloat16 g_wo_h[LL * DD * DD],  g_wo_l[LL * DD * DD];
__device__ __nv_bfloat16 g_w1_h[LL * DF * DD],  g_w1_l[LL * DF * DD];
__device__ __nv_bfloat16 g_w2_h[LL * DD * DF],  g_w2_l[LL * DD * DF];
__device__ __nv_bfloat16 g_wf_h[VV * DD],       g_wf_l[VV * DD];

// ---------------------------------------------------------------------------
// PTX helpers (mma.sync / ldmatrix / cp.async -- standard ISA, sm_80+)
// ---------------------------------------------------------------------------
__device__ __forceinline__ uint32_t smem_u32(const void* p) {
    uint32_t a;
    asm("{ .reg .u64 t; cvta.to.shared.u64 t, %1; cvt.u32.u64 %0, t; }"
        : "=r"(a) : "l"(p));
    return a;
}
__device__ __forceinline__ void cpasync16(uint32_t s, const void* g) {
    asm volatile("cp.async.ca.shared.global [%0], [%1], 16;"
                 :: "r"(s), "l"(g) : "memory");
}
__device__ __forceinline__ void ldm_x4(uint32_t a, uint32_t r[4]) {
    asm volatile("ldmatrix.sync.aligned.m8n8.x4.shared.b16 {%0,%1,%2,%3}, [%4];"
                 : "=r"(r[0]), "=r"(r[1]), "=r"(r[2]), "=r"(r[3]) : "r"(a));
}
__device__ __forceinline__ void mma_bf16(float c[4], const uint32_t a[4],
                                         const uint32_t b[2]) {
    asm volatile("mma.sync.aligned.m16n8k16.row.col.f32.bf16.bf16.f32 "
                 "{%0,%1,%2,%3}, {%4,%5,%6,%7}, {%8,%9}, {%0,%1,%2,%3};"
                 : "+f"(c[0]), "+f"(c[1]), "+f"(c[2]), "+f"(c[3])
                 : "r"(a[0]), "r"(a[1]), "r"(a[2]), "r"(a[3]),
                   "r"(b[0]), "r"(b[1]));
}
__device__ __forceinline__ uint32_t pack_bf2(float a, float b) {
    __nv_bfloat162 t = __floats2bfloat162_rn(a, b);
    return *(uint32_t*)&t;
}
__device__ __forceinline__ float bf_hi(float v) {
    return __bfloat162float(__float2bfloat16(v));
}

// ---------------------------------------------------------------------------
// Unified batched split-bf16 HMMA GEMM.
// OUT: 0 fp32 C; 1 split bf16; 2 split bf16 transposed (smem staged);
//      3 attention-logit mode: v = (acc + qe_gather)*scale + pad_mask (or
//        -1e30 beyond causal), written fp32 to C; per-(row,tile,half) sum of
//        exp(v) written to psum (Cl), qe passed via Ch, tokens x via bias.
// ---------------------------------------------------------------------------
template<int BN, int SKIP, bool KCAP, int OUT, bool RELU>
__global__ __launch_bounds__(256, 2)
void gemm_mma(const __nv_bfloat16* __restrict__ Ahi, const __nv_bfloat16* __restrict__ Alo,
              const __nv_bfloat16* __restrict__ Bhi, const __nv_bfloat16* __restrict__ Blo,
              const float* __restrict__ bias, float* __restrict__ C,
              __nv_bfloat16* __restrict__ Ch, __nv_bfloat16* __restrict__ Cl,
              int K, int lda, int ldb, int ldc, int zdiv,
              long long sA1, long long sA2,
              long long sB1, long long sB2,
              long long sC1, long long sC2)
{
    constexpr int ABY = 10240;            // 128 rows * 80B
    constexpr int BBY = BN * 80;
    constexpr int STG = 2 * ABY + 2 * BBY;
    constexpr int NT  = BN / 16;
    constexpr int BN2 = BN / 2;
    constexpr int TP  = 136;              // transpose-stage pitch (bf16 elems)

    const int m0 = blockIdx.y * 128;
    const int n0 = blockIdx.x * BN;
    if (SKIP == 1 && (m0 + n0 + 127 + BN - 1 < SS - 1)) return;
    if (SKIP == 2 && (n0 >= m0 + 128)) return;

    extern __shared__ char dynsmem[];
    const uint32_t sbase = smem_u32(dynsmem);
    const int tid  = threadIdx.x;
    const int lane = tid & 31;
    const int warp = tid >> 5;
    const int wm = warp & 3;
    const int wn = warp >> 2;

    const int z  = blockIdx.z;
    const int zb = z / zdiv;
    const int zh = z % zdiv;
    Ahi += (size_t)zb * sA1 + (size_t)zh * sA2;
    Alo += (size_t)zb * sA1 + (size_t)zh * sA2;
    Bhi += (size_t)zb * sB1 + (size_t)zh * sB2;
    Blo += (size_t)zb * sB1 + (size_t)zh * sB2;
    if (OUT == 0 || OUT == 3) C += (size_t)zb * sC1 + (size_t)zh * sC2;
    if (OUT == 1 || OUT == 2) { Ch += (size_t)zb * sC1 + (size_t)zh * sC2;
                                Cl += (size_t)zb * sC1 + (size_t)zh * sC2; }
    // OUT==3 extras: qe (fp32, same strides as C) via Ch; psum via Cl; x via bias
    const float* qeB = (OUT == 3)
        ? ((const float*)Ch + (size_t)zb * sC1 + (size_t)zh * sC2) : nullptr;
    float* psB = (OUT == 3) ? ((float*)Cl + (size_t)z * SS * 16) : nullptr;
    const int* xB = (OUT == 3) ? ((const int*)bias + (size_t)zb * SS) : nullptr;

    float acc[2][NT][4];
#pragma unroll
    for (int mt = 0; mt < 2; ++mt)
#pragma unroll
        for (int nt = 0; nt < NT; ++nt)
#pragma unroll
            for (int r = 0; r < 4; ++r) acc[mt][nt][r] = 0.f;

    const int Keff = KCAP ? min(K, m0 + 128) : K;
    const int nch  = Keff >> 5;

    auto load_stage = [&](int c) {
        const int k0c = c << 5;
        const uint32_t sb = sbase + (c & 1) * STG;
#pragma unroll
        for (int i = 0; i < 2; ++i) {
            const int u = tid + i * 256;
            const int row = u >> 2, seg = u & 3;
            const uint32_t so = sb + row * 80 + seg * 16;
            const size_t ga = (size_t)(m0 + row) * lda + k0c + seg * 8;
            cpasync16(so,       Ahi + ga);
            cpasync16(so + ABY, Alo + ga);
        }
        constexpr int BU = (BN * 4) / 256;
#pragma unroll
        for (int i = 0; i < BU; ++i) {
            const int u = tid + i * 256;
            const int row = u >> 2, seg = u & 3;
            const uint32_t so = sb + 2 * ABY + row * 80 + seg * 16;
            const size_t gb = (size_t)(n0 + row) * ldb + k0c + seg * 8;
            cpasync16(so,       Bhi + gb);
            cpasync16(so + BBY, Blo + gb);
        }
        asm volatile("cp.async.commit_group;" ::: "memory");
    };

    load_stage(0);

    const int lr  = lane & 7;
    const int sel = lane >> 3;
    const int a_row_off = lr + ((sel & 1) << 3);
    const int a_k_off   = (sel >> 1) << 3;
    const int b_n_off   = lr + ((sel >> 1) << 3);
    const int b_k_off   = (sel & 1) << 3;

    for (int c = 0; c < nch; ++c) {
        if (c + 1 < nch) {
            load_stage(c + 1);
            asm volatile("cp.async.wait_group 1;" ::: "memory");
        } else {
            asm volatile("cp.async.wait_group 0;" ::: "memory");
        }
        __syncthreads();
        const uint32_t sb = sbase + (c & 1) * STG;

#pragma unroll
        for (int ks = 0; ks < 2; ++ks) {
            const int kk = ks << 4;
            uint32_t ah[2][4], al[2][4], bb[NT][2];
#pragma unroll
            for (int mt = 0; mt < 2; ++mt) {
                const int row = wm * 32 + mt * 16 + a_row_off;
                const uint32_t ad = sb + row * 80 + (kk + a_k_off) * 2;
                ldm_x4(ad, ah[mt]);
                ldm_x4(ad + ABY, al[mt]);
            }
#pragma unroll
            for (int p = 0; p < NT / 2; ++p) {
                const int n = wn * BN2 + p * 16 + b_n_off;
                uint32_t r[4];
                ldm_x4(sb + 2 * ABY + n * 80 + (kk + b_k_off) * 2, r);
                bb[2 * p][0]     = r[0]; bb[2 * p][1]     = r[1];
                bb[2 * p + 1][0] = r[2]; bb[2 * p + 1][1] = r[3];
            }
#pragma unroll
            for (int mt = 0; mt < 2; ++mt)
#pragma unroll
                for (int nt = 0; nt < NT; ++nt)
                    mma_bf16(acc[mt][nt], ah[mt], bb[nt]);
#pragma unroll
            for (int mt = 0; mt < 2; ++mt)
#pragma unroll
                for (int nt = 0; nt < NT; ++nt)
                    mma_bf16(acc[mt][nt], al[mt], bb[nt]);
#pragma unroll
            for (int p = 0; p < NT / 2; ++p) {
                const int n = wn * BN2 + p * 16 + b_n_off;
                uint32_t r[4];
                ldm_x4(sb + 2 * ABY + BBY + n * 80 + (kk + b_k_off) * 2, r);
                bb[2 * p][0]     = r[0]; bb[2 * p][1]     = r[1];
                bb[2 * p + 1][0] = r[2]; bb[2 * p + 1][1] = r[3];
            }
#pragma unroll
            for (int mt = 0; mt < 2; ++mt)
#pragma unroll
                for (int nt = 0; nt < NT; ++nt)
                    mma_bf16(acc[mt][nt], ah[mt], bb[nt]);
        }
        __syncthreads();
    }

    const int rbase = m0 + wm * 32 + (lane >> 2);
    const int cbase = n0 + wn * BN2 + 2 * (lane & 3);
    __nv_bfloat16* tsh = (__nv_bfloat16*)dynsmem;            // OUT==2 staging
    __nv_bfloat16* tsl = (__nv_bfloat16*)(dynsmem + (size_t)BN * TP * 2);
#pragma unroll
    for (int mt = 0; mt < 2; ++mt) {
        const int i0r = rbase + mt * 16;
        const int i1r = i0r + 8;
        float e0 = 0.f, e1 = 0.f;                            // OUT==3 sums
#pragma unroll
        for (int nt = 0; nt < NT; ++nt) {
            const int col = cbase + nt * 8;
            float b0v = 0.f, b1v = 0.f;
            if (OUT != 3 && bias) { b0v = bias[col]; b1v = bias[col + 1]; }
            float v0 = acc[mt][nt][0] + b0v;
            float v1 = acc[mt][nt][1] + b1v;
            float v2 = acc[mt][nt][2] + b0v;
            float v3 = acc[mt][nt][3] + b1v;
            if (RELU) {
                v0 = fmaxf(v0, 0.f); v1 = fmaxf(v1, 0.f);
                v2 = fmaxf(v2, 0.f); v3 = fmaxf(v3, 0.f);
            }
            if (OUT == 0) {
                *(float2*)&C[(size_t)i0r * ldc + col] = make_float2(v0, v1);
                *(float2*)&C[(size_t)i1r * ldc + col] = make_float2(v2, v3);
            } else if (OUT == 1) {
                const float h0 = bf_hi(v0), h1 = bf_hi(v1);
                const float h2 = bf_hi(v2), h3 = bf_hi(v3);
                *(uint32_t*)&Ch[(size_t)i0r * ldc + col] = pack_bf2(h0, h1);
                *(uint32_t*)&Ch[(size_t)i1r * ldc + col] = pack_bf2(h2, h3);
                *(uint32_t*)&Cl[(size_t)i0r * ldc + col] = pack_bf2(v0 - h0, v1 - h1);
                *(uint32_t*)&Cl[(size_t)i1r * ldc + col] = pack_bf2(v2 - h2, v3 - h3);
            } else if (OUT == 2) {
                const float vv[4] = {v0, v1, v2, v3};
#pragma unroll
                for (int e = 0; e < 4; ++e) {
                    const int cc = col - n0 + (e & 1);
                    const int rr = i0r - m0 + (e >> 1) * 8;
                    const __nv_bfloat16 hb = __float2bfloat16(vv[e]);
                    tsh[cc * TP + rr] = hb;
                    tsl[cc * TP + rr] =
                        __float2bfloat16(vv[e] - __bfloat162float(hb));
                }
            } else {  // OUT == 3: attention-logit epilogue
                const int j0 = col, j1 = col + 1;
                const float p0 = (xB[j0] == 0) ? -1e9f : 0.f;
                const float p1 = (xB[j1] == 0) ? -1e9f : 0.f;
                v0 = (j0 <= i0r)
                   ? (v0 + qeB[(size_t)i0r * SS + (SS - 1 - i0r) + j0]) * ATT_SCALE + p0
                   : -1e30f;
                v1 = (j1 <= i0r)
                   ? (v1 + qeB[(size_t)i0r * SS + (SS - 1 - i0r) + j1]) * ATT_SCALE + p1
                   : -1e30f;
                v2 = (j0 <= i1r)
                   ? (v2 + qeB[(size_t)i1r * SS + (SS - 1 - i1r) + j0]) * ATT_SCALE + p0
                   : -1e30f;
                v3 = (j1 <= i1r)
                   ? (v3 + qeB[(size_t)i1r * SS + (SS - 1 - i1r) + j1]) * ATT_SCALE + p1
                   : -1e30f;
                *(float2*)&C[(size_t)i0r * ldc + col] = make_float2(v0, v1);
                *(float2*)&C[(size_t)i1r * ldc + col] = make_float2(v2, v3);
                e0 += __expf(v0) + __expf(v1);
                e1 += __expf(v2) + __expf(v3);
            }
        }
        if (OUT == 3) {
            e0 += __shfl_xor_sync(0xffffffffu, e0, 1);
            e0 += __shfl_xor_sync(0xffffffffu, e0, 2);
            e1 += __shfl_xor_sync(0xffffffffu, e1, 1);
            e1 += __shfl_xor_sync(0xffffffffu, e1, 2);
            if ((lane & 3) == 0) {
                psB[(size_t)i0r * 16 + (n0 >> 7) * 2 + wn] = e0;
                psB[(size_t)i1r * 16 + (n0 >> 7) * 2 + wn] = e1;
            }
        }
    }
    if (OUT == 2) {
        __syncthreads();
#pragma unroll
        for (int p = 0; p < BN / 16; ++p) {
            const int idx = tid + p * 256;
            const int row = idx >> 4, seg = idx & 15;
            const uint4 vh = *(const uint4*)&tsh[row * TP + seg * 8];
            const uint4 vl = *(const uint4*)&tsl[row * TP + seg * 8];
            *(uint4*)&Ch[(size_t)(n0 + row) * ldc + m0 + seg * 8] = vh;
            *(uint4*)&Cl[(size_t)(n0 + row) * ldc + m0 + seg * 8] = vl;
        }
    }
}

// ---------------------------------------------------------------------------
// Combine per-tile sumexp partials -> 1/rowsum (deterministic fixed order)
// ---------------------------------------------------------------------------
__global__ __launch_bounds__(256)
void sum_combine(const float* __restrict__ ps, float* __restrict__ rs)
{
    const int idx = blockIdx.x * 256 + threadIdx.x;   // bh*SS + i
    if (idx >= BB * HH * SS) return;
    const int i = idx & (SS - 1);
    const float* p = ps + (size_t)idx * 16;
    const int ntile = (i >> 7) + 1;
    float s = 0.f;
    for (int t = 0; t < ntile; ++t) s += p[t * 2] + p[t * 2 + 1];
    rs[idx] = 1.f / s;
}

// ---------------------------------------------------------------------------
// AV GEMM: attn = softmax(lg) @ v, reading prepared fp32 logits directly.
// A-fragments built in registers: p = exp(v) * invS, split hi/lo.
// B = v^T (split bf16). Batched over bh via blockIdx.z. K capped causally.
// ---------------------------------------------------------------------------
constexpr int AV_AP   = 36;                       // A pitch (floats)
constexpr int AV_ABY  = 128 * AV_AP * 4;          // 18432 B
constexpr int AV_BBY  = 64 * 80;                  // 5120 B
constexpr int AV_STG  = AV_ABY + 2 * AV_BBY;      // 28672
constexpr int AV_SMEM = 2 * AV_STG;               // 57344

__global__ __launch_bounds__(256, 2)
void av_gemm(const float* __restrict__ lg, const float* __restrict__ rs,
             const __nv_bfloat16* __restrict__ vth, const __nv_bfloat16* __restrict__ vtl,
             __nv_bfloat16* __restrict__ oh, __nv_bfloat16* __restrict__ ol)
{
    extern __shared__ char dynsmem[];
    const uint32_t sbase = smem_u32(dynsmem);
    float* Asf = (float*)dynsmem;
    const int tid  = threadIdx.x;
    const int lane = tid & 31;
    const int warp = tid >> 5;
    const int wm = warp & 3;
    const int wn = warp >> 2;
    const int m0 = blockIdx.y * 128;
    const int bh = blockIdx.z;
    const int b  = bh >> 4;
    const int h  = bh & 15;

    const float* A = lg + (size_t)bh * SS * SS;
    const __nv_bfloat16* Bh = vth + ((size_t)b * DD + h * HD) * SS;
    const __nv_bfloat16* Bl = vtl + ((size_t)b * DD + h * HD) * SS;

    // invS for this thread's 4 rows
    const int rr0 = m0 + wm * 32 + (lane >> 2);
    float iv[4];
#pragma unroll
    for (int r = 0; r < 4; ++r) iv[r] = rs[bh * SS + rr0 + r * 8];

    float acc[2][4][4];
#pragma unroll
    for (int mt = 0; mt < 2; ++mt)
#pragma unroll
        for (int nt = 0; nt < 4; ++nt)
#pragma unroll
            for (int r = 0; r < 4; ++r) acc[mt][nt][r] = 0.f;

    const int Keff = min(SS, m0 + 128);
    const int nch  = Keff >> 5;

    auto load_stage = [&](int c) {
        const int k0c = c << 5;
        const uint32_t sb = sbase + (c & 1) * AV_STG;
#pragma unroll
        for (int i = 0; i < 4; ++i) {                 // A: 128 rows x 8 segs(4 fp32)
            const int u = tid + i * 256;
            const int row = u >> 3, seg = u & 7;
            cpasync16(sb + row * (AV_AP * 4) + seg * 16,
                      A + (size_t)(m0 + row) * SS + k0c + seg * 4);
        }
        {                                             // B: 64 rows x 4 segs(8 bf16)
            const int row = tid >> 2, seg = tid & 3;
            const uint32_t so = sb + AV_ABY + row * 80 + seg * 16;
            const size_t gb = (size_t)row * SS + k0c + seg * 8;
            cpasync16(so,          Bh + gb);
            cpasync16(so + AV_BBY, Bl + gb);
        }
        asm volatile("cp.async.commit_group;" ::: "memory");
    };

    load_stage(0);

    const int lr  = lane & 7;
    const int sel = lane >> 3;
    const int b_n_off = lr + ((sel >> 1) << 3);
    const int b_k_off = (sel & 1) << 3;

    for (int c = 0; c < nch; ++c) {
        if (c + 1 < nch) {
            load_stage(c + 1);
            asm volatile("cp.async.wait_group 1;" ::: "memory");
        } else {
            asm volatile("cp.async.wait_group 0;" ::: "memory");
        }
        __syncthreads();
        const float* Af = Asf + ((c & 1) ? AV_STG / 4 : 0);
        const uint32_t sbB = sbase + (c & 1) * AV_STG + AV_ABY;

#pragma unroll
        for (int ks = 0; ks < 2; ++ks) {
            const int kk = ks << 4;
            const int c0 = kk + (lane & 3) * 2;
            uint32_t aH[2][4], aL[2][4], bb[4][2];
#pragma unroll
            for (int mt = 0; mt < 2; ++mt) {
                const float* Ar = Af + (wm * 32 + mt * 16 + (lane >> 2)) * AV_AP;
                const float2 x00 = *(const float2*)(Ar + c0);
                const float2 x10 = *(const float2*)(Ar + 8 * AV_AP + c0);
                const float2 x01 = *(const float2*)(Ar + c0 + 8);
                const float2 x11 = *(const float2*)(Ar + 8 * AV_AP + c0 + 8);
                const float i0 = iv[mt * 2], i1 = iv[mt * 2 + 1];
                const float p0 = __expf(x00.x) * i0, p1 = __expf(x00.y) * i0;
                const float p2 = __expf(x10.x) * i1, p3 = __expf(x10.y) * i1;
                const float p4 = __expf(x01.x) * i0, p5 = __expf(x01.y) * i0;
                const float p6 = __expf(x11.x) * i1, p7 = __expf(x11.y) * i1;
                const float h0 = bf_hi(p0), h1 = bf_hi(p1), h2 = bf_hi(p2), h3 = bf_hi(p3);
                const float h4 = bf_hi(p4), h5 = bf_hi(p5), h6 = bf_hi(p6), h7 = bf_hi(p7);
                aH[mt][0] = pack_bf2(h0, h1); aH[mt][1] = pack_bf2(h2, h3);
                aH[mt][2] = pack_bf2(h4, h5); aH[mt][3] = pack_bf2(h6, h7);
                aL[mt][0] = pack_bf2(p0 - h0, p1 - h1);
                aL[mt][1] = pack_bf2(p2 - h2, p3 - h3);
                aL[mt][2] = pack_bf2(p4 - h4, p5 - h5);
                aL[mt][3] = pack_bf2(p6 - h6, p7 - h7);
            }
#pragma unroll
            for (int np = 0; np < 2; ++np) {
                const int n = wn * 32 + np * 16 + b_n_off;
                uint32_t r[4];
                ldm_x4(sbB + n * 80 + (kk + b_k_off) * 2, r);
                bb[2 * np][0]     = r[0]; bb[2 * np][1]     = r[1];
                bb[2 * np + 1][0] = r[2]; bb[2 * np + 1][1] = r[3];
            }
#pragma unroll
            for (int mt = 0; mt < 2; ++mt)
#pragma unroll
                for (int nt = 0; nt < 4; ++nt)
                    mma_bf16(acc[mt][nt], aH[mt], bb[nt]);
#pragma unroll
            for (int mt = 0; mt < 2; ++mt)
#pragma unroll
                for (int nt = 0; nt < 4; ++nt)
                    mma_bf16(acc[mt][nt], aL[mt], bb[nt]);
#pragma unroll
            for (int np = 0; np < 2; ++np) {
                const int n = wn * 32 + np * 16 + b_n_off;
                uint32_t r[4];
                ldm_x4(sbB + AV_BBY + n * 80 + (kk + b_k_off) * 2, r);
                bb[2 * np][0]     = r[0]; bb[2 * np][1]     = r[1];
                bb[2 * np + 1][0] = r[2]; bb[2 * np + 1][1] = r[3];
            }
#pragma unroll
            for (int mt = 0; mt < 2; ++mt)
#pragma unroll
                for (int nt = 0; nt < 4; ++nt)
                    mma_bf16(acc[mt][nt], aH[mt], bb[nt]);
        }
        __syncthreads();
    }

    // split-bf16 epilogue to (b*SS + row)*DD + h*HD + col
    __nv_bfloat16* Oh = oh + ((size_t)b * SS) * DD + h * HD;
    __nv_bfloat16* Ol = ol + ((size_t)b * SS) * DD + h * HD;
    const int cb = wn * 32 + 2 * (lane & 3);
#pragma unroll
    for (int mt = 0; mt < 2; ++mt) {
        const int i0r = rr0 + mt * 16;
        const int i1r = i0r + 8;
#pragma unroll
        for (int nt = 0; nt < 4; ++nt) {
            const int col = cb + nt * 8;
            const float v0 = acc[mt][nt][0], v1 = acc[mt][nt][1];
            const float v2 = acc[mt][nt][2], v3 = acc[mt][nt][3];
            const float h0 = bf_hi(v0), h1 = bf_hi(v1);
            const float h2 = bf_hi(v2), h3 = bf_hi(v3);
            *(uint32_t*)&Oh[(size_t)i0r * DD + col] = pack_bf2(h0, h1);
            *(uint32_t*)&Oh[(size_t)i1r * DD + col] = pack_bf2(h2, h3);
            *(uint32_t*)&Ol[(size_t)i0r * DD + col] = pack_bf2(v0 - h0, v1 - h1);
            *(uint32_t*)&Ol[(size_t)i1r * DD + col] = pack_bf2(v2 - h2, v3 - h3);
        }
    }
}

// ---------------------------------------------------------------------------
// Weight transpose + bf16 hi/lo split (64x64 tiles, packed stores)
// ---------------------------------------------------------------------------
__global__ __launch_bounds__(256)
void conv_w(const float* __restrict__ W, __nv_bfloat16* __restrict__ hi,
            __nv_bfloat16* __restrict__ lo, int K, int N, long long lstride)
{
    __shared__ float t[64][65];   // [n][k]
    const int l = blockIdx.z;
    W  += (size_t)l * K * N;
    hi += (size_t)l * lstride;
    lo += (size_t)l * lstride;
    const int k0 = blockIdx.y * 64, n0 = blockIdx.x * 64;
    const int tid = threadIdx.x;
    const int tc = tid & 31;
    const int tr = tid >> 5;
#pragma unroll
    for (int i = 0; i < 8; ++i) {
        const int kk = tr + i * 8;
        const float2 v = *(const float2*)&W[(size_t)(k0 + kk) * N + n0 + tc * 2];
        t[tc * 2][kk]     = v.x;
        t[tc * 2 + 1][kk] = v.y;
    }
    __syncthreads();
    const int kp = (tid & 31) * 2;
    const int nb = tid >> 5;
#pragma unroll
    for (int i = 0; i < 8; ++i) {
        const int n = nb + i * 8;
        const float a = t[n][kp], b = t[n][kp + 1];
        const float ha = bf_hi(a), hb = bf_hi(b);
        *(uint32_t*)&hi[(size_t)(n0 + n) * K + k0 + kp] = pack_bf2(ha, hb);
        *(uint32_t*)&lo[(size_t)(n0 + n) * K + k0 + kp] = pack_bf2(a - ha, b - hb);
    }
}

// elementwise hi/lo split (for E)
__global__ void split_act(const float* __restrict__ x, __nv_bfloat16* __restrict__ hi,
                          __nv_bfloat16* __restrict__ lo, int n4)
{
    const int i = blockIdx.x * 256 + threadIdx.x;
    if (i >= n4) return;
    const float4 v = ((const float4*)x)[i];
    const float f[4] = {v.x, v.y, v.z, v.w};
    unsigned short hh[4], ll[4];
#pragma unroll
    for (int j = 0; j < 4; j++) {
        const __nv_bfloat16 hb = __float2bfloat16(f[j]);
        const __nv_bfloat16 lb = __float2bfloat16(f[j] - __bfloat162float(hb));
        hh[j] = __bfloat16_as_ushort(hb);
        ll[j] = __bfloat16_as_ushort(lb);
    }
    ((uint2*)hi)[i] = *(const uint2*)hh;
    ((uint2*)lo)[i] = *(const uint2*)ll;
}

// build combined q|k bias [L][2048]
__global__ void concat_bias(const float* __restrict__ bq, const float* __restrict__ bk,
                            float* __restrict__ bqk)
{
    const int i = blockIdx.x * 256 + threadIdx.x;
    if (i >= LL * QKW) return;
    const int l = i >> 11, c = i & (QKW - 1);
    bqk[i] = (c < DD) ? bq[l * DD + c] : bk[l * DD + c - DD];
}

// ---------------------------------------------------------------------------
// Sinusoid rate + embedding (writes split bf16 directly)
// ---------------------------------------------------------------------------
__global__ void rate_kernel(float* __restrict__ rate)
{
    const int d = blockIdx.x * 256 + threadIdx.x;
    if (d >= DD) return;
    const double LN1E4 = 9.210340371976184;
    const int par = d & 1;
    const float r1 = (float)exp(-LN1E4 * (double)d   / 1024.0);
    const float r2 = (float)exp( LN1E4 * (double)par / 1024.0);
    rate[d] = r1 * r2;
}

__global__ void embed_split(const int* __restrict__ x,
                            const float* __restrict__ emb,
                            const float* __restrict__ rate,
                            __nv_bfloat16* __restrict__ oh,
                            __nv_bfloat16* __restrict__ ol)
{
    const int bs = blockIdx.x;
    const int s  = bs & (SS - 1);
    const int tok = x[bs];
    const float* e = emb + (size_t)tok * DD;
    for (int d = threadIdx.x; d < DD; d += blockDim.x) {
        const int par = d & 1;
        const float ph = (float)s * rate[d] + 1.5707964f * (float)par;
        const float v = e[d] * 32.0f + sinf(ph);
        const __nv_bfloat16 hb = __float2bfloat16(v);
        oh[(size_t)bs * DD + d] = hb;
        ol[(size_t)bs * DD + d] = __float2bfloat16(v - __bfloat162float(hb));
    }
}

// ---------------------------------------------------------------------------
// LayerNorm over last dim (1024); reads fp32, writes SPLIT bf16.
// ---------------------------------------------------------------------------
__global__ __launch_bounds__(256)
void ln_split(const float* __restrict__ xin, const float* __restrict__ g,
              const float* __restrict__ be,
              __nv_bfloat16* __restrict__ oh, __nv_bfloat16* __restrict__ ol)
{
    const int row = blockIdx.x;
    const float* p = xin + (size_t)row * DD;
    const int t = threadIdx.x;
    float v[4];
    float s = 0.f, s2 = 0.f;
#pragma unroll
    for (int c = 0; c < 4; c++) {
        v[c] = p[t + c * 256];
        s += v[c];
        s2 += v[c] * v[c];
    }
    __shared__ float sh1[8], sh2[8];
#pragma unroll
    for (int o = 16; o > 0; o >>= 1) {
        s  += __shfl_xor_sync(0xffffffffu, s,  o);
        s2 += __shfl_xor_sync(0xffffffffu, s2, o);
    }
    if ((t & 31) == 0) { sh1[t >> 5] = s; sh2[t >> 5] = s2; }
    __syncthreads();
    s = 0.f; s2 = 0.f;
#pragma unroll
    for (int w = 0; w < 8; w++) { s += sh1[w]; s2 += sh2[w]; }
    const float mu  = s  * (1.f / DD);
    const float var = s2 * (1.f / DD) - mu * mu;
    const float inv = rsqrtf(var + 1e-6f);
#pragma unroll
    for (int c = 0; c < 4; c++) {
        const int d = t + c * 256;
        const float o = (v[c] - mu) * inv * g[d] + be[d];
        const __nv_bfloat16 hb = __float2bfloat16(o);
        oh[(size_t)row * DD + d] = hb;
        ol[(size_t)row * DD + d] = __float2bfloat16(o - __bfloat162float(hb));
    }
}

// ---------------------------------------------------------------------------
// Host side
// ---------------------------------------------------------------------------
using bf16 = __nv_bfloat16;

template<int BN, int SKIP, bool KCAP, int OUT, bool RELU>
static void run_mma_s(cudaStream_t st,
                      const bf16* ah, const bf16* al, const bf16* bh, const bf16* bl,
                      const float* bias, float* C, bf16* Ch, bf16* Cl,
                      int M, int N, int K, int lda, int ldb, int ldc,
                      int batch, int zdiv,
                      long long sA1, long long sA2,
                      long long sB1, long long sB2,
                      long long sC1, long long sC2)
{
    constexpr int STG = 2 * 10240 + 2 * BN * 80;
    static bool init = false;
    if (!init) {
        cudaFuncSetAttribute(gemm_mma<BN, SKIP, KCAP, OUT, RELU>,
                             cudaFuncAttributeMaxDynamicSharedMemorySize, 2 * STG);
        init = true;
    }
    dim3 grid(N / BN, M / 128, batch);
    gemm_mma<BN, SKIP, KCAP, OUT, RELU><<<grid, 256, 2 * STG, st>>>(
        ah, al, bh, bl, bias, C, Ch, Cl, K, lda, ldb, ldc,
        zdiv, sA1, sA2, sB1, sB2, sC1, sC2);
}

extern "C" void kernel_launch(void* const* d_in, const int* in_sizes, int n_in,
                              void* d_out, int out_size)
{
    const int*   x   = (const int*)  d_in[0];
    const float* emb = (const float*)d_in[1];
    const float* Wq  = (const float*)d_in[2];
    const float* bq  = (const float*)d_in[3];
    const float* Wk  = (const float*)d_in[4];
    const float* bk  = (const float*)d_in[5];
    const float* Wv  = (const float*)d_in[6];
    const float* bv  = (const float*)d_in[7];
    const float* Wo  = (const float*)d_in[8];
    const float* bo  = (const float*)d_in[9];
    const float* W1  = (const float*)d_in[10];
    const float* b1  = (const float*)d_in[11];
    const float* W2  = (const float*)d_in[12];
    const float* b2  = (const float*)d_in[13];
    const float* g1  = (const float*)d_in[14];
    const float* be1 = (const float*)d_in[15];
    const float* g2  = (const float*)d_in[16];
    const float* be2 = (const float*)d_in[17];
    const float* E   = (const float*)d_in[18];
    const float* Wf  = (const float*)d_in[19];
    const float* bf  = (const float*)d_in[20];
    float* out = (float*)d_out;

    static cudaStream_t s1 = nullptr;
    static cudaEvent_t evFork = nullptr, evJoin = nullptr, evV = nullptr;
    if (!s1) {
        cudaStreamCreateWithFlags(&s1, cudaStreamNonBlocking);
        cudaEventCreateWithFlags(&evFork, cudaEventDisableTiming);
        cudaEventCreateWithFlags(&evJoin, cudaEventDisableTiming);
        cudaEventCreateWithFlags(&evV,    cudaEventDisableTiming);
    }
    cudaStream_t s0 = 0;

    cudaFuncSetAttribute(av_gemm, cudaFuncAttributeMaxDynamicSharedMemorySize,
                         AV_SMEM);

    float *t1, *h2, *qe, *lg, *rate, *bqk, *ps, *rs;
    cudaGetSymbolAddress((void**)&t1, g_t1);
    cudaGetSymbolAddress((void**)&h2, g_h2);
    cudaGetSymbolAddress((void**)&qe, g_qe);
    cudaGetSymbolAddress((void**)&lg, g_lg);
    cudaGetSymbolAddress((void**)&rate, g_rate);
    cudaGetSymbolAddress((void**)&bqk, g_bqk);
    cudaGetSymbolAddress((void**)&ps, g_ps);
    cudaGetSymbolAddress((void**)&rs, g_rs);

    bf16 *xh, *xl, *qkh, *qkl, *vth, *vtl, *ath, *atl, *ffh, *ffl, *eh, *el;
    cudaGetSymbolAddress((void**)&xh,  g_xh);  cudaGetSymbolAddress((void**)&xl,  g_xl);
    cudaGetSymbolAddress((void**)&qkh, g_qkh); cudaGetSymbolAddress((void**)&qkl, g_qkl);
    cudaGetSymbolAddress((void**)&vth, g_vth); cudaGetSymbolAddress((void**)&vtl, g_vtl);
    cudaGetSymbolAddress((void**)&ath, g_ath); cudaGetSymbolAddress((void**)&atl, g_atl);
    cudaGetSymbolAddress((void**)&ffh, g_ffh); cudaGetSymbolAddress((void**)&ffl, g_ffl);
    cudaGetSymbolAddress((void**)&eh,  g_eh);  cudaGetSymbolAddress((void**)&el,  g_el);

    bf16 *wqkh, *wqkl, *wvh, *wvl, *woh, *wol;
    bf16 *w1h, *w1l, *w2h, *w2l, *wfh, *wfl;
    cudaGetSymbolAddress((void**)&wqkh, g_wqk_h); cudaGetSymbolAddress((void**)&wqkl, g_wqk_l);
    cudaGetSymbolAddress((void**)&wvh, g_wv_h); cudaGetSymbolAddress((void**)&wvl, g_wv_l);
    cudaGetSymbolAddress((void**)&woh, g_wo_h); cudaGetSymbolAddress((void**)&wol, g_wo_l);
    cudaGetSymbolAddress((void**)&w1h, g_w1_h); cudaGetSymbolAddress((void**)&w1l, g_w1_l);
    cudaGetSymbolAddress((void**)&w2h, g_w2_h); cudaGetSymbolAddress((void**)&w2l, g_w2_l);
    cudaGetSymbolAddress((void**)&wfh, g_wf_h); cudaGetSymbolAddress((void**)&wfl, g_wf_l);

    const int M = BB * SS;  // 2048
    const long long sSD  = (long long)SS * DD;
    const long long sSQK = (long long)SS * QKW;
    const long long sHSS = (long long)HH * SS * SS;
    const long long sSSq = (long long)SS * SS;
    const long long sDS  = (long long)DD * SS;
    const long long wQKL = (long long)QKW * DD;

    // ---- setup: conversions on s0 || {rest, rate, embed} on s1
    cudaEventRecord(evFork, s0);
    cudaStreamWaitEvent(s1, evFork, 0);

    conv_w<<<dim3(DD / 64, DD / 64, LL), 256, 0, s0>>>(Wq, wqkh, wqkl, DD, DD, wQKL);
    conv_w<<<dim3(DD / 64, DD / 64, LL), 256, 0, s0>>>(Wk, wqkh + (size_t)DD * DD,
                                                       wqkl + (size_t)DD * DD, DD, DD, wQKL);
    conv_w<<<dim3(DD / 64, DD / 64, LL), 256, 0, s0>>>(Wv, wvh, wvl, DD, DD, (long long)DD * DD);

    conv_w<<<dim3(DD / 64, DD / 64, LL), 256, 0, s1>>>(Wo, woh, wol, DD, DD, (long long)DD * DD);
    conv_w<<<dim3(DF / 64, DD / 64, LL), 256, 0, s1>>>(W1, w1h, w1l, DD, DF, (long long)DF * DD);
    conv_w<<<dim3(DD / 64, DF / 64, LL), 256, 0, s1>>>(W2, w2h, w2l, DF, DD, (long long)DD * DF);
    conv_w<<<dim3(VV / 64, DD / 64, 1),  256, 0, s1>>>(Wf, wfh, wfl, DD, VV, (long long)VV * DD);
    split_act<<<(LL * SS * HD / 4 + 255) / 256, 256, 0, s1>>>(E, eh, el, LL * SS * HD / 4);
    concat_bias<<<(LL * QKW + 255) / 256, 256, 0, s1>>>(bq, bk, bqk);
    rate_kernel<<<4, 256, 0, s1>>>(rate);
    embed_split<<<BB * SS, 256, 0, s1>>>(x, emb, rate, xh, xl);

    cudaEventRecord(evJoin, s1);
    cudaStreamWaitEvent(s0, evJoin, 0);

    for (int l = 0; l < LL; l++) {
        const size_t wdd = (size_t)l * DD * DD;
        const size_t wdf = (size_t)l * DF * DD;
        const bf16* ehl = eh + (size_t)l * SS * HD;
        const bf16* ell = el + (size_t)l * SS * HD;

        // combined Q|K projection on s0
        run_mma_s<128, 0, false, 1, false>(s0, xh, xl, wqkh + (size_t)l * wQKL,
                                           wqkl + (size_t)l * wQKL, bqk + l * QKW,
                                           nullptr, qkh, qkl, M, QKW, DD, DD, DD, QKW,
                                           1, 1, 0, 0, 0, 0, 0, 0);

        // fork: s1 does V-proj; s0 does QE then fused QK
        cudaEventRecord(evFork, s0);
        cudaStreamWaitEvent(s1, evFork, 0);
        run_mma_s<128, 0, false, 2, false>(s1, xh, xl, wvh + wdd, wvl + wdd, bv + l * DD,
                                           nullptr, vth, vtl, SS, DD, DD, DD, DD, SS,
                                           BB, 1, sSD, 0, 0, 0, sDS, 0);
        cudaEventRecord(evV, s1);

        // QE (anti-diagonal tiles only) on s0 -- feeds fused QK epilogue
        run_mma_s<128, 1, false, 0, false>(s0, qkh, qkl, ehl, ell, nullptr, qe,
                                           nullptr, nullptr,
                                           SS, SS, HD, QKW, HD, SS, BB * HH, HH,
                                           sSQK, HD, 0, 0, sHSS, sSSq);

        // QK^T with fused Srel gather + masks + sumexp partials (OUT=3)
        run_mma_s<128, 2, false, 3, false>(s0, qkh, qkl, qkh + DD, qkl + DD,
                                           (const float*)x, lg, (bf16*)qe, (bf16*)ps,
                                           SS, SS, HD, QKW, QKW, SS, BB * HH, HH,
                                           sSQK, HD, sSQK, HD, sHSS, sSSq);

        sum_combine<<<(BB * HH * SS + 255) / 256, 256, 0, s0>>>(ps, rs);

        // attn = softmax @ v, reading lg directly
        cudaStreamWaitEvent(s0, evV, 0);
        av_gemm<<<dim3(1, SS / 128, BB * HH), 256, AV_SMEM, s0>>>(
            lg, rs, vth, vtl, ath, atl);

        // Wo + LN1
        run_mma_s<128, 0, false, 0, false>(s0, ath, atl, woh + wdd, wol + wdd, bo + l * DD,
                                           t1, nullptr, nullptr, M, DD, DD, DD, DD, DD,
                                           1, 1, 0, 0, 0, 0, 0, 0);
        ln_split<<<BB * SS, 256, 0, s0>>>(t1, g1 + l * DD, be1 + l * DD, xh, xl);

        // FFN
        run_mma_s<64, 0, false, 1, true>(s0, xh, xl, w1h + wdf, w1l + wdf, b1 + l * DF,
                                         nullptr, ffh, ffl, M, DF, DD, DD, DD, DF,
                                         1, 1, 0, 0, 0, 0, 0, 0);
        run_mma_s<128, 0, false, 0, false>(s0, ffh, ffl, w2h + wdf, w2l + wdf, b2 + l * DD,
                                           h2, nullptr, nullptr, M, DD, DF, DF, DF, DD,
                                           1, 1, 0, 0, 0, 0, 0, 0);
        ln_split<<<BB * SS, 256, 0, s0>>>(h2, g2 + l * DD, be2 + l * DD, xh, xl);
    }

    // final projection to vocab
    run_mma_s<64, 0, false, 0, false>(s0, xh, xl, wfh, wfl, bf, out, nullptr, nullptr,
                                      M, VV, DD, DD, DD, VV, 1, 1, 0, 0, 0, 0, 0, 0);
}

// round 14
// speedup vs baseline: 1.7706x; 1.0598x over previous
#include <cuda_runtime.h>
#include <cuda_bf16.h>
#include <math.h>
#include <stdint.h>

// ---------------------------------------------------------------------------
// Problem constants
// ---------------------------------------------------------------------------
constexpr int BB = 2;     // batch
constexpr int SS = 1024;  // seq len
constexpr int DD = 1024;  // model dim
constexpr int HH = 16;    // heads
constexpr int LL = 6;     // layers
constexpr int VV = 256;   // vocab
constexpr int HD = 64;    // head dim
constexpr int DF = 512;   // ffn dim
constexpr int QKW = 2048; // combined q|k width
constexpr float ATT_SCALE = 0.125f;  // 1/sqrt(64)

// ---------------------------------------------------------------------------
// Scratch (static device globals -- no allocations allowed)
// ---------------------------------------------------------------------------
__device__ float g_t1 [BB * SS * DD];                 // pre-LN fp32
__device__ float g_h2 [BB * SS * DD];                 // pre-LN fp32
__device__ float g_qe [(size_t)BB * HH * SS * SS];    // 134 MB
__device__ float g_lg [(size_t)BB * HH * SS * SS];    // exp(logits), 134 MB
__device__ float g_rate[DD];
__device__ float g_ps [(size_t)BB * HH * SS * 16];    // per-(row,tile,half) sumexp

// split activation buffers
__device__ __nv_bfloat16 g_xh [BB * SS * DD], g_xl [BB * SS * DD];  // layer in
__device__ __nv_bfloat16 g_qkh[BB * SS * QKW], g_qkl[BB * SS * QKW]; // q|k
__device__ __nv_bfloat16 g_vth[BB * DD * SS], g_vtl[BB * DD * SS];  // v^T per head
__device__ __nv_bfloat16 g_ath[BB * SS * DD], g_atl[BB * SS * DD];  // attn out
__device__ __nv_bfloat16 g_ffh[BB * SS * DF], g_ffl[BB * SS * DF];
__device__ __nv_bfloat16 g_eh [LL * SS * HD], g_el [LL * SS * HD];

// bf16 split weight buffers ([N, K] transposed, hi/lo)
__device__ __nv_bfloat16 g_wqk_h[LL * QKW * DD], g_wqk_l[LL * QKW * DD];
__device__ __nv_bfloat16 g_wv_h[LL * DD * DD],  g_wv_l[LL * DD * DD];
__device__ __nv_bfloat16 g_wo_h[LL * DD * DD],  g_wo_l[LL * DD * DD];
__device__ __nv_bfloat16 g_w1_h[LL * DF * DD],  g_w1_l[LL * DF * DD];
__device__ __nv_bfloat16 g_w2_h[LL * DD * DF],  g_w2_l[LL * DD * DF];
__device__ __nv_bfloat16 g_wf_h[VV * DD],       g_wf_l[VV * DD];

// ---------------------------------------------------------------------------
// PTX helpers (mma.sync / ldmatrix / cp.async -- standard ISA, sm_80+)
// ---------------------------------------------------------------------------
__device__ __forceinline__ uint32_t smem_u32(const void* p) {
    uint32_t a;
    asm("{ .reg .u64 t; cvta.to.shared.u64 t, %1; cvt.u32.u64 %0, t; }"
        : "=r"(a) : "l"(p));
    return a;
}
__device__ __forceinline__ void cpasync16(uint32_t s, const void* g) {
    asm volatile("cp.async.ca.shared.global [%0], [%1], 16;"
                 :: "r"(s), "l"(g) : "memory");
}
__device__ __forceinline__ void ldm_x4(uint32_t a, uint32_t r[4]) {
    asm volatile("ldmatrix.sync.aligned.m8n8.x4.shared.b16 {%0,%1,%2,%3}, [%4];"
                 : "=r"(r[0]), "=r"(r[1]), "=r"(r[2]), "=r"(r[3]) : "r"(a));
}
__device__ __forceinline__ void mma_bf16(float c[4], const uint32_t a[4],
                                         const uint32_t b[2]) {
    asm volatile("mma.sync.aligned.m16n8k16.row.col.f32.bf16.bf16.f32 "
                 "{%0,%1,%2,%3}, {%4,%5,%6,%7}, {%8,%9}, {%0,%1,%2,%3};"
                 : "+f"(c[0]), "+f"(c[1]), "+f"(c[2]), "+f"(c[3])
                 : "r"(a[0]), "r"(a[1]), "r"(a[2]), "r"(a[3]),
                   "r"(b[0]), "r"(b[1]));
}
__device__ __forceinline__ uint32_t pack_bf2(float a, float b) {
    __nv_bfloat162 t = __floats2bfloat162_rn(a, b);
    return *(uint32_t*)&t;
}
__device__ __forceinline__ float bf_hi(float v) {
    return __bfloat162float(__float2bfloat16(v));
}

// ---------------------------------------------------------------------------
// Unified batched split-bf16 HMMA GEMM.
// OUT: 0 fp32 C; 1 split bf16; 2 split bf16 transposed (smem staged);
//      3 attention-logit mode: v = (acc + qe_gather)*scale + pad_mask (or
//        -1e30 beyond causal); exp(v) written fp32 to C; per-(row,tile,half)
//        sum of exp(v) written to psum (Cl), qe via Ch, tokens x via bias.
// ---------------------------------------------------------------------------
template<int BN, int SKIP, bool KCAP, int OUT, bool RELU>
__global__ __launch_bounds__(256, 2)
void gemm_mma(const __nv_bfloat16* __restrict__ Ahi, const __nv_bfloat16* __restrict__ Alo,
              const __nv_bfloat16* __restrict__ Bhi, const __nv_bfloat16* __restrict__ Blo,
              const float* __restrict__ bias, float* __restrict__ C,
              __nv_bfloat16* __restrict__ Ch, __nv_bfloat16* __restrict__ Cl,
              int K, int lda, int ldb, int ldc, int zdiv,
              long long sA1, long long sA2,
              long long sB1, long long sB2,
              long long sC1, long long sC2)
{
    constexpr int ABY = 10240;            // 128 rows * 80B
    constexpr int BBY = BN * 80;
    constexpr int STG = 2 * ABY + 2 * BBY;
    constexpr int NT  = BN / 16;
    constexpr int BN2 = BN / 2;
    constexpr int TP  = 136;              // transpose-stage pitch (bf16 elems)

    const int m0 = blockIdx.y * 128;
    const int n0 = blockIdx.x * BN;
    if (SKIP == 1 && (m0 + n0 + 127 + BN - 1 < SS - 1)) return;
    if (SKIP == 2 && (n0 >= m0 + 128)) return;

    extern __shared__ char dynsmem[];
    const uint32_t sbase = smem_u32(dynsmem);
    const int tid  = threadIdx.x;
    const int lane = tid & 31;
    const int warp = tid >> 5;
    const int wm = warp & 3;
    const int wn = warp >> 2;

    const int z  = blockIdx.z;
    const int zb = z / zdiv;
    const int zh = z % zdiv;
    Ahi += (size_t)zb * sA1 + (size_t)zh * sA2;
    Alo += (size_t)zb * sA1 + (size_t)zh * sA2;
    Bhi += (size_t)zb * sB1 + (size_t)zh * sB2;
    Blo += (size_t)zb * sB1 + (size_t)zh * sB2;
    if (OUT == 0 || OUT == 3) C += (size_t)zb * sC1 + (size_t)zh * sC2;
    if (OUT == 1 || OUT == 2) { Ch += (size_t)zb * sC1 + (size_t)zh * sC2;
                                Cl += (size_t)zb * sC1 + (size_t)zh * sC2; }
    const float* qeB = (OUT == 3)
        ? ((const float*)Ch + (size_t)zb * sC1 + (size_t)zh * sC2) : nullptr;
    float* psB = (OUT == 3) ? ((float*)Cl + (size_t)z * SS * 16) : nullptr;
    const int* xB = (OUT == 3) ? ((const int*)bias + (size_t)zb * SS) : nullptr;

    float acc[2][NT][4];
#pragma unroll
    for (int mt = 0; mt < 2; ++mt)
#pragma unroll
        for (int nt = 0; nt < NT; ++nt)
#pragma unroll
            for (int r = 0; r < 4; ++r) acc[mt][nt][r] = 0.f;

    const int Keff = KCAP ? min(K, m0 + 128) : K;
    const int nch  = Keff >> 5;

    auto load_stage = [&](int c) {
        const int k0c = c << 5;
        const uint32_t sb = sbase + (c & 1) * STG;
#pragma unroll
        for (int i = 0; i < 2; ++i) {
            const int u = tid + i * 256;
            const int row = u >> 2, seg = u & 3;
            const uint32_t so = sb + row * 80 + seg * 16;
            const size_t ga = (size_t)(m0 + row) * lda + k0c + seg * 8;
            cpasync16(so,       Ahi + ga);
            cpasync16(so + ABY, Alo + ga);
        }
        constexpr int BU = (BN * 4) / 256;
#pragma unroll
        for (int i = 0; i < BU; ++i) {
            const int u = tid + i * 256;
            const int row = u >> 2, seg = u & 3;
            const uint32_t so = sb + 2 * ABY + row * 80 + seg * 16;
            const size_t gb = (size_t)(n0 + row) * ldb + k0c + seg * 8;
            cpasync16(so,       Bhi + gb);
            cpasync16(so + BBY, Blo + gb);
        }
        asm volatile("cp.async.commit_group;" ::: "memory");
    };

    load_stage(0);

    const int lr  = lane & 7;
    const int sel = lane >> 3;
    const int a_row_off = lr + ((sel & 1) << 3);
    const int a_k_off   = (sel >> 1) << 3;
    const int b_n_off   = lr + ((sel >> 1) << 3);
    const int b_k_off   = (sel & 1) << 3;

    for (int c = 0; c < nch; ++c) {
        if (c + 1 < nch) {
            load_stage(c + 1);
            asm volatile("cp.async.wait_group 1;" ::: "memory");
        } else {
            asm volatile("cp.async.wait_group 0;" ::: "memory");
        }
        __syncthreads();
        const uint32_t sb = sbase + (c & 1) * STG;

#pragma unroll
        for (int ks = 0; ks < 2; ++ks) {
            const int kk = ks << 4;
            uint32_t ah[2][4], al[2][4], bb[NT][2];
#pragma unroll
            for (int mt = 0; mt < 2; ++mt) {
                const int row = wm * 32 + mt * 16 + a_row_off;
                const uint32_t ad = sb + row * 80 + (kk + a_k_off) * 2;
                ldm_x4(ad, ah[mt]);
                ldm_x4(ad + ABY, al[mt]);
            }
#pragma unroll
            for (int p = 0; p < NT / 2; ++p) {
                const int n = wn * BN2 + p * 16 + b_n_off;
                uint32_t r[4];
                ldm_x4(sb + 2 * ABY + n * 80 + (kk + b_k_off) * 2, r);
                bb[2 * p][0]     = r[0]; bb[2 * p][1]     = r[1];
                bb[2 * p + 1][0] = r[2]; bb[2 * p + 1][1] = r[3];
            }
#pragma unroll
            for (int mt = 0; mt < 2; ++mt)
#pragma unroll
                for (int nt = 0; nt < NT; ++nt)
                    mma_bf16(acc[mt][nt], ah[mt], bb[nt]);
#pragma unroll
            for (int mt = 0; mt < 2; ++mt)
#pragma unroll
                for (int nt = 0; nt < NT; ++nt)
                    mma_bf16(acc[mt][nt], al[mt], bb[nt]);
#pragma unroll
            for (int p = 0; p < NT / 2; ++p) {
                const int n = wn * BN2 + p * 16 + b_n_off;
                uint32_t r[4];
                ldm_x4(sb + 2 * ABY + BBY + n * 80 + (kk + b_k_off) * 2, r);
                bb[2 * p][0]     = r[0]; bb[2 * p][1]     = r[1];
                bb[2 * p + 1][0] = r[2]; bb[2 * p + 1][1] = r[3];
            }
#pragma unroll
            for (int mt = 0; mt < 2; ++mt)
#pragma unroll
                for (int nt = 0; nt < NT; ++nt)
                    mma_bf16(acc[mt][nt], ah[mt], bb[nt]);
        }
        __syncthreads();
    }

    const int rbase = m0 + wm * 32 + (lane >> 2);
    const int cbase = n0 + wn * BN2 + 2 * (lane & 3);
    __nv_bfloat16* tsh = (__nv_bfloat16*)dynsmem;            // OUT==2 staging
    __nv_bfloat16* tsl = (__nv_bfloat16*)(dynsmem + (size_t)BN * TP * 2);
#pragma unroll
    for (int mt = 0; mt < 2; ++mt) {
        const int i0r = rbase + mt * 16;
        const int i1r = i0r + 8;
        float e0 = 0.f, e1 = 0.f;                            // OUT==3 sums
#pragma unroll
        for (int nt = 0; nt < NT; ++nt) {
            const int col = cbase + nt * 8;
            float b0v = 0.f, b1v = 0.f;
            if (OUT != 3 && bias) { b0v = bias[col]; b1v = bias[col + 1]; }
            float v0 = acc[mt][nt][0] + b0v;
            float v1 = acc[mt][nt][1] + b1v;
            float v2 = acc[mt][nt][2] + b0v;
            float v3 = acc[mt][nt][3] + b1v;
            if (RELU) {
                v0 = fmaxf(v0, 0.f); v1 = fmaxf(v1, 0.f);
                v2 = fmaxf(v2, 0.f); v3 = fmaxf(v3, 0.f);
            }
            if (OUT == 0) {
                *(float2*)&C[(size_t)i0r * ldc + col] = make_float2(v0, v1);
                *(float2*)&C[(size_t)i1r * ldc + col] = make_float2(v2, v3);
            } else if (OUT == 1) {
                const float h0 = bf_hi(v0), h1 = bf_hi(v1);
                const float h2 = bf_hi(v2), h3 = bf_hi(v3);
                *(uint32_t*)&Ch[(size_t)i0r * ldc + col] = pack_bf2(h0, h1);
                *(uint32_t*)&Ch[(size_t)i1r * ldc + col] = pack_bf2(h2, h3);
                *(uint32_t*)&Cl[(size_t)i0r * ldc + col] = pack_bf2(v0 - h0, v1 - h1);
                *(uint32_t*)&Cl[(size_t)i1r * ldc + col] = pack_bf2(v2 - h2, v3 - h3);
            } else if (OUT == 2) {
                const float vv[4] = {v0, v1, v2, v3};
#pragma unroll
                for (int e = 0; e < 4; ++e) {
                    const int cc = col - n0 + (e & 1);
                    const int rr = i0r - m0 + (e >> 1) * 8;
                    const __nv_bfloat16 hb = __float2bfloat16(vv[e]);
                    tsh[cc * TP + rr] = hb;
                    tsl[cc * TP + rr] =
                        __float2bfloat16(vv[e] - __bfloat162float(hb));
                }
            } else {  // OUT == 3: attention-logit epilogue, stores exp(v)
                const int j0 = col, j1 = col + 1;
                const float p0 = (xB[j0] == 0) ? -1e9f : 0.f;
                const float p1 = (xB[j1] == 0) ? -1e9f : 0.f;
                v0 = (j0 <= i0r)
                   ? (v0 + qeB[(size_t)i0r * SS + (SS - 1 - i0r) + j0]) * ATT_SCALE + p0
                   : -1e30f;
                v1 = (j1 <= i0r)
                   ? (v1 + qeB[(size_t)i0r * SS + (SS - 1 - i0r) + j1]) * ATT_SCALE + p1
                   : -1e30f;
                v2 = (j0 <= i1r)
                   ? (v2 + qeB[(size_t)i1r * SS + (SS - 1 - i1r) + j0]) * ATT_SCALE + p0
                   : -1e30f;
                v3 = (j1 <= i1r)
                   ? (v3 + qeB[(size_t)i1r * SS + (SS - 1 - i1r) + j1]) * ATT_SCALE + p1
                   : -1e30f;
                const float ex0 = __expf(v0), ex1 = __expf(v1);
                const float ex2 = __expf(v2), ex3 = __expf(v3);
                *(float2*)&C[(size_t)i0r * ldc + col] = make_float2(ex0, ex1);
                *(float2*)&C[(size_t)i1r * ldc + col] = make_float2(ex2, ex3);
                e0 += ex0 + ex1;
                e1 += ex2 + ex3;
            }
        }
        if (OUT == 3) {
            e0 += __shfl_xor_sync(0xffffffffu, e0, 1);
            e0 += __shfl_xor_sync(0xffffffffu, e0, 2);
            e1 += __shfl_xor_sync(0xffffffffu, e1, 1);
            e1 += __shfl_xor_sync(0xffffffffu, e1, 2);
            if ((lane & 3) == 0) {
                psB[(size_t)i0r * 16 + (n0 >> 7) * 2 + wn] = e0;
                psB[(size_t)i1r * 16 + (n0 >> 7) * 2 + wn] = e1;
            }
        }
    }
    if (OUT == 2) {
        __syncthreads();
#pragma unroll
        for (int p = 0; p < BN / 16; ++p) {
            const int idx = tid + p * 256;
            const int row = idx >> 4, seg = idx & 15;
            const uint4 vh = *(const uint4*)&tsh[row * TP + seg * 8];
            const uint4 vl = *(const uint4*)&tsl[row * TP + seg * 8];
            *(uint4*)&Ch[(size_t)(n0 + row) * ldc + m0 + seg * 8] = vh;
            *(uint4*)&Cl[(size_t)(n0 + row) * ldc + m0 + seg * 8] = vl;
        }
    }
}

// ---------------------------------------------------------------------------
// AV GEMM: attn = P @ v, reading stored exp-values directly; invS computed
// inline from psum partials. B = v^T (split bf16). K capped causally.
// ---------------------------------------------------------------------------
constexpr int AV_AP   = 36;                       // A pitch (floats)
constexpr int AV_ABY  = 128 * AV_AP * 4;          // 18432 B
constexpr int AV_BBY  = 64 * 80;                  // 5120 B
constexpr int AV_STG  = AV_ABY + 2 * AV_BBY;      // 28672
constexpr int AV_SMEM = 2 * AV_STG;               // 57344

__global__ __launch_bounds__(256, 2)
void av_gemm(const float* __restrict__ lg, const float* __restrict__ ps,
             const __nv_bfloat16* __restrict__ vth, const __nv_bfloat16* __restrict__ vtl,
             __nv_bfloat16* __restrict__ oh, __nv_bfloat16* __restrict__ ol)
{
    extern __shared__ char dynsmem[];
    const uint32_t sbase = smem_u32(dynsmem);
    float* Asf = (float*)dynsmem;
    const int tid  = threadIdx.x;
    const int lane = tid & 31;
    const int warp = tid >> 5;
    const int wm = warp & 3;
    const int wn = warp >> 2;
    const int m0 = blockIdx.y * 128;
    const int bh = blockIdx.z;
    const int b  = bh >> 4;
    const int h  = bh & 15;

    const float* A = lg + (size_t)bh * SS * SS;
    const __nv_bfloat16* Bh = vth + ((size_t)b * DD + h * HD) * SS;
    const __nv_bfloat16* Bl = vtl + ((size_t)b * DD + h * HD) * SS;

    // inline invS from psum partials (deterministic fixed order)
    const int rr0 = m0 + wm * 32 + (lane >> 2);
    float iv[4];
#pragma unroll
    for (int r = 0; r < 4; ++r) {
        const int row = rr0 + r * 8;
        const float* pp = ps + ((size_t)bh * SS + row) * 16;
        const int nt2 = ((row >> 7) + 1) * 2;
        float s = 0.f;
        for (int t = 0; t < nt2; ++t) s += pp[t];
        iv[r] = 1.f / s;
    }

    float acc[2][4][4];
#pragma unroll
    for (int mt = 0; mt < 2; ++mt)
#pragma unroll
        for (int nt = 0; nt < 4; ++nt)
#pragma unroll
            for (int r = 0; r < 4; ++r) acc[mt][nt][r] = 0.f;

    const int Keff = min(SS, m0 + 128);
    const int nch  = Keff >> 5;

    auto load_stage = [&](int c) {
        const int k0c = c << 5;
        const uint32_t sb = sbase + (c & 1) * AV_STG;
#pragma unroll
        for (int i = 0; i < 4; ++i) {
            const int u = tid + i * 256;
            const int row = u >> 3, seg = u & 7;
            cpasync16(sb + row * (AV_AP * 4) + seg * 16,
                      A + (size_t)(m0 + row) * SS + k0c + seg * 4);
        }
        {
            const int row = tid >> 2, seg = tid & 3;
            const uint32_t so = sb + AV_ABY + row * 80 + seg * 16;
            const size_t gb = (size_t)row * SS + k0c + seg * 8;
            cpasync16(so,          Bh + gb);
            cpasync16(so + AV_BBY, Bl + gb);
        }
        asm volatile("cp.async.commit_group;" ::: "memory");
    };

    load_stage(0);

    const int lr  = lane & 7;
    const int sel = lane >> 3;
    const int b_n_off = lr + ((sel >> 1) << 3);
    const int b_k_off = (sel & 1) << 3;

    for (int c = 0; c < nch; ++c) {
        if (c + 1 < nch) {
            load_stage(c + 1);
            asm volatile("cp.async.wait_group 1;" ::: "memory");
        } else {
            asm volatile("cp.async.wait_group 0;" ::: "memory");
        }
        __syncthreads();
        const float* Af = Asf + ((c & 1) ? AV_STG / 4 : 0);
        const uint32_t sbB = sbase + (c & 1) * AV_STG + AV_ABY;

#pragma unroll
        for (int ks = 0; ks < 2; ++ks) {
            const int kk = ks << 4;
            const int c0 = kk + (lane & 3) * 2;
            uint32_t aH[2][4], aL[2][4], bb[4][2];
#pragma unroll
            for (int mt = 0; mt < 2; ++mt) {
                const float* Ar = Af + (wm * 32 + mt * 16 + (lane >> 2)) * AV_AP;
                const float2 x00 = *(const float2*)(Ar + c0);
                const float2 x10 = *(const float2*)(Ar + 8 * AV_AP + c0);
                const float2 x01 = *(const float2*)(Ar + c0 + 8);
                const float2 x11 = *(const float2*)(Ar + 8 * AV_AP + c0 + 8);
                const float i0 = iv[mt * 2], i1 = iv[mt * 2 + 1];
                const float p0 = x00.x * i0, p1 = x00.y * i0;
                const float p2 = x10.x * i1, p3 = x10.y * i1;
                const float p4 = x01.x * i0, p5 = x01.y * i0;
                const float p6 = x11.x * i1, p7 = x11.y * i1;
                const float h0 = bf_hi(p0), h1 = bf_hi(p1), h2 = bf_hi(p2), h3 = bf_hi(p3);
                const float h4 = bf_hi(p4), h5 = bf_hi(p5), h6 = bf_hi(p6), h7 = bf_hi(p7);
                aH[mt][0] = pack_bf2(h0, h1); aH[mt][1] = pack_bf2(h2, h3);
                aH[mt][2] = pack_bf2(h4, h5); aH[mt][3] = pack_bf2(h6, h7);
                aL[mt][0] = pack_bf2(p0 - h0, p1 - h1);
                aL[mt][1] = pack_bf2(p2 - h2, p3 - h3);
                aL[mt][2] = pack_bf2(p4 - h4, p5 - h5);
                aL[mt][3] = pack_bf2(p6 - h6, p7 - h7);
            }
#pragma unroll
            for (int np = 0; np < 2; ++np) {
                const int n = wn * 32 + np * 16 + b_n_off;
                uint32_t r[4];
                ldm_x4(sbB + n * 80 + (kk + b_k_off) * 2, r);
                bb[2 * np][0]     = r[0]; bb[2 * np][1]     = r[1];
                bb[2 * np + 1][0] = r[2]; bb[2 * np + 1][1] = r[3];
            }
#pragma unroll
            for (int mt = 0; mt < 2; ++mt)
#pragma unroll
                for (int nt = 0; nt < 4; ++nt)
                    mma_bf16(acc[mt][nt], aH[mt], bb[nt]);
#pragma unroll
            for (int mt = 0; mt < 2; ++mt)
#pragma unroll
                for (int nt = 0; nt < 4; ++nt)
                    mma_bf16(acc[mt][nt], aL[mt], bb[nt]);
#pragma unroll
            for (int np = 0; np < 2; ++np) {
                const int n = wn * 32 + np * 16 + b_n_off;
                uint32_t r[4];
                ldm_x4(sbB + AV_BBY + n * 80 + (kk + b_k_off) * 2, r);
                bb[2 * np][0]     = r[0]; bb[2 * np][1]     = r[1];
                bb[2 * np + 1][0] = r[2]; bb[2 * np + 1][1] = r[3];
            }
#pragma unroll
            for (int mt = 0; mt < 2; ++mt)
#pragma unroll
                for (int nt = 0; nt < 4; ++nt)
                    mma_bf16(acc[mt][nt], aH[mt], bb[nt]);
        }
        __syncthreads();
    }

    __nv_bfloat16* Oh = oh + ((size_t)b * SS) * DD + h * HD;
    __nv_bfloat16* Ol = ol + ((size_t)b * SS) * DD + h * HD;
    const int cb = wn * 32 + 2 * (lane & 3);
#pragma unroll
    for (int mt = 0; mt < 2; ++mt) {
        const int i0r = rr0 + mt * 16;
        const int i1r = i0r + 8;
#pragma unroll
        for (int nt = 0; nt < 4; ++nt) {
            const int col = cb + nt * 8;
            const float v0 = acc[mt][nt][0], v1 = acc[mt][nt][1];
            const float v2 = acc[mt][nt][2], v3 = acc[mt][nt][3];
            const float h0 = bf_hi(v0), h1 = bf_hi(v1);
            const float h2 = bf_hi(v2), h3 = bf_hi(v3);
            *(uint32_t*)&Oh[(size_t)i0r * DD + col] = pack_bf2(h0, h1);
            *(uint32_t*)&Oh[(size_t)i1r * DD + col] = pack_bf2(h2, h3);
            *(uint32_t*)&Ol[(size_t)i0r * DD + col] = pack_bf2(v0 - h0, v1 - h1);
            *(uint32_t*)&Ol[(size_t)i1r * DD + col] = pack_bf2(v2 - h2, v3 - h3);
        }
    }
}

// ---------------------------------------------------------------------------
// Weight transpose + bf16 hi/lo split (64x64 tiles, packed stores)
// ---------------------------------------------------------------------------
__global__ __launch_bounds__(256)
void conv_w(const float* __restrict__ W, __nv_bfloat16* __restrict__ hi,
            __nv_bfloat16* __restrict__ lo, int K, int N, long long lstride)
{
    __shared__ float t[64][65];   // [n][k]
    const int l = blockIdx.z;
    W  += (size_t)l * K * N;
    hi += (size_t)l * lstride;
    lo += (size_t)l * lstride;
    const int k0 = blockIdx.y * 64, n0 = blockIdx.x * 64;
    const int tid = threadIdx.x;
    const int tc = tid & 31;
    const int tr = tid >> 5;
#pragma unroll
    for (int i = 0; i < 8; ++i) {
        const int kk = tr + i * 8;
        const float2 v = *(const float2*)&W[(size_t)(k0 + kk) * N + n0 + tc * 2];
        t[tc * 2][kk]     = v.x;
        t[tc * 2 + 1][kk] = v.y;
    }
    __syncthreads();
    const int kp = (tid & 31) * 2;
    const int nb = tid >> 5;
#pragma unroll
    for (int i = 0; i < 8; ++i) {
        const int n = nb + i * 8;
        const float a = t[n][kp], b = t[n][kp + 1];
        const float ha = bf_hi(a), hb = bf_hi(b);
        *(uint32_t*)&hi[(size_t)(n0 + n) * K + k0 + kp] = pack_bf2(ha, hb);
        *(uint32_t*)&lo[(size_t)(n0 + n) * K + k0 + kp] = pack_bf2(a - ha, b - hb);
    }
}

// elementwise hi/lo split (for E)
__global__ void split_act(const float* __restrict__ x, __nv_bfloat16* __restrict__ hi,
                          __nv_bfloat16* __restrict__ lo, int n4)
{
    const int i = blockIdx.x * 256 + threadIdx.x;
    if (i >= n4) return;
    const float4 v = ((const float4*)x)[i];
    const float f[4] = {v.x, v.y, v.z, v.w};
    unsigned short hh[4], ll[4];
#pragma unroll
    for (int j = 0; j < 4; j++) {
        const __nv_bfloat16 hb = __float2bfloat16(f[j]);
        const __nv_bfloat16 lb = __float2bfloat16(f[j] - __bfloat162float(hb));
        hh[j] = __bfloat16_as_ushort(hb);
        ll[j] = __bfloat16_as_ushort(lb);
    }
    ((uint2*)hi)[i] = *(const uint2*)hh;
    ((uint2*)lo)[i] = *(const uint2*)ll;
}

// ---------------------------------------------------------------------------
// Sinusoid rate + embedding (writes split bf16 directly)
// ---------------------------------------------------------------------------
__global__ void rate_kernel(float* __restrict__ rate)
{
    const int d = blockIdx.x * 256 + threadIdx.x;
    if (d >= DD) return;
    const double LN1E4 = 9.210340371976184;
    const int par = d & 1;
    const float r1 = (float)exp(-LN1E4 * (double)d   / 1024.0);
    const float r2 = (float)exp( LN1E4 * (double)par / 1024.0);
    rate[d] = r1 * r2;
}

__global__ void embed_split(const int* __restrict__ x,
                            const float* __restrict__ emb,
                            const float* __restrict__ rate,
                            __nv_bfloat16* __restrict__ oh,
                            __nv_bfloat16* __restrict__ ol)
{
    const int bs = blockIdx.x;
    const int s  = bs & (SS - 1);
    const int tok = x[bs];
    const float* e = emb + (size_t)tok * DD;
    for (int d = threadIdx.x; d < DD; d += blockDim.x) {
        const int par = d & 1;
        const float ph = (float)s * rate[d] + 1.5707964f * (float)par;
        const float v = e[d] * 32.0f + sinf(ph);
        const __nv_bfloat16 hb = __float2bfloat16(v);
        oh[(size_t)bs * DD + d] = hb;
        ol[(size_t)bs * DD + d] = __float2bfloat16(v - __bfloat162float(hb));
    }
}

// ---------------------------------------------------------------------------
// LayerNorm over last dim (1024); reads fp32, writes SPLIT bf16.
// ---------------------------------------------------------------------------
__global__ __launch_bounds__(256)
void ln_split(const float* __restrict__ xin, const float* __restrict__ g,
              const float* __restrict__ be,
              __nv_bfloat16* __restrict__ oh, __nv_bfloat16* __restrict__ ol)
{
    const int row = blockIdx.x;
    const float* p = xin + (size_t)row * DD;
    const int t = threadIdx.x;
    float v[4];
    float s = 0.f, s2 = 0.f;
#pragma unroll
    for (int c = 0; c < 4; c++) {
        v[c] = p[t + c * 256];
        s += v[c];
        s2 += v[c] * v[c];
    }
    __shared__ float sh1[8], sh2[8];
#pragma unroll
    for (int o = 16; o > 0; o >>= 1) {
        s  += __shfl_xor_sync(0xffffffffu, s,  o);
        s2 += __shfl_xor_sync(0xffffffffu, s2, o);
    }
    if ((t & 31) == 0) { sh1[t >> 5] = s; sh2[t >> 5] = s2; }
    __syncthreads();
    s = 0.f; s2 = 0.f;
#pragma unroll
    for (int w = 0; w < 8; w++) { s += sh1[w]; s2 += sh2[w]; }
    const float mu  = s  * (1.f / DD);
    const float var = s2 * (1.f / DD) - mu * mu;
    const float inv = rsqrtf(var + 1e-6f);
#pragma unroll
    for (int c = 0; c < 4; c++) {
        const int d = t + c * 256;
        const float o = (v[c] - mu) * inv * g[d] + be[d];
        const __nv_bfloat16 hb = __float2bfloat16(o);
        oh[(size_t)row * DD + d] = hb;
        ol[(size_t)row * DD + d] = __float2bfloat16(o - __bfloat162float(hb));
    }
}

// ---------------------------------------------------------------------------
// Host side
// ---------------------------------------------------------------------------
using bf16 = __nv_bfloat16;

template<int BN, int SKIP, bool KCAP, int OUT, bool RELU>
static void run_mma_s(cudaStream_t st,
                      const bf16* ah, const bf16* al, const bf16* bh, const bf16* bl,
                      const float* bias, float* C, bf16* Ch, bf16* Cl,
                      int M, int N, int K, int lda, int ldb, int ldc,
                      int batch, int zdiv,
                      long long sA1, long long sA2,
                      long long sB1, long long sB2,
                      long long sC1, long long sC2)
{
    constexpr int STG = 2 * 10240 + 2 * BN * 80;
    static bool init = false;
    if (!init) {
        cudaFuncSetAttribute(gemm_mma<BN, SKIP, KCAP, OUT, RELU>,
                             cudaFuncAttributeMaxDynamicSharedMemorySize, 2 * STG);
        init = true;
    }
    dim3 grid(N / BN, M / 128, batch);
    gemm_mma<BN, SKIP, KCAP, OUT, RELU><<<grid, 256, 2 * STG, st>>>(
        ah, al, bh, bl, bias, C, Ch, Cl, K, lda, ldb, ldc,
        zdiv, sA1, sA2, sB1, sB2, sC1, sC2);
}

extern "C" void kernel_launch(void* const* d_in, const int* in_sizes, int n_in,
                              void* d_out, int out_size)
{
    const int*   x   = (const int*)  d_in[0];
    const float* emb = (const float*)d_in[1];
    const float* Wq  = (const float*)d_in[2];
    const float* bq  = (const float*)d_in[3];
    const float* Wk  = (const float*)d_in[4];
    const float* bk  = (const float*)d_in[5];
    const float* Wv  = (const float*)d_in[6];
    const float* bv  = (const float*)d_in[7];
    const float* Wo  = (const float*)d_in[8];
    const float* bo  = (const float*)d_in[9];
    const float* W1  = (const float*)d_in[10];
    const float* b1  = (const float*)d_in[11];
    const float* W2  = (const float*)d_in[12];
    const float* b2  = (const float*)d_in[13];
    const float* g1  = (const float*)d_in[14];
    const float* be1 = (const float*)d_in[15];
    const float* g2  = (const float*)d_in[16];
    const float* be2 = (const float*)d_in[17];
    const float* E   = (const float*)d_in[18];
    const float* Wf  = (const float*)d_in[19];
    const float* bf  = (const float*)d_in[20];
    float* out = (float*)d_out;

    static cudaStream_t s1 = nullptr;
    static cudaEvent_t evFork = nullptr, evJoin = nullptr, evK = nullptr, evV = nullptr;
    if (!s1) {
        cudaStreamCreateWithFlags(&s1, cudaStreamNonBlocking);
        cudaEventCreateWithFlags(&evFork, cudaEventDisableTiming);
        cudaEventCreateWithFlags(&evJoin, cudaEventDisableTiming);
        cudaEventCreateWithFlags(&evK,    cudaEventDisableTiming);
        cudaEventCreateWithFlags(&evV,    cudaEventDisableTiming);
    }
    cudaStream_t s0 = 0;

    cudaFuncSetAttribute(av_gemm, cudaFuncAttributeMaxDynamicSharedMemorySize,
                         AV_SMEM);

    float *t1, *h2, *qe, *lg, *rate, *ps;
    cudaGetSymbolAddress((void**)&t1, g_t1);
    cudaGetSymbolAddress((void**)&h2, g_h2);
    cudaGetSymbolAddress((void**)&qe, g_qe);
    cudaGetSymbolAddress((void**)&lg, g_lg);
    cudaGetSymbolAddress((void**)&rate, g_rate);
    cudaGetSymbolAddress((void**)&ps, g_ps);

    bf16 *xh, *xl, *qkh, *qkl, *vth, *vtl, *ath, *atl, *ffh, *ffl, *eh, *el;
    cudaGetSymbolAddress((void**)&xh,  g_xh);  cudaGetSymbolAddress((void**)&xl,  g_xl);
    cudaGetSymbolAddress((void**)&qkh, g_qkh); cudaGetSymbolAddress((void**)&qkl, g_qkl);
    cudaGetSymbolAddress((void**)&vth, g_vth); cudaGetSymbolAddress((void**)&vtl, g_vtl);
    cudaGetSymbolAddress((void**)&ath, g_ath); cudaGetSymbolAddress((void**)&atl, g_atl);
    cudaGetSymbolAddress((void**)&ffh, g_ffh); cudaGetSymbolAddress((void**)&ffl, g_ffl);
    cudaGetSymbolAddress((void**)&eh,  g_eh);  cudaGetSymbolAddress((void**)&el,  g_el);

    bf16 *wqkh, *wqkl, *wvh, *wvl, *woh, *wol;
    bf16 *w1h, *w1l, *w2h, *w2l, *wfh, *wfl;
    cudaGetSymbolAddress((void**)&wqkh, g_wqk_h); cudaGetSymbolAddress((void**)&wqkl, g_wqk_l);
    cudaGetSymbolAddress((void**)&wvh, g_wv_h); cudaGetSymbolAddress((void**)&wvl, g_wv_l);
    cudaGetSymbolAddress((void**)&woh, g_wo_h); cudaGetSymbolAddress((void**)&wol, g_wo_l);
    cudaGetSymbolAddress((void**)&w1h, g_w1_h); cudaGetSymbolAddress((void**)&w1l, g_w1_l);
    cudaGetSymbolAddress((void**)&w2h, g_w2_h); cudaGetSymbolAddress((void**)&w2l, g_w2_l);
    cudaGetSymbolAddress((void**)&wfh, g_wf_h); cudaGetSymbolAddress((void**)&wfl, g_wf_l);

    const int M = BB * SS;  // 2048
    const long long sSD  = (long long)SS * DD;
    const long long sSQK = (long long)SS * QKW;
    const long long sHSS = (long long)HH * SS * SS;
    const long long sSSq = (long long)SS * SS;
    const long long sDS  = (long long)DD * SS;
    const long long wQKL = (long long)QKW * DD;

    // ---- setup: conversions on s0 || {rest, rate, embed} on s1
    cudaEventRecord(evFork, s0);
    cudaStreamWaitEvent(s1, evFork, 0);

    conv_w<<<dim3(DD / 64, DD / 64, LL), 256, 0, s0>>>(Wq, wqkh, wqkl, DD, DD, wQKL);
    conv_w<<<dim3(DD / 64, DD / 64, LL), 256, 0, s0>>>(Wk, wqkh + (size_t)DD * DD,
                                                       wqkl + (size_t)DD * DD, DD, DD, wQKL);
    conv_w<<<dim3(DD / 64, DD / 64, LL), 256, 0, s0>>>(Wv, wvh, wvl, DD, DD, (long long)DD * DD);

    conv_w<<<dim3(DD / 64, DD / 64, LL), 256, 0, s1>>>(Wo, woh, wol, DD, DD, (long long)DD * DD);
    conv_w<<<dim3(DF / 64, DD / 64, LL), 256, 0, s1>>>(W1, w1h, w1l, DD, DF, (long long)DF * DD);
    conv_w<<<dim3(DD / 64, DF / 64, LL), 256, 0, s1>>>(W2, w2h, w2l, DF, DD, (long long)DD * DF);
    conv_w<<<dim3(VV / 64, DD / 64, 1),  256, 0, s1>>>(Wf, wfh, wfl, DD, VV, (long long)VV * DD);
    split_act<<<(LL * SS * HD / 4 + 255) / 256, 256, 0, s1>>>(E, eh, el, LL * SS * HD / 4);
    rate_kernel<<<4, 256, 0, s1>>>(rate);
    embed_split<<<BB * SS, 256, 0, s1>>>(x, emb, rate, xh, xl);

    cudaEventRecord(evJoin, s1);
    cudaStreamWaitEvent(s0, evJoin, 0);

    for (int l = 0; l < LL; l++) {
        const size_t wdd = (size_t)l * DD * DD;
        const size_t wdf = (size_t)l * DF * DD;
        const bf16* ehl = eh + (size_t)l * SS * HD;
        const bf16* ell = el + (size_t)l * SS * HD;

        // fork: K-proj + V-proj on s1, Q-proj -> QE -> QK on s0
        cudaEventRecord(evFork, s0);
        cudaStreamWaitEvent(s1, evFork, 0);

        // Q projection (columns 0..1023 of qk buffer)
        run_mma_s<128, 0, false, 1, false>(s0, xh, xl, wqkh + (size_t)l * wQKL,
                                           wqkl + (size_t)l * wQKL, bq + l * DD,
                                           nullptr, qkh, qkl, M, DD, DD, DD, DD, QKW,
                                           1, 1, 0, 0, 0, 0, 0, 0);

        // K projection (columns 1024..2047) on s1
        run_mma_s<128, 0, false, 1, false>(s1, xh, xl,
                                           wqkh + (size_t)l * wQKL + (size_t)DD * DD,
                                           wqkl + (size_t)l * wQKL + (size_t)DD * DD,
                                           bk + l * DD,
                                           nullptr, qkh + DD, qkl + DD,
                                           M, DD, DD, DD, DD, QKW,
                                           1, 1, 0, 0, 0, 0, 0, 0);
        cudaEventRecord(evK, s1);
        // V projection (split-transposed per batch) on s1
        run_mma_s<128, 0, false, 2, false>(s1, xh, xl, wvh + wdd, wvl + wdd, bv + l * DD,
                                           nullptr, vth, vtl, SS, DD, DD, DD, DD, SS,
                                           BB, 1, sSD, 0, 0, 0, sDS, 0);
        cudaEventRecord(evV, s1);

        // QE (anti-diagonal tiles only) on s0 -- needs q only
        run_mma_s<128, 1, false, 0, false>(s0, qkh, qkl, ehl, ell, nullptr, qe,
                                           nullptr, nullptr,
                                           SS, SS, HD, QKW, HD, SS, BB * HH, HH,
                                           sSQK, HD, 0, 0, sHSS, sSSq);

        // QK^T with fused Srel + masks + exp + sumexp partials (OUT=3)
        cudaStreamWaitEvent(s0, evK, 0);
        run_mma_s<128, 2, false, 3, false>(s0, qkh, qkl, qkh + DD, qkl + DD,
                                           (const float*)x, lg, (bf16*)qe, (bf16*)ps,
                                           SS, SS, HD, QKW, QKW, SS, BB * HH, HH,
                                           sSQK, HD, sSQK, HD, sHSS, sSSq);

        // attn = P @ v, inline invS
        cudaStreamWaitEvent(s0, evV, 0);
        av_gemm<<<dim3(1, SS / 128, BB * HH), 256, AV_SMEM, s0>>>(
            lg, ps, vth, vtl, ath, atl);

        // Wo + LN1
        run_mma_s<128, 0, false, 0, false>(s0, ath, atl, woh + wdd, wol + wdd, bo + l * DD,
                                           t1, nullptr, nullptr, M, DD, DD, DD, DD, DD,
                                           1, 1, 0, 0, 0, 0, 0, 0);
        ln_split<<<BB * SS, 256, 0, s0>>>(t1, g1 + l * DD, be1 + l * DD, xh, xl);

        // FFN
        run_mma_s<64, 0, false, 1, true>(s0, xh, xl, w1h + wdf, w1l + wdf, b1 + l * DF,
                                         nullptr, ffh, ffl, M, DF, DD, DD, DD, DF,
                                         1, 1, 0, 0, 0, 0, 0, 0);
        run_mma_s<128, 0, false, 0, false>(s0, ffh, ffl, w2h + wdf, w2l + wdf, b2 + l * DD,
                                           h2, nullptr, nullptr, M, DD, DF, DF, DF, DD,
                                           1, 1, 0, 0, 0, 0, 0, 0);
        ln_split<<<BB * SS, 256, 0, s0>>>(h2, g2 + l * DD, be2 + l * DD, xh, xl);
    }

    // final projection to vocab
    run_mma_s<64, 0, false, 0, false>(s0, xh, xl, wfh, wfl, bf, out, nullptr, nullptr,
                                      M, VV, DD, DD, DD, VV, 1, 1, 0, 0, 0, 0, 0, 0);
}